// round 6
// baseline (speedup 1.0000x reference)
#include <cuda_runtime.h>
#include <cuda_bf16.h>
#include <math.h>
#include <stdint.h>

#define NB 64
#define NN 2048
#define NC 64
#define ND 10
#define NJ 4096          // NB*NC
#define KI 192           // cheb_k * C_IN

// ------------------ scratch (static device globals) ------------------
__device__ __nv_bfloat16 g_Shi [NN * NN];
__device__ __nv_bfloat16 g_Slo [NN * NN];
__device__ __nv_bfloat16 g_Xqhi[(size_t)NJ * NN];   // [j][m]
__device__ __nv_bfloat16 g_Xqlo[(size_t)NJ * NN];
__device__ __nv_bfloat16 g_Y1qhi[(size_t)NJ * NN];  // [j][m]
__device__ __nv_bfloat16 g_Y1qlo[(size_t)NJ * NN];
__device__ float g_Y1nm[(size_t)NN * NJ];           // [n][j]
__device__ float g_Y2nm[(size_t)NN * NJ];
__device__ float g_W   [(size_t)NN * KI * NC];

// ------------------ helpers ------------------
__device__ __forceinline__ uint32_t smem_u32(const void* p) {
    uint32_t a;
    asm("{ .reg .u64 t; cvta.to.shared.u64 t, %1; cvt.u32.u64 %0, t; }" : "=r"(a) : "l"(p));
    return a;
}
__device__ __forceinline__ void cpa16(uint32_t s, const void* g) {
    asm volatile("cp.async.cg.shared.global [%0], [%1], 16;" :: "r"(s), "l"(g));
}
__device__ __forceinline__ void bf16_split(float v, __nv_bfloat16& hi, __nv_bfloat16& lo) {
    hi = __float2bfloat16(v);
    lo = __float2bfloat16(v - __bfloat162float(hi));
}

#define LDSM4(r, a) \
    asm volatile("ldmatrix.sync.aligned.m8n8.x4.shared.b16 {%0,%1,%2,%3}, [%4];" \
        : "=r"((r)[0]), "=r"((r)[1]), "=r"((r)[2]), "=r"((r)[3]) : "r"(a))

#define MMA_BF16(c, a, b0, b1) \
    asm volatile("mma.sync.aligned.m16n8k16.row.col.f32.bf16.bf16.f32 " \
        "{%0,%1,%2,%3}, {%4,%5,%6,%7}, {%8,%9}, {%0,%1,%2,%3};" \
        : "+f"((c)[0]), "+f"((c)[1]), "+f"((c)[2]), "+f"((c)[3]) \
        : "r"((a)[0]), "r"((a)[1]), "r"((a)[2]), "r"((a)[3]), "r"(b0), "r"(b1))

// ============================================================
// supports: S[n,:] = softmax(relu(E[n]·E[m])), split bf16 hi/lo
// ============================================================
__global__ __launch_bounds__(256) void supports_kernel(const float* __restrict__ E) {
    __shared__ float vals[NN];
    __shared__ float red[256];
    const int n = blockIdx.x;
    const int tid = threadIdx.x;

    float en[ND];
#pragma unroll
    for (int d = 0; d < ND; d++) en[d] = E[n * ND + d];

    float lmax = -1e30f;
    for (int m = tid; m < NN; m += 256) {
        float v = 0.f;
#pragma unroll
        for (int d = 0; d < ND; d++) v = fmaf(en[d], E[m * ND + d], v);
        v = fmaxf(v, 0.f);
        vals[m] = v;
        lmax = fmaxf(lmax, v);
    }
    red[tid] = lmax; __syncthreads();
    for (int s = 128; s > 0; s >>= 1) { if (tid < s) red[tid] = fmaxf(red[tid], red[tid + s]); __syncthreads(); }
    const float gmax = red[0]; __syncthreads();

    float lsum = 0.f;
    for (int m = tid; m < NN; m += 256) {
        float e = expf(vals[m] - gmax);
        vals[m] = e; lsum += e;
    }
    red[tid] = lsum; __syncthreads();
    for (int s = 128; s > 0; s >>= 1) { if (tid < s) red[tid] += red[tid + s]; __syncthreads(); }
    const float inv = 1.f / red[0];
    for (int m = tid; m < NN; m += 256) {
        float v = vals[m] * inv;
        __nv_bfloat16 hi, lo; bf16_split(v, hi, lo);
        g_Shi[n * NN + m] = hi;
        g_Slo[n * NN + m] = lo;
    }
}

// ============================================================
// Xq builder: Xq[j = b*64+c][m] = x[b][m][c], split bf16 hi/lo
// ============================================================
__global__ __launch_bounds__(256) void xq_kernel(const float* __restrict__ x) {
    __shared__ float sm[64 * 33];
    const int m0 = blockIdx.x * 32;
    const int b  = blockIdx.y;
    const int t  = threadIdx.x;
#pragma unroll
    for (int p = 0; p < 8; p++) {
        int e = t + 256 * p;
        int r = e >> 6, c = e & 63;
        sm[c * 33 + r] = x[(size_t)b * (NN * NC) + (size_t)(m0 + r) * NC + c];
    }
    __syncthreads();
#pragma unroll
    for (int p = 0; p < 8; p++) {
        int e = t + 256 * p;
        int c = e >> 5, r = e & 31;
        float v = sm[c * 33 + r];
        __nv_bfloat16 hi, lo; bf16_split(v, hi, lo);
        size_t off = (size_t)(b * 64 + c) * NN + m0 + r;
        g_Xqhi[off] = hi;
        g_Xqlo[off] = lo;
    }
}

// ============================================================
// weights: W[n, ki, o] = sum_d E[n,d] * Wp[d, ki, o]
// ============================================================
__global__ __launch_bounds__(256) void weights_kernel(const float* __restrict__ E,
                                                      const float* __restrict__ Wp) {
    __shared__ float Es[16][ND];
    const int e0 = blockIdx.x * 256;
    const int n0 = blockIdx.y * 16;
    const int tid = threadIdx.x;
    if (tid < 16 * ND) Es[tid / ND][tid % ND] = E[(n0 + tid / ND) * ND + (tid % ND)];
    __syncthreads();
    const int e = e0 + tid;
    float wp[ND];
#pragma unroll
    for (int d = 0; d < ND; d++) wp[d] = Wp[d * (KI * NC) + e];
#pragma unroll
    for (int nn = 0; nn < 16; nn++) {
        float acc = 0.f;
#pragma unroll
        for (int d = 0; d < ND; d++) acc = fmaf(Es[nn][d], wp[d], acc);
        g_W[(size_t)(n0 + nn) * (KI * NC) + e] = acc;
    }
}

// ============================================================
// 3xBF16 mma.sync GEMM (m16n8k16): C[128x128] tile, 512 threads,
// 16 warps in 4x4 grid, warp tile 32x32. 3-stage cp.async, BK=64.
// ============================================================
#define STAGE_BYTES 65536
#define AHI_OFF 0
#define ALO_OFF 16384
#define BHI_OFF 32768
#define BLO_OFF 49152
#define GEMM_SMEM (3 * STAGE_BYTES)
#define NITER (NN / 64)   // 32

template <int MODE>
__global__ void __launch_bounds__(512, 1) gemm_bf16x3_kernel() {
    extern __shared__ float dsm[];
    const int t = threadIdx.x;
    const int l = t & 31;
    const int wid = t >> 5;        // 0..15
    const int wm = wid >> 2;       // 0..3  (m direction, 32 rows each)
    const int wn = wid & 3;        // 0..3  (n direction, 32 cols each)
    const int bm = blockIdx.y * 128;
    const int bn = blockIdx.x * 128;

    const __nv_bfloat16* Ah = g_Shi + (size_t)bm * NN;
    const __nv_bfloat16* Al = g_Slo + (size_t)bm * NN;
    const __nv_bfloat16* Bh = (MODE == 1 ? g_Xqhi : g_Y1qhi) + (size_t)bn * NN;
    const __nv_bfloat16* Bl = (MODE == 1 ? g_Xqlo : g_Y1qlo) + (size_t)bn * NN;

    const uint32_t sb0 = smem_u32(dsm);

    auto load_stage = [&](int s, int k0) {
        const uint32_t sb = sb0 + (uint32_t)s * STAGE_BYTES;
#pragma unroll
        for (int p = 0; p < 2; p++) {
            const int g = t + 512 * p;          // granule id (16B = 8 bf16)
            const int row = g >> 3;
            const int c16 = g & 7;
            const int sw = c16 ^ (row & 7);     // XOR swizzle on 16B columns
            const uint32_t so = sb + (uint32_t)(row * 128 + sw * 16);
            const size_t go = (size_t)row * NN + k0 + c16 * 8;
            cpa16(so + AHI_OFF, Ah + go);
            cpa16(so + ALO_OFF, Al + go);
            cpa16(so + BHI_OFF, Bh + go);
            cpa16(so + BLO_OFF, Bl + go);
        }
        asm volatile("cp.async.commit_group;" ::: "memory");
    };

    float acc[2][4][4];
#pragma unroll
    for (int a = 0; a < 2; a++)
#pragma unroll
        for (int b = 0; b < 4; b++)
#pragma unroll
            for (int c = 0; c < 4; c++) acc[a][b][c] = 0.f;

    // ldmatrix lane geometry (x4: lanes 0-7/8-15/16-23/24-31 -> 4 matrices)
    const int t4 = l >> 3;
    const int l7 = l & 7;
    const int arow_in = ((t4 & 1) << 3) + l7;    // A: m-subrow
    const int brow_in = ((t4 >> 1) << 3) + l7;   // B: n-subrow
    const uint32_t abase = (uint32_t)((wm * 32 + arow_in) * 128);
    const uint32_t bbase = (uint32_t)((wn * 32 + brow_in) * 128);
    const int akg = t4 >> 1;                     // A k-granule select (k16 halves)
    const int bkg = t4 & 1;                      // B k-granule select

    load_stage(0, 0);
    load_stage(1, 64);

    for (int i = 0; i < NITER; i++) {
        asm volatile("cp.async.wait_group 1;" ::: "memory");
        __syncthreads();
        if (i + 2 < NITER) load_stage((i + 2) % 3, (i + 2) * 64);
        const uint32_t sb = sb0 + (uint32_t)(i % 3) * STAGE_BYTES;
#pragma unroll
        for (int ks = 0; ks < 4; ks++) {         // k16 steps within BK=64
            const uint32_t xa = (uint32_t)(((ks * 2 + akg) ^ l7) << 4);
            const uint32_t xb = (uint32_t)(((ks * 2 + bkg) ^ l7) << 4);
            uint32_t ah[2][4], al[2][4];
            uint32_t bhf[2][4], blf[2][4];

#pragma unroll
            for (int mt = 0; mt < 2; mt++)
                LDSM4(ah[mt], sb + abase + (uint32_t)(mt * 16 * 128) + xa + AHI_OFF);
#pragma unroll
            for (int nh = 0; nh < 2; nh++)
                LDSM4(bhf[nh], sb + bbase + (uint32_t)(nh * 16 * 128) + xb + BHI_OFF);

            // term 1: hi*hi
#pragma unroll
            for (int mt = 0; mt < 2; mt++)
#pragma unroll
                for (int n8 = 0; n8 < 4; n8++) {
                    const int nh = n8 >> 1, q = (n8 & 1) * 2;
                    MMA_BF16(acc[mt][n8], ah[mt], bhf[nh][q], bhf[nh][q + 1]);
                }

            // term 2: lo*hi
#pragma unroll
            for (int mt = 0; mt < 2; mt++)
                LDSM4(al[mt], sb + abase + (uint32_t)(mt * 16 * 128) + xa + ALO_OFF);
#pragma unroll
            for (int mt = 0; mt < 2; mt++)
#pragma unroll
                for (int n8 = 0; n8 < 4; n8++) {
                    const int nh = n8 >> 1, q = (n8 & 1) * 2;
                    MMA_BF16(acc[mt][n8], al[mt], bhf[nh][q], bhf[nh][q + 1]);
                }

            // term 3: hi*lo
#pragma unroll
            for (int nh = 0; nh < 2; nh++)
                LDSM4(blf[nh], sb + bbase + (uint32_t)(nh * 16 * 128) + xb + BLO_OFF);
#pragma unroll
            for (int mt = 0; mt < 2; mt++)
#pragma unroll
                for (int n8 = 0; n8 < 4; n8++) {
                    const int nh = n8 >> 1, q = (n8 & 1) * 2;
                    MMA_BF16(acc[mt][n8], ah[mt], blf[nh][q], blf[nh][q + 1]);
                }
        }
    }

    // ---------------- epilogue ----------------
    float* Ynm = (MODE == 1) ? g_Y1nm : g_Y2nm;
    const int lm = l >> 2;
    const int lc = (l & 3) << 1;
#pragma unroll
    for (int mt = 0; mt < 2; mt++)
#pragma unroll
        for (int n8 = 0; n8 < 4; n8++) {
            const int r = bm + wm * 32 + mt * 16 + lm;
            const int col = bn + wn * 32 + n8 * 8 + lc;
            *(float2*)&Ynm[(size_t)r * NJ + col] =
                make_float2(acc[mt][n8][0], acc[mt][n8][1]);
            *(float2*)&Ynm[(size_t)(r + 8) * NJ + col] =
                make_float2(acc[mt][n8][2], acc[mt][n8][3]);
        }

    if (MODE == 1) {
        // transpose tile via smem (pitch 132), then coalesced bf16 hi/lo stores
        __syncthreads();
#pragma unroll
        for (int mt = 0; mt < 2; mt++)
#pragma unroll
            for (int n8 = 0; n8 < 4; n8++) {
                const int jl = wn * 32 + n8 * 8 + lc;
                const int ml = wm * 32 + mt * 16 + lm;
                dsm[jl * 132 + ml]           = acc[mt][n8][0];
                dsm[(jl + 1) * 132 + ml]     = acc[mt][n8][1];
                dsm[jl * 132 + ml + 8]       = acc[mt][n8][2];
                dsm[(jl + 1) * 132 + ml + 8] = acc[mt][n8][3];
            }
        __syncthreads();
#pragma unroll
        for (int it = 0; it < 8; it++) {
            const int j = wid * 8 + it;
            const int m4 = l * 4;
            const float4 v = *(const float4*)&dsm[j * 132 + m4];
            __nv_bfloat16 h0, h1, h2, h3, o0, o1, o2, o3;
            bf16_split(v.x, h0, o0);
            bf16_split(v.y, h1, o1);
            bf16_split(v.z, h2, o2);
            bf16_split(v.w, h3, o3);
            const size_t off = (size_t)(bn + j) * NN + bm + m4;
            __nv_bfloat162 hp0 = make_bfloat162(h0, h1), hp1 = make_bfloat162(h2, h3);
            __nv_bfloat162 lp0 = make_bfloat162(o0, o1), lp1 = make_bfloat162(o2, o3);
            uint2 hw, lw;
            hw.x = *(uint32_t*)&hp0; hw.y = *(uint32_t*)&hp1;
            lw.x = *(uint32_t*)&lp0; lw.y = *(uint32_t*)&lp1;
            *(uint2*)&g_Y1qhi[off] = hw;
            *(uint2*)&g_Y1qlo[off] = lw;
        }
    }
}

// ============================================================
// output: per node n, out[b,n,o] = A_n[b,ki] @ W_n[ki,o] + bias_n[o]
// ============================================================
__global__ __launch_bounds__(256) void output_kernel(const float* __restrict__ x,
                                                     const float* __restrict__ E,
                                                     const float* __restrict__ bp,
                                                     float* __restrict__ out) {
    extern __shared__ float sm[];
    float* As = sm;                 // 192 * 65
    float* Ws = sm + KI * 65;       // 192 * 64

    const int n = blockIdx.x;
    const int tid = threadIdx.x;

    for (int idx = tid; idx < NJ; idx += 256) {
        const int b = idx >> 6;
        const int i = idx & 63;
        const float xv = x[(size_t)b * (NN * NC) + n * NC + i];
        const float y1 = g_Y1nm[(size_t)n * NJ + idx];
        const float y2 = g_Y2nm[(size_t)n * NJ + idx];
        As[(i)       * 65 + b] = xv;
        As[(64 + i)  * 65 + b] = y1;
        As[(128 + i) * 65 + b] = 2.f * y2 - xv;
    }
    const float* Wrow = &g_W[(size_t)n * (KI * NC)];
    for (int idx = tid * 4; idx < KI * NC; idx += 1024)
        *(float4*)&Ws[idx] = *(const float4*)&Wrow[idx];
    __syncthreads();

    const int o0 = (tid % 16) * 4;
    const int b0 = (tid / 16) * 4;
    float acc[4][4] = {};
#pragma unroll 4
    for (int kk = 0; kk < KI; kk++) {
        const float a0 = As[kk * 65 + b0 + 0];
        const float a1 = As[kk * 65 + b0 + 1];
        const float a2 = As[kk * 65 + b0 + 2];
        const float a3 = As[kk * 65 + b0 + 3];
        const float4 w = *(const float4*)&Ws[kk * 64 + o0];
        acc[0][0] = fmaf(a0, w.x, acc[0][0]); acc[0][1] = fmaf(a0, w.y, acc[0][1]);
        acc[0][2] = fmaf(a0, w.z, acc[0][2]); acc[0][3] = fmaf(a0, w.w, acc[0][3]);
        acc[1][0] = fmaf(a1, w.x, acc[1][0]); acc[1][1] = fmaf(a1, w.y, acc[1][1]);
        acc[1][2] = fmaf(a1, w.z, acc[1][2]); acc[1][3] = fmaf(a1, w.w, acc[1][3]);
        acc[2][0] = fmaf(a2, w.x, acc[2][0]); acc[2][1] = fmaf(a2, w.y, acc[2][1]);
        acc[2][2] = fmaf(a2, w.z, acc[2][2]); acc[2][3] = fmaf(a2, w.w, acc[2][3]);
        acc[3][0] = fmaf(a3, w.x, acc[3][0]); acc[3][1] = fmaf(a3, w.y, acc[3][1]);
        acc[3][2] = fmaf(a3, w.z, acc[3][2]); acc[3][3] = fmaf(a3, w.w, acc[3][3]);
    }

    float bias[4];
#pragma unroll
    for (int oo = 0; oo < 4; oo++) {
        float s = 0.f;
#pragma unroll
        for (int d = 0; d < ND; d++) s = fmaf(E[n * ND + d], bp[d * NC + o0 + oo], s);
        bias[oo] = s;
    }

#pragma unroll
    for (int bb = 0; bb < 4; bb++) {
        float4 v = make_float4(acc[bb][0] + bias[0], acc[bb][1] + bias[1],
                               acc[bb][2] + bias[2], acc[bb][3] + bias[3]);
        *(float4*)&out[(size_t)(b0 + bb) * (NN * NC) + n * NC + o0] = v;
    }
}

// ============================================================
extern "C" void kernel_launch(void* const* d_in, const int* in_sizes, int n_in,
                              void* d_out, int out_size) {
    (void)in_sizes; (void)n_in; (void)out_size;
    const float* x  = (const float*)d_in[0];
    const float* E  = (const float*)d_in[1];
    const float* Wp = (const float*)d_in[2];
    const float* bp = (const float*)d_in[3];
    float* out = (float*)d_out;

    const int kOutSmem = (KI * 65 + KI * NC) * (int)sizeof(float);
    cudaFuncSetAttribute(output_kernel, cudaFuncAttributeMaxDynamicSharedMemorySize, kOutSmem);
    cudaFuncSetAttribute(gemm_bf16x3_kernel<1>, cudaFuncAttributeMaxDynamicSharedMemorySize, GEMM_SMEM);
    cudaFuncSetAttribute(gemm_bf16x3_kernel<2>, cudaFuncAttributeMaxDynamicSharedMemorySize, GEMM_SMEM);

    supports_kernel<<<NN, 256>>>(E);
    xq_kernel<<<dim3(NN / 32, NB), 256>>>(x);
    weights_kernel<<<dim3((KI * NC) / 256, NN / 16), 256>>>(E, Wp);

    dim3 ggrid(NJ / 128, NN / 128);   // (32, 16)
    gemm_bf16x3_kernel<1><<<ggrid, 512, GEMM_SMEM>>>();
    gemm_bf16x3_kernel<2><<<ggrid, 512, GEMM_SMEM>>>();

    output_kernel<<<NN, 256, kOutSmem>>>(x, E, bp, out);
}

// round 7
// speedup vs baseline: 1.0551x; 1.0551x over previous
#include <cuda_runtime.h>
#include <cuda_bf16.h>
#include <math.h>
#include <stdint.h>

#define NB 64
#define NN 2048
#define NC 64
#define ND 10
#define NJ 4096          // NB*NC
#define KI 192           // cheb_k * C_IN

// ------------------ scratch (static device globals) ------------------
__device__ __nv_bfloat16 g_Shi [NN * NN];
__device__ __nv_bfloat16 g_Slo [NN * NN];
__device__ __nv_bfloat16 g_Xqhi[(size_t)NJ * NN];   // [j][m]
__device__ __nv_bfloat16 g_Xqlo[(size_t)NJ * NN];
__device__ __nv_bfloat16 g_Y1qhi[(size_t)NJ * NN];  // [j][m]
__device__ __nv_bfloat16 g_Y1qlo[(size_t)NJ * NN];
__device__ float g_Y1nm[(size_t)NN * NJ];           // [n][j]
__device__ float g_Y2nm[(size_t)NN * NJ];
__device__ float g_W   [(size_t)NN * KI * NC];

// ------------------ helpers ------------------
__device__ __forceinline__ uint32_t smem_u32(const void* p) {
    uint32_t a;
    asm("{ .reg .u64 t; cvta.to.shared.u64 t, %1; cvt.u32.u64 %0, t; }" : "=r"(a) : "l"(p));
    return a;
}
__device__ __forceinline__ void cpa16(uint32_t s, const void* g) {
    asm volatile("cp.async.cg.shared.global [%0], [%1], 16;" :: "r"(s), "l"(g));
}
__device__ __forceinline__ void bf16_split(float v, __nv_bfloat16& hi, __nv_bfloat16& lo) {
    hi = __float2bfloat16(v);
    lo = __float2bfloat16(v - __bfloat162float(hi));
}

#define LDSM4(r, a) \
    asm volatile("ldmatrix.sync.aligned.m8n8.x4.shared.b16 {%0,%1,%2,%3}, [%4];" \
        : "=r"((r)[0]), "=r"((r)[1]), "=r"((r)[2]), "=r"((r)[3]) : "r"(a))

#define MMA_BF16(c, a, b0, b1) \
    asm volatile("mma.sync.aligned.m16n8k16.row.col.f32.bf16.bf16.f32 " \
        "{%0,%1,%2,%3}, {%4,%5,%6,%7}, {%8,%9}, {%0,%1,%2,%3};" \
        : "+f"((c)[0]), "+f"((c)[1]), "+f"((c)[2]), "+f"((c)[3]) \
        : "r"((a)[0]), "r"((a)[1]), "r"((a)[2]), "r"((a)[3]), "r"(b0), "r"(b1))

// ============================================================
// supports: S[n,:] = softmax(relu(E[n]·E[m])), split bf16 hi/lo
// ============================================================
__global__ __launch_bounds__(256) void supports_kernel(const float* __restrict__ E) {
    __shared__ float vals[NN];
    __shared__ float red[256];
    const int n = blockIdx.x;
    const int tid = threadIdx.x;

    float en[ND];
#pragma unroll
    for (int d = 0; d < ND; d++) en[d] = E[n * ND + d];

    float lmax = -1e30f;
    for (int m = tid; m < NN; m += 256) {
        float v = 0.f;
#pragma unroll
        for (int d = 0; d < ND; d++) v = fmaf(en[d], E[m * ND + d], v);
        v = fmaxf(v, 0.f);
        vals[m] = v;
        lmax = fmaxf(lmax, v);
    }
    red[tid] = lmax; __syncthreads();
    for (int s = 128; s > 0; s >>= 1) { if (tid < s) red[tid] = fmaxf(red[tid], red[tid + s]); __syncthreads(); }
    const float gmax = red[0]; __syncthreads();

    float lsum = 0.f;
    for (int m = tid; m < NN; m += 256) {
        float e = expf(vals[m] - gmax);
        vals[m] = e; lsum += e;
    }
    red[tid] = lsum; __syncthreads();
    for (int s = 128; s > 0; s >>= 1) { if (tid < s) red[tid] += red[tid + s]; __syncthreads(); }
    const float inv = 1.f / red[0];
    for (int m = tid; m < NN; m += 256) {
        float v = vals[m] * inv;
        __nv_bfloat16 hi, lo; bf16_split(v, hi, lo);
        g_Shi[n * NN + m] = hi;
        g_Slo[n * NN + m] = lo;
    }
}

// ============================================================
// Xq builder: Xq[j = b*64+c][m] = x[b][m][c], split bf16 hi/lo
// ============================================================
__global__ __launch_bounds__(256) void xq_kernel(const float* __restrict__ x) {
    __shared__ float sm[64 * 33];
    const int m0 = blockIdx.x * 32;
    const int b  = blockIdx.y;
    const int t  = threadIdx.x;
#pragma unroll
    for (int p = 0; p < 8; p++) {
        int e = t + 256 * p;
        int r = e >> 6, c = e & 63;
        sm[c * 33 + r] = x[(size_t)b * (NN * NC) + (size_t)(m0 + r) * NC + c];
    }
    __syncthreads();
#pragma unroll
    for (int p = 0; p < 8; p++) {
        int e = t + 256 * p;
        int c = e >> 5, r = e & 31;
        float v = sm[c * 33 + r];
        __nv_bfloat16 hi, lo; bf16_split(v, hi, lo);
        size_t off = (size_t)(b * 64 + c) * NN + m0 + r;
        g_Xqhi[off] = hi;
        g_Xqlo[off] = lo;
    }
}

// ============================================================
// weights: W[n, ki, o] = sum_d E[n,d] * Wp[d, ki, o]
// ============================================================
__global__ __launch_bounds__(256) void weights_kernel(const float* __restrict__ E,
                                                      const float* __restrict__ Wp) {
    __shared__ float Es[16][ND];
    const int e0 = blockIdx.x * 256;
    const int n0 = blockIdx.y * 16;
    const int tid = threadIdx.x;
    if (tid < 16 * ND) Es[tid / ND][tid % ND] = E[(n0 + tid / ND) * ND + (tid % ND)];
    __syncthreads();
    const int e = e0 + tid;
    float wp[ND];
#pragma unroll
    for (int d = 0; d < ND; d++) wp[d] = Wp[d * (KI * NC) + e];
#pragma unroll
    for (int nn = 0; nn < 16; nn++) {
        float acc = 0.f;
#pragma unroll
        for (int d = 0; d < ND; d++) acc = fmaf(Es[nn][d], wp[d], acc);
        g_W[(size_t)(n0 + nn) * (KI * NC) + e] = acc;
    }
}

// ============================================================
// 3xBF16 mma.sync GEMM (m16n8k16): C[128x128] tile, 256 threads,
// 8 warps (2x4), warp tile 64x32. 3-stage cp.async, BK=64.
// Register-double-buffered fragments: LDSM for ks+1 issued during
// MMAs of ks, hiding LDS latency under tensor work.
// ============================================================
#define STAGE_BYTES 65536
#define AHI_OFF 0
#define ALO_OFF 16384
#define BHI_OFF 32768
#define BLO_OFF 49152
#define GEMM_SMEM (3 * STAGE_BYTES)
#define NITER (NN / 64)   // 32

template <int MODE>
__global__ void __launch_bounds__(256, 1) gemm_bf16x3_kernel() {
    extern __shared__ float dsm[];
    const int t = threadIdx.x;
    const int l = t & 31;
    const int wid = t >> 5;
    const int wm = wid >> 2;       // 0..1  (m direction, 64 rows each)
    const int wn = wid & 3;        // 0..3  (n direction, 32 cols each)
    const int bm = blockIdx.y * 128;
    const int bn = blockIdx.x * 128;

    const __nv_bfloat16* Ah = g_Shi + (size_t)bm * NN;
    const __nv_bfloat16* Al = g_Slo + (size_t)bm * NN;
    const __nv_bfloat16* Bh = (MODE == 1 ? g_Xqhi : g_Y1qhi) + (size_t)bn * NN;
    const __nv_bfloat16* Bl = (MODE == 1 ? g_Xqlo : g_Y1qlo) + (size_t)bn * NN;

    const uint32_t sb0 = smem_u32(dsm);

    auto load_stage = [&](int s, int k0) {
        const uint32_t sb = sb0 + (uint32_t)s * STAGE_BYTES;
#pragma unroll
        for (int p = 0; p < 4; p++) {
            const int g = t + 256 * p;          // granule id (16B = 8 bf16)
            const int row = g >> 3;
            const int c16 = g & 7;
            const int sw = c16 ^ (row & 7);     // XOR swizzle on 16B columns
            const uint32_t so = sb + (uint32_t)(row * 128 + sw * 16);
            const size_t go = (size_t)row * NN + k0 + c16 * 8;
            cpa16(so + AHI_OFF, Ah + go);
            cpa16(so + ALO_OFF, Al + go);
            cpa16(so + BHI_OFF, Bh + go);
            cpa16(so + BLO_OFF, Bl + go);
        }
        asm volatile("cp.async.commit_group;" ::: "memory");
    };

    float acc[4][4][4];
#pragma unroll
    for (int a = 0; a < 4; a++)
#pragma unroll
        for (int b = 0; b < 4; b++)
#pragma unroll
            for (int c = 0; c < 4; c++) acc[a][b][c] = 0.f;

    // ldmatrix lane geometry (x4: lanes 0-7/8-15/16-23/24-31 -> 4 matrices)
    const int t4 = l >> 3;
    const int l7 = l & 7;
    const int arow_in = ((t4 & 1) << 3) + l7;    // A: m-subrow
    const int brow_in = ((t4 >> 1) << 3) + l7;   // B: n-subrow
    const uint32_t abase = (uint32_t)((wm * 64 + arow_in) * 128);
    const uint32_t bbase = (uint32_t)((wn * 32 + brow_in) * 128);
    const int akg = t4 >> 1;                     // A k-granule select (k16 halves)
    const int bkg = t4 & 1;                      // B k-granule select

    // double-buffered fragments
    uint32_t ah[2][4][4], al[2][4][4];
    uint32_t bh[2][2][4], bl[2][2][4];

    load_stage(0, 0);
    load_stage(1, 64);

    for (int i = 0; i < NITER; i++) {
        asm volatile("cp.async.wait_group 1;" ::: "memory");
        __syncthreads();
        if (i + 2 < NITER) load_stage((i + 2) % 3, (i + 2) * 64);
        const uint32_t sb = sb0 + (uint32_t)(i % 3) * STAGE_BYTES;

        // prologue: fragments for ks=0
        {
            const uint32_t xa = (uint32_t)(((0 + akg) ^ l7) << 4);
            const uint32_t xb = (uint32_t)(((0 + bkg) ^ l7) << 4);
#pragma unroll
            for (int mt = 0; mt < 4; mt++) {
                LDSM4(ah[0][mt], sb + abase + (uint32_t)(mt * 16 * 128) + xa + AHI_OFF);
                LDSM4(al[0][mt], sb + abase + (uint32_t)(mt * 16 * 128) + xa + ALO_OFF);
            }
#pragma unroll
            for (int nh = 0; nh < 2; nh++) {
                LDSM4(bh[0][nh], sb + bbase + (uint32_t)(nh * 16 * 128) + xb + BHI_OFF);
                LDSM4(bl[0][nh], sb + bbase + (uint32_t)(nh * 16 * 128) + xb + BLO_OFF);
            }
        }

#pragma unroll
        for (int ks = 0; ks < 4; ks++) {
            const int cur = ks & 1;
            const int nxt = cur ^ 1;
            // prefetch fragments for ks+1 (hidden under this ks's 48 MMAs)
            if (ks < 3) {
                const uint32_t xa = (uint32_t)((((ks + 1) * 2 + akg) ^ l7) << 4);
                const uint32_t xb = (uint32_t)((((ks + 1) * 2 + bkg) ^ l7) << 4);
#pragma unroll
                for (int mt = 0; mt < 4; mt++) {
                    LDSM4(ah[nxt][mt], sb + abase + (uint32_t)(mt * 16 * 128) + xa + AHI_OFF);
                    LDSM4(al[nxt][mt], sb + abase + (uint32_t)(mt * 16 * 128) + xa + ALO_OFF);
                }
#pragma unroll
                for (int nh = 0; nh < 2; nh++) {
                    LDSM4(bh[nxt][nh], sb + bbase + (uint32_t)(nh * 16 * 128) + xb + BHI_OFF);
                    LDSM4(bl[nxt][nh], sb + bbase + (uint32_t)(nh * 16 * 128) + xb + BLO_OFF);
                }
            }

            // term 1: hi*hi
#pragma unroll
            for (int mt = 0; mt < 4; mt++)
#pragma unroll
                for (int n8 = 0; n8 < 4; n8++) {
                    const int nh = n8 >> 1, q = (n8 & 1) * 2;
                    MMA_BF16(acc[mt][n8], ah[cur][mt], bh[cur][nh][q], bh[cur][nh][q + 1]);
                }
            // term 2: lo*hi
#pragma unroll
            for (int mt = 0; mt < 4; mt++)
#pragma unroll
                for (int n8 = 0; n8 < 4; n8++) {
                    const int nh = n8 >> 1, q = (n8 & 1) * 2;
                    MMA_BF16(acc[mt][n8], al[cur][mt], bh[cur][nh][q], bh[cur][nh][q + 1]);
                }
            // term 3: hi*lo
#pragma unroll
            for (int mt = 0; mt < 4; mt++)
#pragma unroll
                for (int n8 = 0; n8 < 4; n8++) {
                    const int nh = n8 >> 1, q = (n8 & 1) * 2;
                    MMA_BF16(acc[mt][n8], ah[cur][mt], bl[cur][nh][q], bl[cur][nh][q + 1]);
                }
        }
    }

    // ---------------- epilogue ----------------
    float* Ynm = (MODE == 1) ? g_Y1nm : g_Y2nm;
    const int lm = l >> 2;
    const int lc = (l & 3) << 1;
#pragma unroll
    for (int mt = 0; mt < 4; mt++)
#pragma unroll
        for (int n8 = 0; n8 < 4; n8++) {
            const int r = bm + wm * 64 + mt * 16 + lm;
            const int col = bn + wn * 32 + n8 * 8 + lc;
            *(float2*)&Ynm[(size_t)r * NJ + col] =
                make_float2(acc[mt][n8][0], acc[mt][n8][1]);
            *(float2*)&Ynm[(size_t)(r + 8) * NJ + col] =
                make_float2(acc[mt][n8][2], acc[mt][n8][3]);
        }

    if (MODE == 1) {
        // transpose tile via smem (pitch 132), then coalesced bf16 hi/lo stores
        __syncthreads();
#pragma unroll
        for (int mt = 0; mt < 4; mt++)
#pragma unroll
            for (int n8 = 0; n8 < 4; n8++) {
                const int jl = wn * 32 + n8 * 8 + lc;
                const int ml = wm * 64 + mt * 16 + lm;
                dsm[jl * 132 + ml]           = acc[mt][n8][0];
                dsm[(jl + 1) * 132 + ml]     = acc[mt][n8][1];
                dsm[jl * 132 + ml + 8]       = acc[mt][n8][2];
                dsm[(jl + 1) * 132 + ml + 8] = acc[mt][n8][3];
            }
        __syncthreads();
#pragma unroll
        for (int it = 0; it < 16; it++) {
            const int j = wid * 16 + it;
            const int m4 = l * 4;
            const float4 v = *(const float4*)&dsm[j * 132 + m4];
            __nv_bfloat16 h0, h1, h2, h3, o0, o1, o2, o3;
            bf16_split(v.x, h0, o0);
            bf16_split(v.y, h1, o1);
            bf16_split(v.z, h2, o2);
            bf16_split(v.w, h3, o3);
            const size_t off = (size_t)(bn + j) * NN + bm + m4;
            __nv_bfloat162 hp0 = make_bfloat162(h0, h1), hp1 = make_bfloat162(h2, h3);
            __nv_bfloat162 lp0 = make_bfloat162(o0, o1), lp1 = make_bfloat162(o2, o3);
            uint2 hw, lw;
            hw.x = *(uint32_t*)&hp0; hw.y = *(uint32_t*)&hp1;
            lw.x = *(uint32_t*)&lp0; lw.y = *(uint32_t*)&lp1;
            *(uint2*)&g_Y1qhi[off] = hw;
            *(uint2*)&g_Y1qlo[off] = lw;
        }
    }
}

// ============================================================
// output: per node n, out[b,n,o] = A_n[b,ki] @ W_n[ki,o] + bias_n[o]
// ============================================================
__global__ __launch_bounds__(256) void output_kernel(const float* __restrict__ x,
                                                     const float* __restrict__ E,
                                                     const float* __restrict__ bp,
                                                     float* __restrict__ out) {
    extern __shared__ float sm[];
    float* As = sm;                 // 192 * 65
    float* Ws = sm + KI * 65;       // 192 * 64

    const int n = blockIdx.x;
    const int tid = threadIdx.x;

    for (int idx = tid; idx < NJ; idx += 256) {
        const int b = idx >> 6;
        const int i = idx & 63;
        const float xv = x[(size_t)b * (NN * NC) + n * NC + i];
        const float y1 = g_Y1nm[(size_t)n * NJ + idx];
        const float y2 = g_Y2nm[(size_t)n * NJ + idx];
        As[(i)       * 65 + b] = xv;
        As[(64 + i)  * 65 + b] = y1;
        As[(128 + i) * 65 + b] = 2.f * y2 - xv;
    }
    const float* Wrow = &g_W[(size_t)n * (KI * NC)];
    for (int idx = tid * 4; idx < KI * NC; idx += 1024)
        *(float4*)&Ws[idx] = *(const float4*)&Wrow[idx];
    __syncthreads();

    const int o0 = (tid % 16) * 4;
    const int b0 = (tid / 16) * 4;
    float acc[4][4] = {};
#pragma unroll 4
    for (int kk = 0; kk < KI; kk++) {
        const float a0 = As[kk * 65 + b0 + 0];
        const float a1 = As[kk * 65 + b0 + 1];
        const float a2 = As[kk * 65 + b0 + 2];
        const float a3 = As[kk * 65 + b0 + 3];
        const float4 w = *(const float4*)&Ws[kk * 64 + o0];
        acc[0][0] = fmaf(a0, w.x, acc[0][0]); acc[0][1] = fmaf(a0, w.y, acc[0][1]);
        acc[0][2] = fmaf(a0, w.z, acc[0][2]); acc[0][3] = fmaf(a0, w.w, acc[0][3]);
        acc[1][0] = fmaf(a1, w.x, acc[1][0]); acc[1][1] = fmaf(a1, w.y, acc[1][1]);
        acc[1][2] = fmaf(a1, w.z, acc[1][2]); acc[1][3] = fmaf(a1, w.w, acc[1][3]);
        acc[2][0] = fmaf(a2, w.x, acc[2][0]); acc[2][1] = fmaf(a2, w.y, acc[2][1]);
        acc[2][2] = fmaf(a2, w.z, acc[2][2]); acc[2][3] = fmaf(a2, w.w, acc[2][3]);
        acc[3][0] = fmaf(a3, w.x, acc[3][0]); acc[3][1] = fmaf(a3, w.y, acc[3][1]);
        acc[3][2] = fmaf(a3, w.z, acc[3][2]); acc[3][3] = fmaf(a3, w.w, acc[3][3]);
    }

    float bias[4];
#pragma unroll
    for (int oo = 0; oo < 4; oo++) {
        float s = 0.f;
#pragma unroll
        for (int d = 0; d < ND; d++) s = fmaf(E[n * ND + d], bp[d * NC + o0 + oo], s);
        bias[oo] = s;
    }

#pragma unroll
    for (int bb = 0; bb < 4; bb++) {
        float4 v = make_float4(acc[bb][0] + bias[0], acc[bb][1] + bias[1],
                               acc[bb][2] + bias[2], acc[bb][3] + bias[3]);
        *(float4*)&out[(size_t)(b0 + bb) * (NN * NC) + n * NC + o0] = v;
    }
}

// ============================================================
extern "C" void kernel_launch(void* const* d_in, const int* in_sizes, int n_in,
                              void* d_out, int out_size) {
    (void)in_sizes; (void)n_in; (void)out_size;
    const float* x  = (const float*)d_in[0];
    const float* E  = (const float*)d_in[1];
    const float* Wp = (const float*)d_in[2];
    const float* bp = (const float*)d_in[3];
    float* out = (float*)d_out;

    const int kOutSmem = (KI * 65 + KI * NC) * (int)sizeof(float);
    cudaFuncSetAttribute(output_kernel, cudaFuncAttributeMaxDynamicSharedMemorySize, kOutSmem);
    cudaFuncSetAttribute(gemm_bf16x3_kernel<1>, cudaFuncAttributeMaxDynamicSharedMemorySize, GEMM_SMEM);
    cudaFuncSetAttribute(gemm_bf16x3_kernel<2>, cudaFuncAttributeMaxDynamicSharedMemorySize, GEMM_SMEM);

    supports_kernel<<<NN, 256>>>(E);
    xq_kernel<<<dim3(NN / 32, NB), 256>>>(x);
    weights_kernel<<<dim3((KI * NC) / 256, NN / 16), 256>>>(E, Wp);

    dim3 ggrid(NJ / 128, NN / 128);   // (32, 16)
    gemm_bf16x3_kernel<1><<<ggrid, 256, GEMM_SMEM>>>();
    gemm_bf16x3_kernel<2><<<ggrid, 256, GEMM_SMEM>>>();

    output_kernel<<<NN, 256, kOutSmem>>>(x, E, bp, out);
}

// round 8
// speedup vs baseline: 1.6104x; 1.5262x over previous
#include <cuda_runtime.h>
#include <cuda_fp16.h>
#include <math.h>
#include <stdint.h>

#define NB 64
#define NN 2048
#define NC 64
#define ND 10
#define NJ 4096          // NB*NC
#define KI 192           // cheb_k * C_IN

// ------------------ scratch (static device globals) ------------------
__device__ __half g_Shi [NN * NN];
__device__ __half g_Slo [NN * NN];
__device__ __half g_Xq  [(size_t)NJ * NN];    // [j][m] fp16 single
__device__ __half g_Y1q [(size_t)NJ * NN];    // [j][m] fp16 single
__device__ float  g_Y1nm[(size_t)NN * NJ];    // [n][j]
__device__ float  g_Y2nm[(size_t)NN * NJ];
__device__ __half g_Whi [(size_t)NN * KI * NC];  // [n][ki][o]
__device__ __half g_Wlo [(size_t)NN * KI * NC];

// ------------------ helpers ------------------
__device__ __forceinline__ uint32_t smem_u32(const void* p) {
    uint32_t a;
    asm("{ .reg .u64 t; cvta.to.shared.u64 t, %1; cvt.u32.u64 %0, t; }" : "=r"(a) : "l"(p));
    return a;
}
__device__ __forceinline__ void cpa16(uint32_t s, const void* g) {
    asm volatile("cp.async.cg.shared.global [%0], [%1], 16;" :: "r"(s), "l"(g));
}
__device__ __forceinline__ void fp16_split(float v, __half& h, __half& l) {
    h = __float2half_rn(v);
    l = __float2half_rn(v - __half2float(h));
}

#define LDSM4(r, a) \
    asm volatile("ldmatrix.sync.aligned.m8n8.x4.shared.b16 {%0,%1,%2,%3}, [%4];" \
        : "=r"((r)[0]), "=r"((r)[1]), "=r"((r)[2]), "=r"((r)[3]) : "r"(a))

#define LDSM4T(r, a) \
    asm volatile("ldmatrix.sync.aligned.m8n8.x4.trans.shared.b16 {%0,%1,%2,%3}, [%4];" \
        : "=r"((r)[0]), "=r"((r)[1]), "=r"((r)[2]), "=r"((r)[3]) : "r"(a))

#define MMA_F16(c, a, b0, b1) \
    asm volatile("mma.sync.aligned.m16n8k16.row.col.f32.f16.f16.f32 " \
        "{%0,%1,%2,%3}, {%4,%5,%6,%7}, {%8,%9}, {%0,%1,%2,%3};" \
        : "+f"((c)[0]), "+f"((c)[1]), "+f"((c)[2]), "+f"((c)[3]) \
        : "r"((a)[0]), "r"((a)[1]), "r"((a)[2]), "r"((a)[3]), "r"(b0), "r"(b1))

// ============================================================
// supports: S[n,:] = softmax(relu(E[n]·E[m])), split fp16 hi/lo
// ============================================================
__global__ __launch_bounds__(256) void supports_kernel(const float* __restrict__ E) {
    __shared__ float vals[NN];
    __shared__ float red[256];
    const int n = blockIdx.x;
    const int tid = threadIdx.x;

    float en[ND];
#pragma unroll
    for (int d = 0; d < ND; d++) en[d] = E[n * ND + d];

    float lmax = -1e30f;
    for (int m = tid; m < NN; m += 256) {
        float v = 0.f;
#pragma unroll
        for (int d = 0; d < ND; d++) v = fmaf(en[d], E[m * ND + d], v);
        v = fmaxf(v, 0.f);
        vals[m] = v;
        lmax = fmaxf(lmax, v);
    }
    red[tid] = lmax; __syncthreads();
    for (int s = 128; s > 0; s >>= 1) { if (tid < s) red[tid] = fmaxf(red[tid], red[tid + s]); __syncthreads(); }
    const float gmax = red[0]; __syncthreads();

    float lsum = 0.f;
    for (int m = tid; m < NN; m += 256) {
        float e = expf(vals[m] - gmax);
        vals[m] = e; lsum += e;
    }
    red[tid] = lsum; __syncthreads();
    for (int s = 128; s > 0; s >>= 1) { if (tid < s) red[tid] += red[tid + s]; __syncthreads(); }
    const float inv = 1.f / red[0];
    for (int m = tid; m < NN; m += 256) {
        float v = vals[m] * inv;
        __half hi, lo; fp16_split(v, hi, lo);
        g_Shi[n * NN + m] = hi;
        g_Slo[n * NN + m] = lo;
    }
}

// ============================================================
// Xq builder: Xq[j = b*64+c][m] = fp16(x[b][m][c])
// ============================================================
__global__ __launch_bounds__(256) void xq_kernel(const float* __restrict__ x) {
    __shared__ float sm[64 * 33];
    const int m0 = blockIdx.x * 32;
    const int b  = blockIdx.y;
    const int t  = threadIdx.x;
#pragma unroll
    for (int p = 0; p < 8; p++) {
        int e = t + 256 * p;
        int r = e >> 6, c = e & 63;
        sm[c * 33 + r] = x[(size_t)b * (NN * NC) + (size_t)(m0 + r) * NC + c];
    }
    __syncthreads();
#pragma unroll
    for (int p = 0; p < 8; p++) {
        int e = t + 256 * p;
        int c = e >> 5, r = e & 31;
        g_Xq[(size_t)(b * 64 + c) * NN + m0 + r] = __float2half_rn(sm[c * 33 + r]);
    }
}

// ============================================================
// weights: W[n, ki, o] = sum_d E[n,d]*Wp[d,ki,o], split fp16 hi/lo
// ============================================================
__global__ __launch_bounds__(256) void weights_kernel(const float* __restrict__ E,
                                                      const float* __restrict__ Wp) {
    __shared__ float Es[16][ND];
    const int e0 = blockIdx.x * 256;
    const int n0 = blockIdx.y * 16;
    const int tid = threadIdx.x;
    if (tid < 16 * ND) Es[tid / ND][tid % ND] = E[(n0 + tid / ND) * ND + (tid % ND)];
    __syncthreads();
    const int e = e0 + tid;
    float wp[ND];
#pragma unroll
    for (int d = 0; d < ND; d++) wp[d] = Wp[d * (KI * NC) + e];
#pragma unroll
    for (int nn = 0; nn < 16; nn++) {
        float acc = 0.f;
#pragma unroll
        for (int d = 0; d < ND; d++) acc = fmaf(Es[nn][d], wp[d], acc);
        __half hi, lo; fp16_split(acc, hi, lo);
        const size_t idx = (size_t)(n0 + nn) * (KI * NC) + e;
        g_Whi[idx] = hi;
        g_Wlo[idx] = lo;
    }
}

// ============================================================
// fp16 2-term GEMM (m16n8k16): C[128x256] tile, 256 threads,
// 8 warps (2x4), warp tile 64x64. 3-stage cp.async, BK=64.
// computed = (Sh+Sl)*Bh  (B rounding exposed, ~3e-4 on Y, diluted in out)
// ============================================================
#define STAGE_BYTES 65536
#define AHI_OFF 0
#define ALO_OFF 16384
#define B_OFF   32768
#define GEMM_SMEM (3 * STAGE_BYTES)
#define NITER (NN / 64)   // 32

template <int MODE>
__global__ void __launch_bounds__(256, 1) gemm_fp16x2_kernel() {
    extern __shared__ float dsm[];
    const int t = threadIdx.x;
    const int l = t & 31;
    const int wid = t >> 5;
    const int wm = wid >> 2;       // 0..1  (m, 64 rows each)
    const int wn = wid & 3;        // 0..3  (n, 64 cols each)
    const int bm = blockIdx.y * 128;
    const int bn = blockIdx.x * 256;

    const __half* Ah = g_Shi + (size_t)bm * NN;
    const __half* Al = g_Slo + (size_t)bm * NN;
    const __half* Bp = (MODE == 1 ? g_Xq : g_Y1q) + (size_t)bn * NN;

    const uint32_t sb0 = smem_u32(dsm);

    auto load_stage = [&](int s, int k0) {
        const uint32_t sb = sb0 + (uint32_t)s * STAGE_BYTES;
#pragma unroll
        for (int p = 0; p < 4; p++) {          // A hi+lo: 128 rows x 8 granules
            const int g = t + 256 * p;
            const int row = g >> 3;
            const int c16 = g & 7;
            const int sw = c16 ^ (row & 7);
            const uint32_t so = sb + (uint32_t)(row * 128 + sw * 16);
            const size_t go = (size_t)row * NN + k0 + c16 * 8;
            cpa16(so + AHI_OFF, Ah + go);
            cpa16(so + ALO_OFF, Al + go);
        }
#pragma unroll
        for (int p = 0; p < 8; p++) {          // B: 256 rows x 8 granules
            const int g = t + 256 * p;
            const int row = g >> 3;
            const int c16 = g & 7;
            const int sw = c16 ^ (row & 7);
            const uint32_t so = sb + (uint32_t)(row * 128 + sw * 16);
            cpa16(so + B_OFF, Bp + (size_t)row * NN + k0 + c16 * 8);
        }
        asm volatile("cp.async.commit_group;" ::: "memory");
    };

    float acc[4][8][4];
#pragma unroll
    for (int a = 0; a < 4; a++)
#pragma unroll
        for (int b = 0; b < 8; b++)
#pragma unroll
            for (int c = 0; c < 4; c++) acc[a][b][c] = 0.f;

    const int t4 = l >> 3;
    const int l7 = l & 7;
    const int arow_in = ((t4 & 1) << 3) + l7;
    const int brow_in = ((t4 >> 1) << 3) + l7;
    const uint32_t abase = (uint32_t)((wm * 64 + arow_in) * 128);
    const uint32_t bbase = (uint32_t)((wn * 64 + brow_in) * 128);
    const int akg = t4 >> 1;
    const int bkg = t4 & 1;

    load_stage(0, 0);
    load_stage(1, 64);

    for (int i = 0; i < NITER; i++) {
        asm volatile("cp.async.wait_group 1;" ::: "memory");
        __syncthreads();
        if (i + 2 < NITER) load_stage((i + 2) % 3, (i + 2) * 64);
        const uint32_t sb = sb0 + (uint32_t)(i % 3) * STAGE_BYTES;
#pragma unroll
        for (int ks = 0; ks < 4; ks++) {
            const uint32_t xa = (uint32_t)(((ks * 2 + akg) ^ l7) << 4);
            const uint32_t xb = (uint32_t)(((ks * 2 + bkg) ^ l7) << 4);
            uint32_t ah[4][4], al[4][4], bf[4][4];

#pragma unroll
            for (int mt = 0; mt < 4; mt++)
                LDSM4(ah[mt], sb + abase + (uint32_t)(mt * 16 * 128) + xa + AHI_OFF);
#pragma unroll
            for (int nh = 0; nh < 4; nh++)
                LDSM4(bf[nh], sb + bbase + (uint32_t)(nh * 16 * 128) + xb + B_OFF);

            // term 1: hi*B
#pragma unroll
            for (int mt = 0; mt < 4; mt++)
#pragma unroll
                for (int n8 = 0; n8 < 8; n8++) {
                    const int nh = n8 >> 1, q = (n8 & 1) * 2;
                    MMA_F16(acc[mt][n8], ah[mt], bf[nh][q], bf[nh][q + 1]);
                }
            // term 2: lo*B
#pragma unroll
            for (int mt = 0; mt < 4; mt++)
                LDSM4(al[mt], sb + abase + (uint32_t)(mt * 16 * 128) + xa + ALO_OFF);
#pragma unroll
            for (int mt = 0; mt < 4; mt++)
#pragma unroll
                for (int n8 = 0; n8 < 8; n8++) {
                    const int nh = n8 >> 1, q = (n8 & 1) * 2;
                    MMA_F16(acc[mt][n8], al[mt], bf[nh][q], bf[nh][q + 1]);
                }
        }
    }

    // ---------------- epilogue ----------------
    float* Ynm = (MODE == 1) ? g_Y1nm : g_Y2nm;
    const int lm = l >> 2;
    const int lc = (l & 3) << 1;
#pragma unroll
    for (int mt = 0; mt < 4; mt++)
#pragma unroll
        for (int n8 = 0; n8 < 8; n8++) {
            const int r = bm + wm * 64 + mt * 16 + lm;
            const int col = bn + wn * 64 + n8 * 8 + lc;
            *(float2*)&Ynm[(size_t)r * NJ + col] =
                make_float2(acc[mt][n8][0], acc[mt][n8][1]);
            *(float2*)&Ynm[(size_t)(r + 8) * NJ + col] =
                make_float2(acc[mt][n8][2], acc[mt][n8][3]);
        }

    if (MODE == 1) {
        // transpose 128m x 256j tile via smem, write Y1q fp16 [j][m]
        __syncthreads();
#pragma unroll
        for (int mt = 0; mt < 4; mt++)
#pragma unroll
            for (int n8 = 0; n8 < 8; n8++) {
                const int jl = wn * 64 + n8 * 8 + lc;
                const int ml = wm * 64 + mt * 16 + lm;
                dsm[jl * 132 + ml]           = acc[mt][n8][0];
                dsm[(jl + 1) * 132 + ml]     = acc[mt][n8][1];
                dsm[jl * 132 + ml + 8]       = acc[mt][n8][2];
                dsm[(jl + 1) * 132 + ml + 8] = acc[mt][n8][3];
            }
        __syncthreads();
#pragma unroll
        for (int it = 0; it < 32; it++) {
            const int j = wid * 32 + it;
            const int m4 = l * 4;
            const float4 v = *(const float4*)&dsm[j * 132 + m4];
            __half2 p0 = __floats2half2_rn(v.x, v.y);
            __half2 p1 = __floats2half2_rn(v.z, v.w);
            uint2 w;
            w.x = *(uint32_t*)&p0; w.y = *(uint32_t*)&p1;
            *(uint2*)&g_Y1q[(size_t)(bn + j) * NN + bm + m4] = w;
        }
    }
}

// ============================================================
// output (tensor-core): per node n, out[b,o] = A[b,ki] @ W[ki,o] + bias
//   A channels: {x, Y1, 2*Y2-x}; fp16 3-term (Ah*Wh + Al*Wh + Ah*Wl)
//   256 threads, 8 warps (2m x 4o), warp tile 32x16, K=192.
// ============================================================
#define OUT_SMEM (96 * 1024)

__global__ void __launch_bounds__(256, 2) output_kernel(const float* __restrict__ x,
                                                        const float* __restrict__ E,
                                                        const float* __restrict__ bp,
                                                        float* __restrict__ out) {
    extern __shared__ char osm[];
    const uint32_t base = smem_u32(osm);
    const uint32_t AHI = base;
    const uint32_t ALO = base + 24576;
    const uint32_t WHI = base + 49152;
    const uint32_t WLO = base + 73728;

    const int n = blockIdx.x;
    const int tid = threadIdx.x;
    const int l = tid & 31;
    const int wid = tid >> 5;
    const int wm = wid >> 2;     // 0..1 (b, 32 rows)
    const int wn = wid & 3;      // 0..3 (o, 16 cols)

    // ---- load W hi/lo into swizzled smem [ki][o] (128B rows) ----
    const __half* Whg = g_Whi + (size_t)n * (KI * NC);
    const __half* Wlg = g_Wlo + (size_t)n * (KI * NC);
#pragma unroll
    for (int p = 0; p < 6; p++) {
        const int g = tid + 256 * p;     // 1536 granules per plane
        const int ki = g >> 3;
        const int og = g & 7;
        const uint32_t dst = (uint32_t)(ki * 128 + ((og ^ (ki & 7)) << 4));
        cpa16(WHI + dst, Whg + ki * 64 + og * 8);
        cpa16(WLO + dst, Wlg + ki * 64 + og * 8);
    }
    asm volatile("cp.async.commit_group;" ::: "memory");

    // ---- build A planes [b=64][ki=192] fp16 hi/lo, swizzled 384B rows ----
    for (int e = tid; e < NJ; e += 256) {
        const int b = e >> 6;
        const int i = e & 63;
        const float xv = x[(size_t)b * (NN * NC) + n * NC + i];
        const float y1 = g_Y1nm[(size_t)n * NJ + e];
        const float y2 = g_Y2nm[(size_t)n * NJ + e];
        const float vals[3] = { xv, y1, 2.f * y2 - xv };
#pragma unroll
        for (int kch = 0; kch < 3; kch++) {
            const int ki = kch * 64 + i;
            __half hi, lo; fp16_split(vals[kch], hi, lo);
            const uint32_t addr = (uint32_t)(b * 384 + ((ki >> 6) << 7) +
                ((((ki >> 3) & 7) ^ (b & 7)) << 4) + ((ki & 7) << 1));
            *(__half*)(osm + (AHI - base) + addr) = hi;
            *(__half*)(osm + (ALO - base) + addr) = lo;
        }
    }
    asm volatile("cp.async.wait_group 0;" ::: "memory");
    __syncthreads();

    // ---- MMA: 12 k16-steps, 3 terms ----
    float acc[2][2][4];
#pragma unroll
    for (int a = 0; a < 2; a++)
#pragma unroll
        for (int b = 0; b < 2; b++)
#pragma unroll
            for (int c = 0; c < 4; c++) acc[a][b][c] = 0.f;

    const int t4 = l >> 3;
    const int l7 = l & 7;
    const int arow_in = ((t4 & 1) << 3) + l7;
    const int akg = t4 >> 1;
    const int wrow_in = ((t4 & 1) << 3) + l7;
    const int wog = wn * 2 + (t4 >> 1);

#pragma unroll
    for (int ks = 0; ks < 12; ks++) {
        uint32_t ahf[2][4], alf[2][4], whf[4], wlf[4];
        const int kg = ks * 2 + akg;
#pragma unroll
        for (int mt = 0; mt < 2; mt++) {
            const int row = wm * 32 + mt * 16 + arow_in;
            const uint32_t aaddr = (uint32_t)(row * 384 + ((kg >> 3) << 7) +
                (((kg & 7) ^ (row & 7)) << 4));
            LDSM4(ahf[mt], AHI + aaddr);
            LDSM4(alf[mt], ALO + aaddr);
        }
        {
            const int wrow = ks * 16 + wrow_in;
            const uint32_t waddr = (uint32_t)(wrow * 128 + ((wog ^ (wrow & 7)) << 4));
            LDSM4T(whf, WHI + waddr);
            LDSM4T(wlf, WLO + waddr);
        }
#pragma unroll
        for (int mt = 0; mt < 2; mt++)
#pragma unroll
            for (int n8 = 0; n8 < 2; n8++)
                MMA_F16(acc[mt][n8], ahf[mt], whf[n8 * 2], whf[n8 * 2 + 1]);
#pragma unroll
        for (int mt = 0; mt < 2; mt++)
#pragma unroll
            for (int n8 = 0; n8 < 2; n8++)
                MMA_F16(acc[mt][n8], alf[mt], whf[n8 * 2], whf[n8 * 2 + 1]);
#pragma unroll
        for (int mt = 0; mt < 2; mt++)
#pragma unroll
            for (int n8 = 0; n8 < 2; n8++)
                MMA_F16(acc[mt][n8], ahf[mt], wlf[n8 * 2], wlf[n8 * 2 + 1]);
    }

    // ---- bias + write ----
    const int lm = l >> 2;
    const int lc = (l & 3) << 1;
    float bias[2][2];
#pragma unroll
    for (int n8 = 0; n8 < 2; n8++)
#pragma unroll
        for (int cc = 0; cc < 2; cc++) {
            const int o = wn * 16 + n8 * 8 + lc + cc;
            float s = 0.f;
#pragma unroll
            for (int d = 0; d < ND; d++) s = fmaf(E[n * ND + d], bp[d * NC + o], s);
            bias[n8][cc] = s;
        }

#pragma unroll
    for (int mt = 0; mt < 2; mt++)
#pragma unroll
        for (int n8 = 0; n8 < 2; n8++) {
            const int b0 = wm * 32 + mt * 16 + lm;
            const int col = wn * 16 + n8 * 8 + lc;
            *(float2*)&out[(size_t)b0 * (NN * NC) + n * NC + col] =
                make_float2(acc[mt][n8][0] + bias[n8][0], acc[mt][n8][1] + bias[n8][1]);
            *(float2*)&out[(size_t)(b0 + 8) * (NN * NC) + n * NC + col] =
                make_float2(acc[mt][n8][2] + bias[n8][0], acc[mt][n8][3] + bias[n8][1]);
        }
}

// ============================================================
extern "C" void kernel_launch(void* const* d_in, const int* in_sizes, int n_in,
                              void* d_out, int out_size) {
    (void)in_sizes; (void)n_in; (void)out_size;
    const float* x  = (const float*)d_in[0];
    const float* E  = (const float*)d_in[1];
    const float* Wp = (const float*)d_in[2];
    const float* bp = (const float*)d_in[3];
    float* out = (float*)d_out;

    cudaFuncSetAttribute(output_kernel, cudaFuncAttributeMaxDynamicSharedMemorySize, OUT_SMEM);
    cudaFuncSetAttribute(gemm_fp16x2_kernel<1>, cudaFuncAttributeMaxDynamicSharedMemorySize, GEMM_SMEM);
    cudaFuncSetAttribute(gemm_fp16x2_kernel<2>, cudaFuncAttributeMaxDynamicSharedMemorySize, GEMM_SMEM);

    supports_kernel<<<NN, 256>>>(E);
    xq_kernel<<<dim3(NN / 32, NB), 256>>>(x);
    weights_kernel<<<dim3((KI * NC) / 256, NN / 16), 256>>>(E, Wp);

    dim3 ggrid(NJ / 256, NN / 128);   // (16, 16) = 256 CTAs
    gemm_fp16x2_kernel<1><<<ggrid, 256, GEMM_SMEM>>>();
    gemm_fp16x2_kernel<2><<<ggrid, 256, GEMM_SMEM>>>();

    output_kernel<<<NN, 256, OUT_SMEM>>>(x, E, bp, out);
}

// round 9
// speedup vs baseline: 2.2281x; 1.3835x over previous
#include <cuda_runtime.h>
#include <cuda_fp16.h>
#include <math.h>
#include <stdint.h>

#define NB 64
#define NN 2048
#define NC 64
#define ND 10
#define NJ 4096          // NB*NC
#define KI 192           // cheb_k * C_IN

// ------------------ scratch (static device globals) ------------------
__device__ __half g_S   [NN * NN];            // fp16 supports
__device__ __half g_Xq  [(size_t)NJ * NN];    // [j][m] fp16
__device__ __half g_Y1q [(size_t)NJ * NN];    // [j][m] fp16
__device__ float  g_Y1nm[(size_t)NN * NJ];    // [n][j]
__device__ float  g_Y2nm[(size_t)NN * NJ];
__device__ __half g_Whi [(size_t)NN * KI * NC];  // [n][ki][o]
__device__ __half g_Wlo [(size_t)NN * KI * NC];

// ------------------ helpers ------------------
__device__ __forceinline__ uint32_t smem_u32(const void* p) {
    uint32_t a;
    asm("{ .reg .u64 t; cvta.to.shared.u64 t, %1; cvt.u32.u64 %0, t; }" : "=r"(a) : "l"(p));
    return a;
}
__device__ __forceinline__ void cpa16(uint32_t s, const void* g) {
    asm volatile("cp.async.cg.shared.global [%0], [%1], 16;" :: "r"(s), "l"(g));
}
__device__ __forceinline__ void fp16_split(float v, __half& h, __half& l) {
    h = __float2half_rn(v);
    l = __float2half_rn(v - __half2float(h));
}

#define LDSM4(r, a) \
    asm volatile("ldmatrix.sync.aligned.m8n8.x4.shared.b16 {%0,%1,%2,%3}, [%4];" \
        : "=r"((r)[0]), "=r"((r)[1]), "=r"((r)[2]), "=r"((r)[3]) : "r"(a))

#define LDSM4T(r, a) \
    asm volatile("ldmatrix.sync.aligned.m8n8.x4.trans.shared.b16 {%0,%1,%2,%3}, [%4];" \
        : "=r"((r)[0]), "=r"((r)[1]), "=r"((r)[2]), "=r"((r)[3]) : "r"(a))

#define MMA_F16(c, a, b0, b1) \
    asm volatile("mma.sync.aligned.m16n8k16.row.col.f32.f16.f16.f32 " \
        "{%0,%1,%2,%3}, {%4,%5,%6,%7}, {%8,%9}, {%0,%1,%2,%3};" \
        : "+f"((c)[0]), "+f"((c)[1]), "+f"((c)[2]), "+f"((c)[3]) \
        : "r"((a)[0]), "r"((a)[1]), "r"((a)[2]), "r"((a)[3]), "r"(b0), "r"(b1))

// ============================================================
// supports: S[n,:] = softmax(relu(E[n]·E[m])) -> fp16
// ============================================================
__global__ __launch_bounds__(256) void supports_kernel(const float* __restrict__ E) {
    __shared__ float vals[NN];
    __shared__ float red[256];
    const int n = blockIdx.x;
    const int tid = threadIdx.x;

    float en[ND];
#pragma unroll
    for (int d = 0; d < ND; d++) en[d] = E[n * ND + d];

    float lmax = -1e30f;
    for (int m = tid; m < NN; m += 256) {
        float v = 0.f;
#pragma unroll
        for (int d = 0; d < ND; d++) v = fmaf(en[d], E[m * ND + d], v);
        v = fmaxf(v, 0.f);
        vals[m] = v;
        lmax = fmaxf(lmax, v);
    }
    red[tid] = lmax; __syncthreads();
    for (int s = 128; s > 0; s >>= 1) { if (tid < s) red[tid] = fmaxf(red[tid], red[tid + s]); __syncthreads(); }
    const float gmax = red[0]; __syncthreads();

    float lsum = 0.f;
    for (int m = tid; m < NN; m += 256) {
        float e = expf(vals[m] - gmax);
        vals[m] = e; lsum += e;
    }
    red[tid] = lsum; __syncthreads();
    for (int s = 128; s > 0; s >>= 1) { if (tid < s) red[tid] += red[tid + s]; __syncthreads(); }
    const float inv = 1.f / red[0];
    for (int m = tid; m < NN; m += 256)
        g_S[n * NN + m] = __float2half_rn(vals[m] * inv);
}

// ============================================================
// Xq builder: Xq[j = b*64+c][m] = fp16(x[b][m][c])
// ============================================================
__global__ __launch_bounds__(256) void xq_kernel(const float* __restrict__ x) {
    __shared__ float sm[64 * 33];
    const int m0 = blockIdx.x * 32;
    const int b  = blockIdx.y;
    const int t  = threadIdx.x;
#pragma unroll
    for (int p = 0; p < 8; p++) {
        int e = t + 256 * p;
        int r = e >> 6, c = e & 63;
        sm[c * 33 + r] = x[(size_t)b * (NN * NC) + (size_t)(m0 + r) * NC + c];
    }
    __syncthreads();
#pragma unroll
    for (int p = 0; p < 8; p++) {
        int e = t + 256 * p;
        int c = e >> 5, r = e & 31;
        g_Xq[(size_t)(b * 64 + c) * NN + m0 + r] = __float2half_rn(sm[c * 33 + r]);
    }
}

// ============================================================
// weights: W[n, ki, o] = sum_d E[n,d]*Wp[d,ki,o], split fp16 hi/lo
// ============================================================
__global__ __launch_bounds__(256) void weights_kernel(const float* __restrict__ E,
                                                      const float* __restrict__ Wp) {
    __shared__ float Es[16][ND];
    const int e0 = blockIdx.x * 256;
    const int n0 = blockIdx.y * 16;
    const int tid = threadIdx.x;
    if (tid < 16 * ND) Es[tid / ND][tid % ND] = E[(n0 + tid / ND) * ND + (tid % ND)];
    __syncthreads();
    const int e = e0 + tid;
    float wp[ND];
#pragma unroll
    for (int d = 0; d < ND; d++) wp[d] = Wp[d * (KI * NC) + e];
#pragma unroll
    for (int nn = 0; nn < 16; nn++) {
        float acc = 0.f;
#pragma unroll
        for (int d = 0; d < ND; d++) acc = fmaf(Es[nn][d], wp[d], acc);
        __half hi, lo; fp16_split(acc, hi, lo);
        const size_t idx = (size_t)(n0 + nn) * (KI * NC) + e;
        g_Whi[idx] = hi;
        g_Wlo[idx] = lo;
    }
}

// ============================================================
// single-term fp16 GEMM (m16n8k16): C[128x256] tile, 256 threads,
// 8 warps (2x4), warp tile 64x64. 4-stage cp.async, BK=64.
// Register double-buffered fragments (prefetch ks+1 during ks MMAs).
// ============================================================
#define STG_A 0
#define STG_B 16384
#define STAGE_BYTES 49152
#define NSTAGE 4
#define GEMM_SMEM (NSTAGE * STAGE_BYTES)   // 192 KB
#define NITER (NN / 64)   // 32

template <int MODE>
__global__ void __launch_bounds__(256, 1) gemm_fp16_kernel() {
    extern __shared__ float dsm[];
    const int t = threadIdx.x;
    const int l = t & 31;
    const int wid = t >> 5;
    const int wm = wid >> 2;       // 0..1  (m, 64 rows each)
    const int wn = wid & 3;        // 0..3  (n, 64 cols each)
    const int bm = blockIdx.y * 128;
    const int bn = blockIdx.x * 256;

    const __half* Ap = g_S + (size_t)bm * NN;
    const __half* Bp = (MODE == 1 ? g_Xq : g_Y1q) + (size_t)bn * NN;

    const uint32_t sb0 = smem_u32(dsm);

    auto load_stage = [&](int s, int k0) {
        const uint32_t sb = sb0 + (uint32_t)s * STAGE_BYTES;
#pragma unroll
        for (int p = 0; p < 4; p++) {          // A: 128 rows x 8 granules
            const int g = t + 256 * p;
            const int row = g >> 3;
            const int c16 = g & 7;
            const int sw = c16 ^ (row & 7);
            cpa16(sb + STG_A + (uint32_t)(row * 128 + sw * 16),
                  Ap + (size_t)row * NN + k0 + c16 * 8);
        }
#pragma unroll
        for (int p = 0; p < 8; p++) {          // B: 256 rows x 8 granules
            const int g = t + 256 * p;
            const int row = g >> 3;
            const int c16 = g & 7;
            const int sw = c16 ^ (row & 7);
            cpa16(sb + STG_B + (uint32_t)(row * 128 + sw * 16),
                  Bp + (size_t)row * NN + k0 + c16 * 8);
        }
        asm volatile("cp.async.commit_group;" ::: "memory");
    };

    float acc[4][8][4];
#pragma unroll
    for (int a = 0; a < 4; a++)
#pragma unroll
        for (int b = 0; b < 8; b++)
#pragma unroll
            for (int c = 0; c < 4; c++) acc[a][b][c] = 0.f;

    const int t4 = l >> 3;
    const int l7 = l & 7;
    const int arow_in = ((t4 & 1) << 3) + l7;
    const int brow_in = ((t4 >> 1) << 3) + l7;
    const uint32_t abase = (uint32_t)((wm * 64 + arow_in) * 128);
    const uint32_t bbase = (uint32_t)((wn * 64 + brow_in) * 128);
    const int akg = t4 >> 1;
    const int bkg = t4 & 1;

    uint32_t af[2][4][4], bf[2][4][4];

    load_stage(0, 0);
    load_stage(1, 64);
    load_stage(2, 128);

    for (int i = 0; i < NITER; i++) {
        asm volatile("cp.async.wait_group 2;" ::: "memory");
        __syncthreads();
        if (i + 3 < NITER) load_stage((i + 3) & 3, (i + 3) * 64);
        const uint32_t sb = sb0 + (uint32_t)(i & 3) * STAGE_BYTES;

        // prologue: fragments for ks=0
        {
            const uint32_t xa = (uint32_t)(((0 + akg) ^ l7) << 4);
            const uint32_t xb = (uint32_t)(((0 + bkg) ^ l7) << 4);
#pragma unroll
            for (int mt = 0; mt < 4; mt++)
                LDSM4(af[0][mt], sb + STG_A + abase + (uint32_t)(mt * 16 * 128) + xa);
#pragma unroll
            for (int nh = 0; nh < 4; nh++)
                LDSM4(bf[0][nh], sb + STG_B + bbase + (uint32_t)(nh * 16 * 128) + xb);
        }

#pragma unroll
        for (int ks = 0; ks < 4; ks++) {
            const int cur = ks & 1;
            const int nxt = cur ^ 1;
            if (ks < 3) {
                const uint32_t xa = (uint32_t)((((ks + 1) * 2 + akg) ^ l7) << 4);
                const uint32_t xb = (uint32_t)((((ks + 1) * 2 + bkg) ^ l7) << 4);
#pragma unroll
                for (int mt = 0; mt < 4; mt++)
                    LDSM4(af[nxt][mt], sb + STG_A + abase + (uint32_t)(mt * 16 * 128) + xa);
#pragma unroll
                for (int nh = 0; nh < 4; nh++)
                    LDSM4(bf[nxt][nh], sb + STG_B + bbase + (uint32_t)(nh * 16 * 128) + xb);
            }
#pragma unroll
            for (int mt = 0; mt < 4; mt++)
#pragma unroll
                for (int n8 = 0; n8 < 8; n8++) {
                    const int nh = n8 >> 1, q = (n8 & 1) * 2;
                    MMA_F16(acc[mt][n8], af[cur][mt], bf[cur][nh][q], bf[cur][nh][q + 1]);
                }
        }
    }

    // ---------------- epilogue ----------------
    float* Ynm = (MODE == 1) ? g_Y1nm : g_Y2nm;
    const int lm = l >> 2;
    const int lc = (l & 3) << 1;
#pragma unroll
    for (int mt = 0; mt < 4; mt++)
#pragma unroll
        for (int n8 = 0; n8 < 8; n8++) {
            const int r = bm + wm * 64 + mt * 16 + lm;
            const int col = bn + wn * 64 + n8 * 8 + lc;
            *(float2*)&Ynm[(size_t)r * NJ + col] =
                make_float2(acc[mt][n8][0], acc[mt][n8][1]);
            *(float2*)&Ynm[(size_t)(r + 8) * NJ + col] =
                make_float2(acc[mt][n8][2], acc[mt][n8][3]);
        }

    if (MODE == 1) {
        // transpose 128m x 256j tile via smem, write Y1q fp16 [j][m]
        __syncthreads();
#pragma unroll
        for (int mt = 0; mt < 4; mt++)
#pragma unroll
            for (int n8 = 0; n8 < 8; n8++) {
                const int jl = wn * 64 + n8 * 8 + lc;
                const int ml = wm * 64 + mt * 16 + lm;
                dsm[jl * 132 + ml]           = acc[mt][n8][0];
                dsm[(jl + 1) * 132 + ml]     = acc[mt][n8][1];
                dsm[jl * 132 + ml + 8]       = acc[mt][n8][2];
                dsm[(jl + 1) * 132 + ml + 8] = acc[mt][n8][3];
            }
        __syncthreads();
#pragma unroll
        for (int it = 0; it < 32; it++) {
            const int j = wid * 32 + it;
            const int m4 = l * 4;
            const float4 v = *(const float4*)&dsm[j * 132 + m4];
            __half2 p0 = __floats2half2_rn(v.x, v.y);
            __half2 p1 = __floats2half2_rn(v.z, v.w);
            uint2 w;
            w.x = *(uint32_t*)&p0; w.y = *(uint32_t*)&p1;
            *(uint2*)&g_Y1q[(size_t)(bn + j) * NN + bm + m4] = w;
        }
    }
}

// ============================================================
// output (tensor-core): per node n, out[b,o] = A[b,ki] @ W[ki,o] + bias
//   A channels: {x, Y1, 2*Y2-x}; fp16 3-term (Ah*Wh + Al*Wh + Ah*Wl)
// ============================================================
#define OUT_SMEM (96 * 1024)

__global__ void __launch_bounds__(256, 2) output_kernel(const float* __restrict__ x,
                                                        const float* __restrict__ E,
                                                        const float* __restrict__ bp,
                                                        float* __restrict__ out) {
    extern __shared__ char osm[];
    const uint32_t base = smem_u32(osm);
    const uint32_t AHI = base;
    const uint32_t ALO = base + 24576;
    const uint32_t WHI = base + 49152;
    const uint32_t WLO = base + 73728;

    const int n = blockIdx.x;
    const int tid = threadIdx.x;
    const int l = tid & 31;
    const int wid = tid >> 5;
    const int wm = wid >> 2;     // 0..1 (b, 32 rows)
    const int wn = wid & 3;      // 0..3 (o, 16 cols)

    const __half* Whg = g_Whi + (size_t)n * (KI * NC);
    const __half* Wlg = g_Wlo + (size_t)n * (KI * NC);
#pragma unroll
    for (int p = 0; p < 6; p++) {
        const int g = tid + 256 * p;
        const int ki = g >> 3;
        const int og = g & 7;
        const uint32_t dst = (uint32_t)(ki * 128 + ((og ^ (ki & 7)) << 4));
        cpa16(WHI + dst, Whg + ki * 64 + og * 8);
        cpa16(WLO + dst, Wlg + ki * 64 + og * 8);
    }
    asm volatile("cp.async.commit_group;" ::: "memory");

    for (int e = tid; e < NJ; e += 256) {
        const int b = e >> 6;
        const int i = e & 63;
        const float xv = x[(size_t)b * (NN * NC) + n * NC + i];
        const float y1 = g_Y1nm[(size_t)n * NJ + e];
        const float y2 = g_Y2nm[(size_t)n * NJ + e];
        const float vals[3] = { xv, y1, 2.f * y2 - xv };
#pragma unroll
        for (int kch = 0; kch < 3; kch++) {
            const int ki = kch * 64 + i;
            __half hi, lo; fp16_split(vals[kch], hi, lo);
            const uint32_t addr = (uint32_t)(b * 384 + ((ki >> 6) << 7) +
                ((((ki >> 3) & 7) ^ (b & 7)) << 4) + ((ki & 7) << 1));
            *(__half*)(osm + (AHI - base) + addr) = hi;
            *(__half*)(osm + (ALO - base) + addr) = lo;
        }
    }
    asm volatile("cp.async.wait_group 0;" ::: "memory");
    __syncthreads();

    float acc[2][2][4];
#pragma unroll
    for (int a = 0; a < 2; a++)
#pragma unroll
        for (int b = 0; b < 2; b++)
#pragma unroll
            for (int c = 0; c < 4; c++) acc[a][b][c] = 0.f;

    const int t4 = l >> 3;
    const int l7 = l & 7;
    const int arow_in = ((t4 & 1) << 3) + l7;
    const int akg = t4 >> 1;
    const int wrow_in = ((t4 & 1) << 3) + l7;
    const int wog = wn * 2 + (t4 >> 1);

#pragma unroll
    for (int ks = 0; ks < 12; ks++) {
        uint32_t ahf[2][4], alf[2][4], whf[4], wlf[4];
        const int kg = ks * 2 + akg;
#pragma unroll
        for (int mt = 0; mt < 2; mt++) {
            const int row = wm * 32 + mt * 16 + arow_in;
            const uint32_t aaddr = (uint32_t)(row * 384 + ((kg >> 3) << 7) +
                (((kg & 7) ^ (row & 7)) << 4));
            LDSM4(ahf[mt], AHI + aaddr);
            LDSM4(alf[mt], ALO + aaddr);
        }
        {
            const int wrow = ks * 16 + wrow_in;
            const uint32_t waddr = (uint32_t)(wrow * 128 + ((wog ^ (wrow & 7)) << 4));
            LDSM4T(whf, WHI + waddr);
            LDSM4T(wlf, WLO + waddr);
        }
#pragma unroll
        for (int mt = 0; mt < 2; mt++)
#pragma unroll
            for (int n8 = 0; n8 < 2; n8++)
                MMA_F16(acc[mt][n8], ahf[mt], whf[n8 * 2], whf[n8 * 2 + 1]);
#pragma unroll
        for (int mt = 0; mt < 2; mt++)
#pragma unroll
            for (int n8 = 0; n8 < 2; n8++)
                MMA_F16(acc[mt][n8], alf[mt], whf[n8 * 2], whf[n8 * 2 + 1]);
#pragma unroll
        for (int mt = 0; mt < 2; mt++)
#pragma unroll
            for (int n8 = 0; n8 < 2; n8++)
                MMA_F16(acc[mt][n8], ahf[mt], wlf[n8 * 2], wlf[n8 * 2 + 1]);
    }

    const int lm = l >> 2;
    const int lc = (l & 3) << 1;
    float bias[2][2];
#pragma unroll
    for (int n8 = 0; n8 < 2; n8++)
#pragma unroll
        for (int cc = 0; cc < 2; cc++) {
            const int o = wn * 16 + n8 * 8 + lc + cc;
            float s = 0.f;
#pragma unroll
            for (int d = 0; d < ND; d++) s = fmaf(E[n * ND + d], bp[d * NC + o], s);
            bias[n8][cc] = s;
        }

#pragma unroll
    for (int mt = 0; mt < 2; mt++)
#pragma unroll
        for (int n8 = 0; n8 < 2; n8++) {
            const int b0 = wm * 32 + mt * 16 + lm;
            const int col = wn * 16 + n8 * 8 + lc;
            *(float2*)&out[(size_t)b0 * (NN * NC) + n * NC + col] =
                make_float2(acc[mt][n8][0] + bias[n8][0], acc[mt][n8][1] + bias[n8][1]);
            *(float2*)&out[(size_t)(b0 + 8) * (NN * NC) + n * NC + col] =
                make_float2(acc[mt][n8][2] + bias[n8][0], acc[mt][n8][3] + bias[n8][1]);
        }
}

// ============================================================
extern "C" void kernel_launch(void* const* d_in, const int* in_sizes, int n_in,
                              void* d_out, int out_size) {
    (void)in_sizes; (void)n_in; (void)out_size;
    const float* x  = (const float*)d_in[0];
    const float* E  = (const float*)d_in[1];
    const float* Wp = (const float*)d_in[2];
    const float* bp = (const float*)d_in[3];
    float* out = (float*)d_out;

    cudaFuncSetAttribute(output_kernel, cudaFuncAttributeMaxDynamicSharedMemorySize, OUT_SMEM);
    cudaFuncSetAttribute(gemm_fp16_kernel<1>, cudaFuncAttributeMaxDynamicSharedMemorySize, GEMM_SMEM);
    cudaFuncSetAttribute(gemm_fp16_kernel<2>, cudaFuncAttributeMaxDynamicSharedMemorySize, GEMM_SMEM);

    supports_kernel<<<NN, 256>>>(E);
    xq_kernel<<<dim3(NN / 32, NB), 256>>>(x);
    weights_kernel<<<dim3((KI * NC) / 256, NN / 16), 256>>>(E, Wp);

    dim3 ggrid(NJ / 256, NN / 128);   // (16, 16) = 256 CTAs
    gemm_fp16_kernel<1><<<ggrid, 256, GEMM_SMEM>>>();
    gemm_fp16_kernel<2><<<ggrid, 256, GEMM_SMEM>>>();

    output_kernel<<<NN, 256, OUT_SMEM>>>(x, E, bp, out);
}

// round 10
// speedup vs baseline: 2.3028x; 1.0335x over previous
#include <cuda_runtime.h>
#include <cuda_fp16.h>
#include <math.h>
#include <stdint.h>

#define NB 64
#define NN 2048
#define NC 64
#define ND 10
#define NJ 4096          // NB*NC
#define KI 192           // cheb_k * C_IN

// ------------------ scratch (static device globals) ------------------
__device__ __half g_S   [NN * NN];            // fp16 supports
__device__ __half g_Xq  [(size_t)NJ * NN];    // [j][m] fp16
__device__ __half g_Y1q [(size_t)NJ * NN];    // [j][m] fp16
__device__ float  g_Y1nm[(size_t)NN * NJ];    // [n][j]
__device__ float  g_Y2nm[(size_t)NN * NJ];
__device__ __half g_Whi [(size_t)NN * KI * NC];  // [n][ki][o]
__device__ __half g_Wlo [(size_t)NN * KI * NC];

// ------------------ helpers ------------------
__device__ __forceinline__ uint32_t smem_u32(const void* p) {
    uint32_t a;
    asm("{ .reg .u64 t; cvta.to.shared.u64 t, %1; cvt.u32.u64 %0, t; }" : "=r"(a) : "l"(p));
    return a;
}
__device__ __forceinline__ void cpa16(uint32_t s, const void* g) {
    asm volatile("cp.async.cg.shared.global [%0], [%1], 16;" :: "r"(s), "l"(g));
}
__device__ __forceinline__ void fp16_split(float v, __half& h, __half& l) {
    h = __float2half_rn(v);
    l = __float2half_rn(v - __half2float(h));
}

#define LDSM4(r, a) \
    asm volatile("ldmatrix.sync.aligned.m8n8.x4.shared.b16 {%0,%1,%2,%3}, [%4];" \
        : "=r"((r)[0]), "=r"((r)[1]), "=r"((r)[2]), "=r"((r)[3]) : "r"(a))

#define LDSM4T(r, a) \
    asm volatile("ldmatrix.sync.aligned.m8n8.x4.trans.shared.b16 {%0,%1,%2,%3}, [%4];" \
        : "=r"((r)[0]), "=r"((r)[1]), "=r"((r)[2]), "=r"((r)[3]) : "r"(a))

#define MMA_F16(c, a, b0, b1) \
    asm volatile("mma.sync.aligned.m16n8k16.row.col.f32.f16.f16.f32 " \
        "{%0,%1,%2,%3}, {%4,%5,%6,%7}, {%8,%9}, {%0,%1,%2,%3};" \
        : "+f"((c)[0]), "+f"((c)[1]), "+f"((c)[2]), "+f"((c)[3]) \
        : "r"((a)[0]), "r"((a)[1]), "r"((a)[2]), "r"((a)[3]), "r"(b0), "r"(b1))

// ============================================================
// supports: S[n,:] = softmax(relu(E[n]·E[m])) -> fp16
// ============================================================
__global__ __launch_bounds__(256) void supports_kernel(const float* __restrict__ E) {
    __shared__ float vals[NN];
    __shared__ float red[256];
    const int n = blockIdx.x;
    const int tid = threadIdx.x;

    float en[ND];
#pragma unroll
    for (int d = 0; d < ND; d++) en[d] = E[n * ND + d];

    float lmax = -1e30f;
    for (int m = tid; m < NN; m += 256) {
        float v = 0.f;
#pragma unroll
        for (int d = 0; d < ND; d++) v = fmaf(en[d], E[m * ND + d], v);
        v = fmaxf(v, 0.f);
        vals[m] = v;
        lmax = fmaxf(lmax, v);
    }
    red[tid] = lmax; __syncthreads();
    for (int s = 128; s > 0; s >>= 1) { if (tid < s) red[tid] = fmaxf(red[tid], red[tid + s]); __syncthreads(); }
    const float gmax = red[0]; __syncthreads();

    float lsum = 0.f;
    for (int m = tid; m < NN; m += 256) {
        float e = expf(vals[m] - gmax);
        vals[m] = e; lsum += e;
    }
    red[tid] = lsum; __syncthreads();
    for (int s = 128; s > 0; s >>= 1) { if (tid < s) red[tid] += red[tid + s]; __syncthreads(); }
    const float inv = 1.f / red[0];
    for (int m = tid; m < NN; m += 256)
        g_S[n * NN + m] = __float2half_rn(vals[m] * inv);
}

// ============================================================
// Xq builder: Xq[j = b*64+c][m] = fp16(x[b][m][c])
// ============================================================
__global__ __launch_bounds__(256) void xq_kernel(const float* __restrict__ x) {
    __shared__ float sm[64 * 33];
    const int m0 = blockIdx.x * 32;
    const int b  = blockIdx.y;
    const int t  = threadIdx.x;
#pragma unroll
    for (int p = 0; p < 8; p++) {
        int e = t + 256 * p;
        int r = e >> 6, c = e & 63;
        sm[c * 33 + r] = x[(size_t)b * (NN * NC) + (size_t)(m0 + r) * NC + c];
    }
    __syncthreads();
#pragma unroll
    for (int p = 0; p < 8; p++) {
        int e = t + 256 * p;
        int c = e >> 5, r = e & 31;
        g_Xq[(size_t)(b * 64 + c) * NN + m0 + r] = __float2half_rn(sm[c * 33 + r]);
    }
}

// ============================================================
// weights: W[n, ki, o] = sum_d E[n,d]*Wp[d,ki,o], split fp16 hi/lo
// ============================================================
__global__ __launch_bounds__(256) void weights_kernel(const float* __restrict__ E,
                                                      const float* __restrict__ Wp) {
    __shared__ float Es[16][ND];
    const int e0 = blockIdx.x * 256;
    const int n0 = blockIdx.y * 16;
    const int tid = threadIdx.x;
    if (tid < 16 * ND) Es[tid / ND][tid % ND] = E[(n0 + tid / ND) * ND + (tid % ND)];
    __syncthreads();
    const int e = e0 + tid;
    float wp[ND];
#pragma unroll
    for (int d = 0; d < ND; d++) wp[d] = Wp[d * (KI * NC) + e];
#pragma unroll
    for (int nn = 0; nn < 16; nn++) {
        float acc = 0.f;
#pragma unroll
        for (int d = 0; d < ND; d++) acc = fmaf(Es[nn][d], wp[d], acc);
        __half hi, lo; fp16_split(acc, hi, lo);
        const size_t idx = (size_t)(n0 + nn) * (KI * NC) + e;
        g_Whi[idx] = hi;
        g_Wlo[idx] = lo;
    }
}

// ============================================================
// single-term fp16 GEMM (m16n8k16): C[128x128] tile, 256 threads,
// 8 warps (2x4), warp tile 64x32. 2-stage cp.async (32KB/stage),
// 68KB smem/CTA, <=128 regs -> 2 CTAs/SM (independent barriers
// cover each other's sync/pipeline bubbles).
// ============================================================
#define STG_A 0
#define STG_B 16384
#define STAGE_BYTES 32768
#define GEMM_SMEM 69632            // max(2 stages 64KB, transpose 128*132*4)
#define NITER (NN / 64)            // 32

template <int MODE>
__global__ void __launch_bounds__(256, 2) gemm_fp16_kernel() {
    extern __shared__ float dsm[];
    const int t = threadIdx.x;
    const int l = t & 31;
    const int wid = t >> 5;
    const int wm = wid >> 2;       // 0..1  (m, 64 rows each)
    const int wn = wid & 3;        // 0..3  (n, 32 cols each)
    const int bm = blockIdx.y * 128;
    const int bn = blockIdx.x * 128;

    const __half* Ap = g_S + (size_t)bm * NN;
    const __half* Bp = (MODE == 1 ? g_Xq : g_Y1q) + (size_t)bn * NN;

    const uint32_t sb0 = smem_u32(dsm);

    auto load_stage = [&](int s, int k0) {
        const uint32_t sb = sb0 + (uint32_t)s * STAGE_BYTES;
#pragma unroll
        for (int p = 0; p < 4; p++) {          // A: 128 rows x 8 granules
            const int g = t + 256 * p;
            const int row = g >> 3;
            const int c16 = g & 7;
            const int sw = c16 ^ (row & 7);
            cpa16(sb + STG_A + (uint32_t)(row * 128 + sw * 16),
                  Ap + (size_t)row * NN + k0 + c16 * 8);
        }
#pragma unroll
        for (int p = 0; p < 4; p++) {          // B: 128 rows x 8 granules
            const int g = t + 256 * p;
            const int row = g >> 3;
            const int c16 = g & 7;
            const int sw = c16 ^ (row & 7);
            cpa16(sb + STG_B + (uint32_t)(row * 128 + sw * 16),
                  Bp + (size_t)row * NN + k0 + c16 * 8);
        }
        asm volatile("cp.async.commit_group;" ::: "memory");
    };

    float acc[4][4][4];
#pragma unroll
    for (int a = 0; a < 4; a++)
#pragma unroll
        for (int b = 0; b < 4; b++)
#pragma unroll
            for (int c = 0; c < 4; c++) acc[a][b][c] = 0.f;

    const int t4 = l >> 3;
    const int l7 = l & 7;
    const int arow_in = ((t4 & 1) << 3) + l7;
    const int brow_in = ((t4 >> 1) << 3) + l7;
    const uint32_t abase = (uint32_t)((wm * 64 + arow_in) * 128);
    const uint32_t bbase = (uint32_t)((wn * 32 + brow_in) * 128);
    const int akg = t4 >> 1;
    const int bkg = t4 & 1;

    load_stage(0, 0);

    for (int i = 0; i < NITER; i++) {
        asm volatile("cp.async.wait_group 0;" ::: "memory");
        __syncthreads();
        // issue next stage into the buffer freed by compute(i-1)
        if (i + 1 < NITER) load_stage((i + 1) & 1, (i + 1) * 64);
        const uint32_t sb = sb0 + (uint32_t)(i & 1) * STAGE_BYTES;
#pragma unroll
        for (int ks = 0; ks < 4; ks++) {
            const uint32_t xa = (uint32_t)(((ks * 2 + akg) ^ l7) << 4);
            const uint32_t xb = (uint32_t)(((ks * 2 + bkg) ^ l7) << 4);
            uint32_t af[4][4], bf[2][4];
#pragma unroll
            for (int mt = 0; mt < 4; mt++)
                LDSM4(af[mt], sb + STG_A + abase + (uint32_t)(mt * 16 * 128) + xa);
#pragma unroll
            for (int nh = 0; nh < 2; nh++)
                LDSM4(bf[nh], sb + STG_B + bbase + (uint32_t)(nh * 16 * 128) + xb);
#pragma unroll
            for (int mt = 0; mt < 4; mt++)
#pragma unroll
                for (int n8 = 0; n8 < 4; n8++) {
                    const int nh = n8 >> 1, q = (n8 & 1) * 2;
                    MMA_F16(acc[mt][n8], af[mt], bf[nh][q], bf[nh][q + 1]);
                }
        }
        __syncthreads();   // compute done before next iter's load overwrites
    }

    // ---------------- epilogue ----------------
    float* Ynm = (MODE == 1) ? g_Y1nm : g_Y2nm;
    const int lm = l >> 2;
    const int lc = (l & 3) << 1;
#pragma unroll
    for (int mt = 0; mt < 4; mt++)
#pragma unroll
        for (int n8 = 0; n8 < 4; n8++) {
            const int r = bm + wm * 64 + mt * 16 + lm;
            const int col = bn + wn * 32 + n8 * 8 + lc;
            *(float2*)&Ynm[(size_t)r * NJ + col] =
                make_float2(acc[mt][n8][0], acc[mt][n8][1]);
            *(float2*)&Ynm[(size_t)(r + 8) * NJ + col] =
                make_float2(acc[mt][n8][2], acc[mt][n8][3]);
        }

    if (MODE == 1) {
        // transpose 128m x 128j tile via smem, write Y1q fp16 [j][m]
        __syncthreads();
#pragma unroll
        for (int mt = 0; mt < 4; mt++)
#pragma unroll
            for (int n8 = 0; n8 < 4; n8++) {
                const int jl = wn * 32 + n8 * 8 + lc;
                const int ml = wm * 64 + mt * 16 + lm;
                dsm[jl * 132 + ml]           = acc[mt][n8][0];
                dsm[(jl + 1) * 132 + ml]     = acc[mt][n8][1];
                dsm[jl * 132 + ml + 8]       = acc[mt][n8][2];
                dsm[(jl + 1) * 132 + ml + 8] = acc[mt][n8][3];
            }
        __syncthreads();
#pragma unroll
        for (int it = 0; it < 16; it++) {
            const int j = wid * 16 + it;
            const int m4 = l * 4;
            const float4 v = *(const float4*)&dsm[j * 132 + m4];
            __half2 p0 = __floats2half2_rn(v.x, v.y);
            __half2 p1 = __floats2half2_rn(v.z, v.w);
            uint2 w;
            w.x = *(uint32_t*)&p0; w.y = *(uint32_t*)&p1;
            *(uint2*)&g_Y1q[(size_t)(bn + j) * NN + bm + m4] = w;
        }
    }
}

// ============================================================
// output (tensor-core): per node n, out[b,o] = A[b,ki] @ W[ki,o] + bias
//   A channels: {x, Y1, 2*Y2-x}; fp16 3-term (Ah*Wh + Al*Wh + Ah*Wl)
// ============================================================
#define OUT_SMEM (96 * 1024)

__global__ void __launch_bounds__(256, 2) output_kernel(const float* __restrict__ x,
                                                        const float* __restrict__ E,
                                                        const float* __restrict__ bp,
                                                        float* __restrict__ out) {
    extern __shared__ char osm[];
    const uint32_t base = smem_u32(osm);
    const uint32_t AHI = base;
    const uint32_t ALO = base + 24576;
    const uint32_t WHI = base + 49152;
    const uint32_t WLO = base + 73728;

    const int n = blockIdx.x;
    const int tid = threadIdx.x;
    const int l = tid & 31;
    const int wid = tid >> 5;
    const int wm = wid >> 2;     // 0..1 (b, 32 rows)
    const int wn = wid & 3;      // 0..3 (o, 16 cols)

    const __half* Whg = g_Whi + (size_t)n * (KI * NC);
    const __half* Wlg = g_Wlo + (size_t)n * (KI * NC);
#pragma unroll
    for (int p = 0; p < 6; p++) {
        const int g = tid + 256 * p;
        const int ki = g >> 3;
        const int og = g & 7;
        const uint32_t dst = (uint32_t)(ki * 128 + ((og ^ (ki & 7)) << 4));
        cpa16(WHI + dst, Whg + ki * 64 + og * 8);
        cpa16(WLO + dst, Wlg + ki * 64 + og * 8);
    }
    asm volatile("cp.async.commit_group;" ::: "memory");

    for (int e = tid; e < NJ; e += 256) {
        const int b = e >> 6;
        const int i = e & 63;
        const float xv = x[(size_t)b * (NN * NC) + n * NC + i];
        const float y1 = g_Y1nm[(size_t)n * NJ + e];
        const float y2 = g_Y2nm[(size_t)n * NJ + e];
        const float vals[3] = { xv, y1, 2.f * y2 - xv };
#pragma unroll
        for (int kch = 0; kch < 3; kch++) {
            const int ki = kch * 64 + i;
            __half hi, lo; fp16_split(vals[kch], hi, lo);
            const uint32_t addr = (uint32_t)(b * 384 + ((ki >> 6) << 7) +
                ((((ki >> 3) & 7) ^ (b & 7)) << 4) + ((ki & 7) << 1));
            *(__half*)(osm + (AHI - base) + addr) = hi;
            *(__half*)(osm + (ALO - base) + addr) = lo;
        }
    }
    asm volatile("cp.async.wait_group 0;" ::: "memory");
    __syncthreads();

    float acc[2][2][4];
#pragma unroll
    for (int a = 0; a < 2; a++)
#pragma unroll
        for (int b = 0; b < 2; b++)
#pragma unroll
            for (int c = 0; c < 4; c++) acc[a][b][c] = 0.f;

    const int t4 = l >> 3;
    const int l7 = l & 7;
    const int arow_in = ((t4 & 1) << 3) + l7;
    const int akg = t4 >> 1;
    const int wrow_in = ((t4 & 1) << 3) + l7;
    const int wog = wn * 2 + (t4 >> 1);

#pragma unroll
    for (int ks = 0; ks < 12; ks++) {
        uint32_t ahf[2][4], alf[2][4], whf[4], wlf[4];
        const int kg = ks * 2 + akg;
#pragma unroll
        for (int mt = 0; mt < 2; mt++) {
            const int row = wm * 32 + mt * 16 + arow_in;
            const uint32_t aaddr = (uint32_t)(row * 384 + ((kg >> 3) << 7) +
                (((kg & 7) ^ (row & 7)) << 4));
            LDSM4(ahf[mt], AHI + aaddr);
            LDSM4(alf[mt], ALO + aaddr);
        }
        {
            const int wrow = ks * 16 + wrow_in;
            const uint32_t waddr = (uint32_t)(wrow * 128 + ((wog ^ (wrow & 7)) << 4));
            LDSM4T(whf, WHI + waddr);
            LDSM4T(wlf, WLO + waddr);
        }
#pragma unroll
        for (int mt = 0; mt < 2; mt++)
#pragma unroll
            for (int n8 = 0; n8 < 2; n8++)
                MMA_F16(acc[mt][n8], ahf[mt], whf[n8 * 2], whf[n8 * 2 + 1]);
#pragma unroll
        for (int mt = 0; mt < 2; mt++)
#pragma unroll
            for (int n8 = 0; n8 < 2; n8++)
                MMA_F16(acc[mt][n8], alf[mt], whf[n8 * 2], whf[n8 * 2 + 1]);
#pragma unroll
        for (int mt = 0; mt < 2; mt++)
#pragma unroll
            for (int n8 = 0; n8 < 2; n8++)
                MMA_F16(acc[mt][n8], ahf[mt], wlf[n8 * 2], wlf[n8 * 2 + 1]);
    }

    const int lm = l >> 2;
    const int lc = (l & 3) << 1;
    float bias[2][2];
#pragma unroll
    for (int n8 = 0; n8 < 2; n8++)
#pragma unroll
        for (int cc = 0; cc < 2; cc++) {
            const int o = wn * 16 + n8 * 8 + lc + cc;
            float s = 0.f;
#pragma unroll
            for (int d = 0; d < ND; d++) s = fmaf(E[n * ND + d], bp[d * NC + o], s);
            bias[n8][cc] = s;
        }

#pragma unroll
    for (int mt = 0; mt < 2; mt++)
#pragma unroll
        for (int n8 = 0; n8 < 2; n8++) {
            const int b0 = wm * 32 + mt * 16 + lm;
            const int col = wn * 16 + n8 * 8 + lc;
            *(float2*)&out[(size_t)b0 * (NN * NC) + n * NC + col] =
                make_float2(acc[mt][n8][0] + bias[n8][0], acc[mt][n8][1] + bias[n8][1]);
            *(float2*)&out[(size_t)(b0 + 8) * (NN * NC) + n * NC + col] =
                make_float2(acc[mt][n8][2] + bias[n8][0], acc[mt][n8][3] + bias[n8][1]);
        }
}

// ============================================================
extern "C" void kernel_launch(void* const* d_in, const int* in_sizes, int n_in,
                              void* d_out, int out_size) {
    (void)in_sizes; (void)n_in; (void)out_size;
    const float* x  = (const float*)d_in[0];
    const float* E  = (const float*)d_in[1];
    const float* Wp = (const float*)d_in[2];
    const float* bp = (const float*)d_in[3];
    float* out = (float*)d_out;

    cudaFuncSetAttribute(output_kernel, cudaFuncAttributeMaxDynamicSharedMemorySize, OUT_SMEM);
    cudaFuncSetAttribute(gemm_fp16_kernel<1>, cudaFuncAttributeMaxDynamicSharedMemorySize, GEMM_SMEM);
    cudaFuncSetAttribute(gemm_fp16_kernel<2>, cudaFuncAttributeMaxDynamicSharedMemorySize, GEMM_SMEM);

    supports_kernel<<<NN, 256>>>(E);
    xq_kernel<<<dim3(NN / 32, NB), 256>>>(x);
    weights_kernel<<<dim3((KI * NC) / 256, NN / 16), 256>>>(E, Wp);

    dim3 ggrid(NJ / 128, NN / 128);   // (32, 16) = 512 CTAs
    gemm_fp16_kernel<1><<<ggrid, 256, GEMM_SMEM>>>();
    gemm_fp16_kernel<2><<<ggrid, 256, GEMM_SMEM>>>();

    output_kernel<<<NN, 256, OUT_SMEM>>>(x, E, bp, out);
}

// round 11
// speedup vs baseline: 2.6794x; 1.1636x over previous
#include <cuda_runtime.h>
#include <cuda_fp16.h>
#include <math.h>
#include <stdint.h>

#define NB 64
#define NN 2048
#define NC 64
#define ND 10
#define NJ 4096          // NB*NC
#define KI 192           // cheb_k * C_IN

// ------------------ scratch (static device globals) ------------------
__device__ __half g_S   [NN * NN];            // fp16 supports
__device__ __half g_Xq  [(size_t)NJ * NN];    // [j][m] fp16
__device__ __half g_Y1q [(size_t)NJ * NN];    // [j][m] fp16
__device__ float  g_Y1nm[(size_t)NN * NJ];    // [n][j]
__device__ float  g_Y2nm[(size_t)NN * NJ];
__device__ __half g_W16 [(size_t)NN * KI * NC];  // [n][ki][o] fp16 single

// ------------------ helpers ------------------
__device__ __forceinline__ uint32_t smem_u32(const void* p) {
    uint32_t a;
    asm("{ .reg .u64 t; cvta.to.shared.u64 t, %1; cvt.u32.u64 %0, t; }" : "=r"(a) : "l"(p));
    return a;
}
__device__ __forceinline__ void cpa16(uint32_t s, const void* g) {
    asm volatile("cp.async.cg.shared.global [%0], [%1], 16;" :: "r"(s), "l"(g));
}
__device__ __forceinline__ void fp16_split(float v, __half& h, __half& l) {
    h = __float2half_rn(v);
    l = __float2half_rn(v - __half2float(h));
}

#define LDSM4(r, a) \
    asm volatile("ldmatrix.sync.aligned.m8n8.x4.shared.b16 {%0,%1,%2,%3}, [%4];" \
        : "=r"((r)[0]), "=r"((r)[1]), "=r"((r)[2]), "=r"((r)[3]) : "r"(a))

#define LDSM4T(r, a) \
    asm volatile("ldmatrix.sync.aligned.m8n8.x4.trans.shared.b16 {%0,%1,%2,%3}, [%4];" \
        : "=r"((r)[0]), "=r"((r)[1]), "=r"((r)[2]), "=r"((r)[3]) : "r"(a))

#define MMA_F16(c, a, b0, b1) \
    asm volatile("mma.sync.aligned.m16n8k16.row.col.f32.f16.f16.f32 " \
        "{%0,%1,%2,%3}, {%4,%5,%6,%7}, {%8,%9}, {%0,%1,%2,%3};" \
        : "+f"((c)[0]), "+f"((c)[1]), "+f"((c)[2]), "+f"((c)[3]) \
        : "r"((a)[0]), "r"((a)[1]), "r"((a)[2]), "r"((a)[3]), "r"(b0), "r"(b1))

// ============================================================
// prep: ONE kernel, three independent jobs dispatched on blockIdx
//   [0, 2048)        supports rows (softmax -> fp16)
//   [2048, 6144)     Xq transpose tiles
//   [6144, 12288)    weights (W = E·Wp -> fp16)
// ============================================================
#define PREP_SUP   NN
#define PREP_XQ    (PREP_SUP + 4096)
#define PREP_TOTAL (PREP_XQ + 6144)

__global__ __launch_bounds__(256) void prep_kernel(const float* __restrict__ x,
                                                   const float* __restrict__ E,
                                                   const float* __restrict__ Wp) {
    __shared__ float sh[2048 + 256];
    const int tid = threadIdx.x;
    const int bid = blockIdx.x;

    if (bid < PREP_SUP) {
        // ---- supports row n ----
        float* vals = sh;
        float* red  = sh + 2048;
        const int n = bid;

        float en[ND];
#pragma unroll
        for (int d = 0; d < ND; d++) en[d] = E[n * ND + d];

        float lmax = -1e30f;
        for (int m = tid; m < NN; m += 256) {
            float v = 0.f;
#pragma unroll
            for (int d = 0; d < ND; d++) v = fmaf(en[d], E[m * ND + d], v);
            v = fmaxf(v, 0.f);
            vals[m] = v;
            lmax = fmaxf(lmax, v);
        }
        red[tid] = lmax; __syncthreads();
        for (int s = 128; s > 0; s >>= 1) { if (tid < s) red[tid] = fmaxf(red[tid], red[tid + s]); __syncthreads(); }
        const float gmax = red[0]; __syncthreads();

        float lsum = 0.f;
        for (int m = tid; m < NN; m += 256) {
            float e = expf(vals[m] - gmax);
            vals[m] = e; lsum += e;
        }
        red[tid] = lsum; __syncthreads();
        for (int s = 128; s > 0; s >>= 1) { if (tid < s) red[tid] += red[tid + s]; __syncthreads(); }
        const float inv = 1.f / red[0];
        for (int m = tid; m < NN; m += 256)
            g_S[n * NN + m] = __float2half_rn(vals[m] * inv);

    } else if (bid < PREP_XQ) {
        // ---- Xq tile: Xq[b*64+c][m] = fp16(x[b][m][c]) ----
        const int id = bid - PREP_SUP;
        const int m0 = (id & 63) * 32;
        const int b  = id >> 6;
        float* sm = sh;   // 64*33 floats
#pragma unroll
        for (int p = 0; p < 8; p++) {
            int e = tid + 256 * p;
            int r = e >> 6, c = e & 63;
            sm[c * 33 + r] = x[(size_t)b * (NN * NC) + (size_t)(m0 + r) * NC + c];
        }
        __syncthreads();
#pragma unroll
        for (int p = 0; p < 8; p++) {
            int e = tid + 256 * p;
            int c = e >> 5, r = e & 31;
            g_Xq[(size_t)(b * 64 + c) * NN + m0 + r] = __float2half_rn(sm[c * 33 + r]);
        }

    } else {
        // ---- weights tile: W16[n, e] = fp16(sum_d E[n,d]*Wp[d,e]) ----
        const int id = bid - PREP_XQ;
        const int e0 = (id % 48) * 256;
        const int n0 = (id / 48) * 16;
        float* Es = sh;   // [16][ND]
        if (tid < 16 * ND) Es[tid] = E[(n0 + tid / ND) * ND + (tid % ND)];
        __syncthreads();
        const int e = e0 + tid;
        float wp[ND];
#pragma unroll
        for (int d = 0; d < ND; d++) wp[d] = Wp[d * (KI * NC) + e];
#pragma unroll
        for (int nn = 0; nn < 16; nn++) {
            float acc = 0.f;
#pragma unroll
            for (int d = 0; d < ND; d++) acc = fmaf(Es[nn * ND + d], wp[d], acc);
            g_W16[(size_t)(n0 + nn) * (KI * NC) + e] = __float2half_rn(acc);
        }
    }
}

// ============================================================
// single-term fp16 GEMM (m16n8k16): C[128x128] tile, 256 threads,
// 8 warps (2x4), warp tile 64x32. 3-stage cp.async (32KB/stage),
// 96KB smem/CTA, <=128 regs -> 2 CTAs/SM.
// ============================================================
#define STG_A 0
#define STG_B 16384
#define STAGE_BYTES 32768
#define GEMM_SMEM 98304            // 3 stages; transpose buf 67584 fits
#define NITER (NN / 64)            // 32

template <int MODE>
__global__ void __launch_bounds__(256, 2) gemm_fp16_kernel() {
    extern __shared__ float dsm[];
    const int t = threadIdx.x;
    const int l = t & 31;
    const int wid = t >> 5;
    const int wm = wid >> 2;       // 0..1  (m, 64 rows each)
    const int wn = wid & 3;        // 0..3  (n, 32 cols each)
    const int bm = blockIdx.y * 128;
    const int bn = blockIdx.x * 128;

    const __half* Ap = g_S + (size_t)bm * NN;
    const __half* Bp = (MODE == 1 ? g_Xq : g_Y1q) + (size_t)bn * NN;

    const uint32_t sb0 = smem_u32(dsm);

    auto load_stage = [&](int s, int k0) {
        const uint32_t sb = sb0 + (uint32_t)s * STAGE_BYTES;
#pragma unroll
        for (int p = 0; p < 4; p++) {
            const int g = t + 256 * p;
            const int row = g >> 3;
            const int c16 = g & 7;
            const int sw = c16 ^ (row & 7);
            cpa16(sb + STG_A + (uint32_t)(row * 128 + sw * 16),
                  Ap + (size_t)row * NN + k0 + c16 * 8);
        }
#pragma unroll
        for (int p = 0; p < 4; p++) {
            const int g = t + 256 * p;
            const int row = g >> 3;
            const int c16 = g & 7;
            const int sw = c16 ^ (row & 7);
            cpa16(sb + STG_B + (uint32_t)(row * 128 + sw * 16),
                  Bp + (size_t)row * NN + k0 + c16 * 8);
        }
        asm volatile("cp.async.commit_group;" ::: "memory");
    };

    float acc[4][4][4];
#pragma unroll
    for (int a = 0; a < 4; a++)
#pragma unroll
        for (int b = 0; b < 4; b++)
#pragma unroll
            for (int c = 0; c < 4; c++) acc[a][b][c] = 0.f;

    const int t4 = l >> 3;
    const int l7 = l & 7;
    const int arow_in = ((t4 & 1) << 3) + l7;
    const int brow_in = ((t4 >> 1) << 3) + l7;
    const uint32_t abase = (uint32_t)((wm * 64 + arow_in) * 128);
    const uint32_t bbase = (uint32_t)((wn * 32 + brow_in) * 128);
    const int akg = t4 >> 1;
    const int bkg = t4 & 1;

    load_stage(0, 0);
    load_stage(1, 64);

    for (int i = 0; i < NITER; i++) {
        if (i + 2 < NITER)
            asm volatile("cp.async.wait_group 1;" ::: "memory");
        else
            asm volatile("cp.async.wait_group 0;" ::: "memory");
        __syncthreads();   // all warps finished compute(i-1) before refill
        if (i + 2 < NITER) load_stage((i + 2) % 3, (i + 2) * 64);
        const uint32_t sb = sb0 + (uint32_t)(i % 3) * STAGE_BYTES;
#pragma unroll
        for (int ks = 0; ks < 4; ks++) {
            const uint32_t xa = (uint32_t)(((ks * 2 + akg) ^ l7) << 4);
            const uint32_t xb = (uint32_t)(((ks * 2 + bkg) ^ l7) << 4);
            uint32_t af[4][4], bf[2][4];
#pragma unroll
            for (int mt = 0; mt < 4; mt++)
                LDSM4(af[mt], sb + STG_A + abase + (uint32_t)(mt * 16 * 128) + xa);
#pragma unroll
            for (int nh = 0; nh < 2; nh++)
                LDSM4(bf[nh], sb + STG_B + bbase + (uint32_t)(nh * 16 * 128) + xb);
#pragma unroll
            for (int mt = 0; mt < 4; mt++)
#pragma unroll
                for (int n8 = 0; n8 < 4; n8++) {
                    const int nh = n8 >> 1, q = (n8 & 1) * 2;
                    MMA_F16(acc[mt][n8], af[mt], bf[nh][q], bf[nh][q + 1]);
                }
        }
    }

    // ---------------- epilogue ----------------
    float* Ynm = (MODE == 1) ? g_Y1nm : g_Y2nm;
    const int lm = l >> 2;
    const int lc = (l & 3) << 1;
#pragma unroll
    for (int mt = 0; mt < 4; mt++)
#pragma unroll
        for (int n8 = 0; n8 < 4; n8++) {
            const int r = bm + wm * 64 + mt * 16 + lm;
            const int col = bn + wn * 32 + n8 * 8 + lc;
            *(float2*)&Ynm[(size_t)r * NJ + col] =
                make_float2(acc[mt][n8][0], acc[mt][n8][1]);
            *(float2*)&Ynm[(size_t)(r + 8) * NJ + col] =
                make_float2(acc[mt][n8][2], acc[mt][n8][3]);
        }

    if (MODE == 1) {
        // transpose 128m x 128j tile via smem, write Y1q fp16 [j][m]
        __syncthreads();
#pragma unroll
        for (int mt = 0; mt < 4; mt++)
#pragma unroll
            for (int n8 = 0; n8 < 4; n8++) {
                const int jl = wn * 32 + n8 * 8 + lc;
                const int ml = wm * 64 + mt * 16 + lm;
                dsm[jl * 132 + ml]           = acc[mt][n8][0];
                dsm[(jl + 1) * 132 + ml]     = acc[mt][n8][1];
                dsm[jl * 132 + ml + 8]       = acc[mt][n8][2];
                dsm[(jl + 1) * 132 + ml + 8] = acc[mt][n8][3];
            }
        __syncthreads();
#pragma unroll
        for (int it = 0; it < 16; it++) {
            const int j = wid * 16 + it;
            const int m4 = l * 4;
            const float4 v = *(const float4*)&dsm[j * 132 + m4];
            __half2 p0 = __floats2half2_rn(v.x, v.y);
            __half2 p1 = __floats2half2_rn(v.z, v.w);
            uint2 w;
            w.x = *(uint32_t*)&p0; w.y = *(uint32_t*)&p1;
            *(uint2*)&g_Y1q[(size_t)(bn + j) * NN + bm + m4] = w;
        }
    }
}

// ============================================================
// output (tensor-core): per node n, out[b,o] = A[b,ki] @ W[ki,o] + bias
//   A channels: {x, Y1, 2*Y2-x}; terms: Ah*W + Al*W (W fp16 single)
// ============================================================
#define OUT_SMEM 73728   // AHI 24576 + ALO 24576 + WHI 24576

__global__ void __launch_bounds__(256, 2) output_kernel(const float* __restrict__ x,
                                                        const float* __restrict__ E,
                                                        const float* __restrict__ bp,
                                                        float* __restrict__ out) {
    extern __shared__ char osm[];
    const uint32_t base = smem_u32(osm);
    const uint32_t AHI = base;
    const uint32_t ALO = base + 24576;
    const uint32_t WHI = base + 49152;

    const int n = blockIdx.x;
    const int tid = threadIdx.x;
    const int l = tid & 31;
    const int wid = tid >> 5;
    const int wm = wid >> 2;     // 0..1 (b, 32 rows)
    const int wn = wid & 3;      // 0..3 (o, 16 cols)

    const __half* Whg = g_W16 + (size_t)n * (KI * NC);
#pragma unroll
    for (int p = 0; p < 6; p++) {
        const int g = tid + 256 * p;
        const int ki = g >> 3;
        const int og = g & 7;
        cpa16(WHI + (uint32_t)(ki * 128 + ((og ^ (ki & 7)) << 4)),
              Whg + ki * 64 + og * 8);
    }
    asm volatile("cp.async.commit_group;" ::: "memory");

    // ---- build A planes [b=64][ki=192] fp16 hi/lo, pairwise vectorized ----
    for (int e = tid * 2; e < NJ; e += 512) {
        const int b = e >> 6;
        const int i = e & 63;            // even
        const float2 xv = *(const float2*)&x[(size_t)b * (NN * NC) + n * NC + i];
        const float2 y1 = *(const float2*)&g_Y1nm[(size_t)n * NJ + e];
        const float2 y2 = *(const float2*)&g_Y2nm[(size_t)n * NJ + e];
        const float2 vals[3] = { xv, y1,
            make_float2(2.f * y2.x - xv.x, 2.f * y2.y - xv.y) };
#pragma unroll
        for (int kch = 0; kch < 3; kch++) {
            const int ki = kch * 64 + i;  // even
            __half h0, l0, h1, l1;
            fp16_split(vals[kch].x, h0, l0);
            fp16_split(vals[kch].y, h1, l1);
            const uint32_t addr = (uint32_t)(b * 384 + ((ki >> 6) << 7) +
                ((((ki >> 3) & 7) ^ (b & 7)) << 4) + ((ki & 7) << 1));
            __half2 hp = make_half2(h0, h1);
            __half2 lp = make_half2(l0, l1);
            *(__half2*)(osm + (AHI - base) + addr) = hp;
            *(__half2*)(osm + (ALO - base) + addr) = lp;
        }
    }
    asm volatile("cp.async.wait_group 0;" ::: "memory");
    __syncthreads();

    float acc[2][2][4];
#pragma unroll
    for (int a = 0; a < 2; a++)
#pragma unroll
        for (int b = 0; b < 2; b++)
#pragma unroll
            for (int c = 0; c < 4; c++) acc[a][b][c] = 0.f;

    const int t4 = l >> 3;
    const int l7 = l & 7;
    const int arow_in = ((t4 & 1) << 3) + l7;
    const int akg = t4 >> 1;
    const int wrow_in = ((t4 & 1) << 3) + l7;
    const int wog = wn * 2 + (t4 >> 1);

#pragma unroll
    for (int ks = 0; ks < 12; ks++) {
        uint32_t ahf[2][4], alf[2][4], whf[4];
        const int kg = ks * 2 + akg;
#pragma unroll
        for (int mt = 0; mt < 2; mt++) {
            const int row = wm * 32 + mt * 16 + arow_in;
            const uint32_t aaddr = (uint32_t)(row * 384 + ((kg >> 3) << 7) +
                (((kg & 7) ^ (row & 7)) << 4));
            LDSM4(ahf[mt], AHI + aaddr);
            LDSM4(alf[mt], ALO + aaddr);
        }
        {
            const int wrow = ks * 16 + wrow_in;
            LDSM4T(whf, WHI + (uint32_t)(wrow * 128 + ((wog ^ (wrow & 7)) << 4)));
        }
#pragma unroll
        for (int mt = 0; mt < 2; mt++)
#pragma unroll
            for (int n8 = 0; n8 < 2; n8++)
                MMA_F16(acc[mt][n8], ahf[mt], whf[n8 * 2], whf[n8 * 2 + 1]);
#pragma unroll
        for (int mt = 0; mt < 2; mt++)
#pragma unroll
            for (int n8 = 0; n8 < 2; n8++)
                MMA_F16(acc[mt][n8], alf[mt], whf[n8 * 2], whf[n8 * 2 + 1]);
    }

    const int lm = l >> 2;
    const int lc = (l & 3) << 1;
    float bias[2][2];
#pragma unroll
    for (int n8 = 0; n8 < 2; n8++)
#pragma unroll
        for (int cc = 0; cc < 2; cc++) {
            const int o = wn * 16 + n8 * 8 + lc + cc;
            float s = 0.f;
#pragma unroll
            for (int d = 0; d < ND; d++) s = fmaf(E[n * ND + d], bp[d * NC + o], s);
            bias[n8][cc] = s;
        }

#pragma unroll
    for (int mt = 0; mt < 2; mt++)
#pragma unroll
        for (int n8 = 0; n8 < 2; n8++) {
            const int b0 = wm * 32 + mt * 16 + lm;
            const int col = wn * 16 + n8 * 8 + lc;
            *(float2*)&out[(size_t)b0 * (NN * NC) + n * NC + col] =
                make_float2(acc[mt][n8][0] + bias[n8][0], acc[mt][n8][1] + bias[n8][1]);
            *(float2*)&out[(size_t)(b0 + 8) * (NN * NC) + n * NC + col] =
                make_float2(acc[mt][n8][2] + bias[n8][0], acc[mt][n8][3] + bias[n8][1]);
        }
}

// ============================================================
extern "C" void kernel_launch(void* const* d_in, const int* in_sizes, int n_in,
                              void* d_out, int out_size) {
    (void)in_sizes; (void)n_in; (void)out_size;
    const float* x  = (const float*)d_in[0];
    const float* E  = (const float*)d_in[1];
    const float* Wp = (const float*)d_in[2];
    const float* bp = (const float*)d_in[3];
    float* out = (float*)d_out;

    cudaFuncSetAttribute(output_kernel, cudaFuncAttributeMaxDynamicSharedMemorySize, OUT_SMEM);
    cudaFuncSetAttribute(gemm_fp16_kernel<1>, cudaFuncAttributeMaxDynamicSharedMemorySize, GEMM_SMEM);
    cudaFuncSetAttribute(gemm_fp16_kernel<2>, cudaFuncAttributeMaxDynamicSharedMemorySize, GEMM_SMEM);

    prep_kernel<<<PREP_TOTAL, 256>>>(x, E, Wp);

    dim3 ggrid(NJ / 128, NN / 128);   // (32, 16) = 512 CTAs
    gemm_fp16_kernel<1><<<ggrid, 256, GEMM_SMEM>>>();
    gemm_fp16_kernel<2><<<ggrid, 256, GEMM_SMEM>>>();

    output_kernel<<<NN, 256, OUT_SMEM>>>(x, E, bp, out);
}

// round 12
// speedup vs baseline: 2.7002x; 1.0078x over previous
#include <cuda_runtime.h>
#include <cuda_fp16.h>
#include <math.h>
#include <stdint.h>

#define NB 64
#define NN 2048
#define NC 64
#define ND 10
#define NJ 4096          // NB*NC
#define KI 192           // cheb_k * C_IN

// ------------------ scratch (static device globals) ------------------
__device__ __half g_S   [NN * NN];            // fp16 supports
__device__ __half g_Xq  [(size_t)NJ * NN];    // [j][m] fp16
__device__ __half g_Y1q [(size_t)NJ * NN];    // [j][m] fp16
__device__ __half g_Y1h [(size_t)NN * NJ];    // [n][j] fp16
__device__ __half g_Y2h [(size_t)NN * NJ];    // [n][j] fp16
__device__ __half g_W16 [(size_t)NN * KI * NC];  // [n][ki][o] fp16

// ------------------ helpers ------------------
__device__ __forceinline__ uint32_t smem_u32(const void* p) {
    uint32_t a;
    asm("{ .reg .u64 t; cvta.to.shared.u64 t, %1; cvt.u32.u64 %0, t; }" : "=r"(a) : "l"(p));
    return a;
}
__device__ __forceinline__ void cpa16(uint32_t s, const void* g) {
    asm volatile("cp.async.cg.shared.global [%0], [%1], 16;" :: "r"(s), "l"(g));
}
__device__ __forceinline__ void fp16_split(float v, __half& h, __half& l) {
    h = __float2half_rn(v);
    l = __float2half_rn(v - __half2float(h));
}

#define LDSM4(r, a) \
    asm volatile("ldmatrix.sync.aligned.m8n8.x4.shared.b16 {%0,%1,%2,%3}, [%4];" \
        : "=r"((r)[0]), "=r"((r)[1]), "=r"((r)[2]), "=r"((r)[3]) : "r"(a))

#define LDSM4T(r, a) \
    asm volatile("ldmatrix.sync.aligned.m8n8.x4.trans.shared.b16 {%0,%1,%2,%3}, [%4];" \
        : "=r"((r)[0]), "=r"((r)[1]), "=r"((r)[2]), "=r"((r)[3]) : "r"(a))

#define MMA_F16(c, a, b0, b1) \
    asm volatile("mma.sync.aligned.m16n8k16.row.col.f32.f16.f16.f32 " \
        "{%0,%1,%2,%3}, {%4,%5,%6,%7}, {%8,%9}, {%0,%1,%2,%3};" \
        : "+f"((c)[0]), "+f"((c)[1]), "+f"((c)[2]), "+f"((c)[3]) \
        : "r"((a)[0]), "r"((a)[1]), "r"((a)[2]), "r"((a)[3]), "r"(b0), "r"(b1))

// ============================================================
// prep: ONE kernel, three independent jobs dispatched on blockIdx
// ============================================================
#define PREP_SUP   NN
#define PREP_XQ    (PREP_SUP + 4096)
#define PREP_TOTAL (PREP_XQ + 6144)

__global__ __launch_bounds__(256) void prep_kernel(const float* __restrict__ x,
                                                   const float* __restrict__ E,
                                                   const float* __restrict__ Wp) {
    __shared__ float sh[2048 + 256];
    const int tid = threadIdx.x;
    const int bid = blockIdx.x;

    if (bid < PREP_SUP) {
        // ---- supports row n ----
        float* vals = sh;
        float* red  = sh + 2048;
        const int n = bid;

        float en[ND];
#pragma unroll
        for (int d = 0; d < ND; d++) en[d] = E[n * ND + d];

        float lmax = -1e30f;
        for (int m = tid; m < NN; m += 256) {
            float v = 0.f;
#pragma unroll
            for (int d = 0; d < ND; d++) v = fmaf(en[d], E[m * ND + d], v);
            v = fmaxf(v, 0.f);
            vals[m] = v;
            lmax = fmaxf(lmax, v);
        }
        red[tid] = lmax; __syncthreads();
        for (int s = 128; s > 0; s >>= 1) { if (tid < s) red[tid] = fmaxf(red[tid], red[tid + s]); __syncthreads(); }
        const float gmax = red[0]; __syncthreads();

        float lsum = 0.f;
        for (int m = tid; m < NN; m += 256) {
            float e = expf(vals[m] - gmax);
            vals[m] = e; lsum += e;
        }
        red[tid] = lsum; __syncthreads();
        for (int s = 128; s > 0; s >>= 1) { if (tid < s) red[tid] += red[tid + s]; __syncthreads(); }
        const float inv = 1.f / red[0];
        for (int m = tid; m < NN; m += 256)
            g_S[n * NN + m] = __float2half_rn(vals[m] * inv);

    } else if (bid < PREP_XQ) {
        // ---- Xq tile: Xq[b*64+c][m] = fp16(x[b][m][c]), half2 stores ----
        const int id = bid - PREP_SUP;
        const int m0 = (id & 63) * 32;
        const int b  = id >> 6;
        float* sm = sh;   // 64*33 floats
#pragma unroll
        for (int p = 0; p < 8; p++) {
            int e = tid + 256 * p;
            int r = e >> 6, c = e & 63;
            sm[c * 33 + r] = x[(size_t)b * (NN * NC) + (size_t)(m0 + r) * NC + c];
        }
        __syncthreads();
#pragma unroll
        for (int p = 0; p < 4; p++) {
            int e = tid + 256 * p;          // 1024 half2 elements (64c x 16 pairs)
            int c = e >> 4, r2 = (e & 15) * 2;
            __half2 hp = __floats2half2_rn(sm[c * 33 + r2], sm[c * 33 + r2 + 1]);
            *(__half2*)&g_Xq[(size_t)(b * 64 + c) * NN + m0 + r2] = hp;
        }

    } else {
        // ---- weights tile: W16[n, e] = fp16(sum_d E[n,d]*Wp[d,e]) ----
        const int id = bid - PREP_XQ;
        const int e0 = (id % 48) * 256;
        const int n0 = (id / 48) * 16;
        float* Es = sh;   // [16][ND]
        if (tid < 16 * ND) Es[tid] = E[(n0 + tid / ND) * ND + (tid % ND)];
        __syncthreads();
        const int e = e0 + tid;
        float wp[ND];
#pragma unroll
        for (int d = 0; d < ND; d++) wp[d] = Wp[d * (KI * NC) + e];
#pragma unroll
        for (int nn = 0; nn < 16; nn++) {
            float acc = 0.f;
#pragma unroll
            for (int d = 0; d < ND; d++) acc = fmaf(Es[nn * ND + d], wp[d], acc);
            g_W16[(size_t)(n0 + nn) * (KI * NC) + e] = __float2half_rn(acc);
        }
    }
}

// ============================================================
// single-term fp16 GEMM (m16n8k16): C[128x128] tile, 256 threads,
// 8 warps (2x4), warp tile 64x32. 3-stage cp.async, 2 CTAs/SM.
// Epilogue writes Y fp16 [n][j] (+ MODE 1: Y1q fp16 [j][m]).
// ============================================================
#define STG_A 0
#define STG_B 16384
#define STAGE_BYTES 32768
#define GEMM_SMEM 98304
#define NITER (NN / 64)            // 32

template <int MODE>
__global__ void __launch_bounds__(256, 2) gemm_fp16_kernel() {
    extern __shared__ float dsm[];
    const int t = threadIdx.x;
    const int l = t & 31;
    const int wid = t >> 5;
    const int wm = wid >> 2;       // 0..1  (m, 64 rows each)
    const int wn = wid & 3;        // 0..3  (n, 32 cols each)
    const int bm = blockIdx.y * 128;
    const int bn = blockIdx.x * 128;

    const __half* Ap = g_S + (size_t)bm * NN;
    const __half* Bp = (MODE == 1 ? g_Xq : g_Y1q) + (size_t)bn * NN;

    const uint32_t sb0 = smem_u32(dsm);

    auto load_stage = [&](int s, int k0) {
        const uint32_t sb = sb0 + (uint32_t)s * STAGE_BYTES;
#pragma unroll
        for (int p = 0; p < 4; p++) {
            const int g = t + 256 * p;
            const int row = g >> 3;
            const int c16 = g & 7;
            const int sw = c16 ^ (row & 7);
            cpa16(sb + STG_A + (uint32_t)(row * 128 + sw * 16),
                  Ap + (size_t)row * NN + k0 + c16 * 8);
        }
#pragma unroll
        for (int p = 0; p < 4; p++) {
            const int g = t + 256 * p;
            const int row = g >> 3;
            const int c16 = g & 7;
            const int sw = c16 ^ (row & 7);
            cpa16(sb + STG_B + (uint32_t)(row * 128 + sw * 16),
                  Bp + (size_t)row * NN + k0 + c16 * 8);
        }
        asm volatile("cp.async.commit_group;" ::: "memory");
    };

    float acc[4][4][4];
#pragma unroll
    for (int a = 0; a < 4; a++)
#pragma unroll
        for (int b = 0; b < 4; b++)
#pragma unroll
            for (int c = 0; c < 4; c++) acc[a][b][c] = 0.f;

    const int t4 = l >> 3;
    const int l7 = l & 7;
    const int arow_in = ((t4 & 1) << 3) + l7;
    const int brow_in = ((t4 >> 1) << 3) + l7;
    const uint32_t abase = (uint32_t)((wm * 64 + arow_in) * 128);
    const uint32_t bbase = (uint32_t)((wn * 32 + brow_in) * 128);
    const int akg = t4 >> 1;
    const int bkg = t4 & 1;

    load_stage(0, 0);
    load_stage(1, 64);

    for (int i = 0; i < NITER; i++) {
        if (i + 2 < NITER)
            asm volatile("cp.async.wait_group 1;" ::: "memory");
        else
            asm volatile("cp.async.wait_group 0;" ::: "memory");
        __syncthreads();
        if (i + 2 < NITER) load_stage((i + 2) % 3, (i + 2) * 64);
        const uint32_t sb = sb0 + (uint32_t)(i % 3) * STAGE_BYTES;
#pragma unroll
        for (int ks = 0; ks < 4; ks++) {
            const uint32_t xa = (uint32_t)(((ks * 2 + akg) ^ l7) << 4);
            const uint32_t xb = (uint32_t)(((ks * 2 + bkg) ^ l7) << 4);
            uint32_t af[4][4], bf[2][4];
#pragma unroll
            for (int mt = 0; mt < 4; mt++)
                LDSM4(af[mt], sb + STG_A + abase + (uint32_t)(mt * 16 * 128) + xa);
#pragma unroll
            for (int nh = 0; nh < 2; nh++)
                LDSM4(bf[nh], sb + STG_B + bbase + (uint32_t)(nh * 16 * 128) + xb);
#pragma unroll
            for (int mt = 0; mt < 4; mt++)
#pragma unroll
                for (int n8 = 0; n8 < 4; n8++) {
                    const int nh = n8 >> 1, q = (n8 & 1) * 2;
                    MMA_F16(acc[mt][n8], af[mt], bf[nh][q], bf[nh][q + 1]);
                }
        }
    }

    // ---------------- epilogue: Y fp16 [n][j] ----------------
    __half* Yh = (MODE == 1) ? g_Y1h : g_Y2h;
    const int lm = l >> 2;
    const int lc = (l & 3) << 1;
#pragma unroll
    for (int mt = 0; mt < 4; mt++)
#pragma unroll
        for (int n8 = 0; n8 < 4; n8++) {
            const int r = bm + wm * 64 + mt * 16 + lm;
            const int col = bn + wn * 32 + n8 * 8 + lc;
            *(__half2*)&Yh[(size_t)r * NJ + col] =
                __floats2half2_rn(acc[mt][n8][0], acc[mt][n8][1]);
            *(__half2*)&Yh[(size_t)(r + 8) * NJ + col] =
                __floats2half2_rn(acc[mt][n8][2], acc[mt][n8][3]);
        }

    if (MODE == 1) {
        // transpose 128m x 128j tile via smem, write Y1q fp16 [j][m]
        __syncthreads();
#pragma unroll
        for (int mt = 0; mt < 4; mt++)
#pragma unroll
            for (int n8 = 0; n8 < 4; n8++) {
                const int jl = wn * 32 + n8 * 8 + lc;
                const int ml = wm * 64 + mt * 16 + lm;
                dsm[jl * 132 + ml]           = acc[mt][n8][0];
                dsm[(jl + 1) * 132 + ml]     = acc[mt][n8][1];
                dsm[jl * 132 + ml + 8]       = acc[mt][n8][2];
                dsm[(jl + 1) * 132 + ml + 8] = acc[mt][n8][3];
            }
        __syncthreads();
#pragma unroll
        for (int it = 0; it < 16; it++) {
            const int j = wid * 16 + it;
            const int m4 = l * 4;
            const float4 v = *(const float4*)&dsm[j * 132 + m4];
            __half2 p0 = __floats2half2_rn(v.x, v.y);
            __half2 p1 = __floats2half2_rn(v.z, v.w);
            uint2 w;
            w.x = *(uint32_t*)&p0; w.y = *(uint32_t*)&p1;
            *(uint2*)&g_Y1q[(size_t)(bn + j) * NN + bm + m4] = w;
        }
    }
}

// ============================================================
// output (tensor-core): per node n, out[b,o] = A[b,ki] @ W[ki,o] + bias
//   A channels: {x, Y1(fp16), 2*Y2(fp16)-x}; terms Ah*W + Al*W
// ============================================================
#define OUT_SMEM 73728   // AHI 24576 + ALO 24576 + WHI 24576

__global__ void __launch_bounds__(256, 2) output_kernel(const float* __restrict__ x,
                                                        const float* __restrict__ E,
                                                        const float* __restrict__ bp,
                                                        float* __restrict__ out) {
    extern __shared__ char osm[];
    const uint32_t base = smem_u32(osm);
    const uint32_t AHI = base;
    const uint32_t ALO = base + 24576;
    const uint32_t WHI = base + 49152;

    const int n = blockIdx.x;
    const int tid = threadIdx.x;
    const int l = tid & 31;
    const int wid = tid >> 5;
    const int wm = wid >> 2;     // 0..1 (b, 32 rows)
    const int wn = wid & 3;      // 0..3 (o, 16 cols)

    const __half* Whg = g_W16 + (size_t)n * (KI * NC);
#pragma unroll
    for (int p = 0; p < 6; p++) {
        const int g = tid + 256 * p;
        const int ki = g >> 3;
        const int og = g & 7;
        cpa16(WHI + (uint32_t)(ki * 128 + ((og ^ (ki & 7)) << 4)),
              Whg + ki * 64 + og * 8);
    }
    asm volatile("cp.async.commit_group;" ::: "memory");

    // ---- build A planes [b=64][ki=192] fp16 hi/lo ----
    for (int e = tid * 2; e < NJ; e += 512) {
        const int b = e >> 6;
        const int i = e & 63;            // even
        const float2 xv = *(const float2*)&x[(size_t)b * (NN * NC) + n * NC + i];
        const __half2 y1h = *(const __half2*)&g_Y1h[(size_t)n * NJ + e];
        const __half2 y2h = *(const __half2*)&g_Y2h[(size_t)n * NJ + e];
        const float2 y1 = __half22float2(y1h);
        const float2 y2 = __half22float2(y2h);
        const float2 vals[3] = { xv, y1,
            make_float2(2.f * y2.x - xv.x, 2.f * y2.y - xv.y) };
#pragma unroll
        for (int kch = 0; kch < 3; kch++) {
            const int ki = kch * 64 + i;  // even
            __half h0, l0, h1, l1;
            fp16_split(vals[kch].x, h0, l0);
            fp16_split(vals[kch].y, h1, l1);
            const uint32_t addr = (uint32_t)(b * 384 + ((ki >> 6) << 7) +
                ((((ki >> 3) & 7) ^ (b & 7)) << 4) + ((ki & 7) << 1));
            *(__half2*)(osm + (AHI - base) + addr) = make_half2(h0, h1);
            *(__half2*)(osm + (ALO - base) + addr) = make_half2(l0, l1);
        }
    }
    asm volatile("cp.async.wait_group 0;" ::: "memory");
    __syncthreads();

    float acc[2][2][4];
#pragma unroll
    for (int a = 0; a < 2; a++)
#pragma unroll
        for (int b = 0; b < 2; b++)
#pragma unroll
            for (int c = 0; c < 4; c++) acc[a][b][c] = 0.f;

    const int t4 = l >> 3;
    const int l7 = l & 7;
    const int arow_in = ((t4 & 1) << 3) + l7;
    const int akg = t4 >> 1;
    const int wrow_in = ((t4 & 1) << 3) + l7;
    const int wog = wn * 2 + (t4 >> 1);

#pragma unroll
    for (int ks = 0; ks < 12; ks++) {
        uint32_t ahf[2][4], alf[2][4], whf[4];
        const int kg = ks * 2 + akg;
#pragma unroll
        for (int mt = 0; mt < 2; mt++) {
            const int row = wm * 32 + mt * 16 + arow_in;
            const uint32_t aaddr = (uint32_t)(row * 384 + ((kg >> 3) << 7) +
                (((kg & 7) ^ (row & 7)) << 4));
            LDSM4(ahf[mt], AHI + aaddr);
            LDSM4(alf[mt], ALO + aaddr);
        }
        {
            const int wrow = ks * 16 + wrow_in;
            LDSM4T(whf, WHI + (uint32_t)(wrow * 128 + ((wog ^ (wrow & 7)) << 4)));
        }
#pragma unroll
        for (int mt = 0; mt < 2; mt++)
#pragma unroll
            for (int n8 = 0; n8 < 2; n8++)
                MMA_F16(acc[mt][n8], ahf[mt], whf[n8 * 2], whf[n8 * 2 + 1]);
#pragma unroll
        for (int mt = 0; mt < 2; mt++)
#pragma unroll
            for (int n8 = 0; n8 < 2; n8++)
                MMA_F16(acc[mt][n8], alf[mt], whf[n8 * 2], whf[n8 * 2 + 1]);
    }

    const int lm = l >> 2;
    const int lc = (l & 3) << 1;
    float bias[2][2];
#pragma unroll
    for (int n8 = 0; n8 < 2; n8++)
#pragma unroll
        for (int cc = 0; cc < 2; cc++) {
            const int o = wn * 16 + n8 * 8 + lc + cc;
            float s = 0.f;
#pragma unroll
            for (int d = 0; d < ND; d++) s = fmaf(E[n * ND + d], bp[d * NC + o], s);
            bias[n8][cc] = s;
        }

#pragma unroll
    for (int mt = 0; mt < 2; mt++)
#pragma unroll
        for (int n8 = 0; n8 < 2; n8++) {
            const int b0 = wm * 32 + mt * 16 + lm;
            const int col = wn * 16 + n8 * 8 + lc;
            *(float2*)&out[(size_t)b0 * (NN * NC) + n * NC + col] =
                make_float2(acc[mt][n8][0] + bias[n8][0], acc[mt][n8][1] + bias[n8][1]);
            *(float2*)&out[(size_t)(b0 + 8) * (NN * NC) + n * NC + col] =
                make_float2(acc[mt][n8][2] + bias[n8][0], acc[mt][n8][3] + bias[n8][1]);
        }
}

// ============================================================
extern "C" void kernel_launch(void* const* d_in, const int* in_sizes, int n_in,
                              void* d_out, int out_size) {
    (void)in_sizes; (void)n_in; (void)out_size;
    const float* x  = (const float*)d_in[0];
    const float* E  = (const float*)d_in[1];
    const float* Wp = (const float*)d_in[2];
    const float* bp = (const float*)d_in[3];
    float* out = (float*)d_out;

    cudaFuncSetAttribute(output_kernel, cudaFuncAttributeMaxDynamicSharedMemorySize, OUT_SMEM);
    cudaFuncSetAttribute(gemm_fp16_kernel<1>, cudaFuncAttributeMaxDynamicSharedMemorySize, GEMM_SMEM);
    cudaFuncSetAttribute(gemm_fp16_kernel<2>, cudaFuncAttributeMaxDynamicSharedMemorySize, GEMM_SMEM);

    prep_kernel<<<PREP_TOTAL, 256>>>(x, E, Wp);

    dim3 ggrid(NJ / 128, NN / 128);   // (32, 16) = 512 CTAs
    gemm_fp16_kernel<1><<<ggrid, 256, GEMM_SMEM>>>();
    gemm_fp16_kernel<2><<<ggrid, 256, GEMM_SMEM>>>();

    output_kernel<<<NN, 256, OUT_SMEM>>>(x, E, bp, out);
}

// round 13
// speedup vs baseline: 3.0529x; 1.1306x over previous
#include <cuda_runtime.h>
#include <cuda_fp16.h>
#include <math.h>
#include <stdint.h>

#define NB 64
#define NN 2048
#define NC 64
#define ND 10
#define NJ 4096          // NB*NC
#define KI 192           // cheb_k * C_IN

// ------------------ scratch (static device globals) ------------------
__device__ __half g_S   [NN * NN];            // fp16 supports
__device__ __half g_Xq  [(size_t)NJ * NN];    // [j][m] fp16
__device__ __half g_Y1q [(size_t)NJ * NN];    // [j][m] fp16
__device__ __half g_Y1h [(size_t)NN * NJ];    // [n][j] fp16
__device__ __half g_Y2h [(size_t)NN * NJ];    // [n][j] fp16
__device__ __half g_W16 [(size_t)NN * KI * NC];  // [n][ki][o] fp16

// ------------------ helpers ------------------
__device__ __forceinline__ uint32_t smem_u32(const void* p) {
    uint32_t a;
    asm("{ .reg .u64 t; cvta.to.shared.u64 t, %1; cvt.u32.u64 %0, t; }" : "=r"(a) : "l"(p));
    return a;
}
__device__ __forceinline__ void cpa16(uint32_t s, const void* g) {
    asm volatile("cp.async.cg.shared.global [%0], [%1], 16;" :: "r"(s), "l"(g));
}

#define LDSM4(r, a) \
    asm volatile("ldmatrix.sync.aligned.m8n8.x4.shared.b16 {%0,%1,%2,%3}, [%4];" \
        : "=r"((r)[0]), "=r"((r)[1]), "=r"((r)[2]), "=r"((r)[3]) : "r"(a))

#define LDSM4T(r, a) \
    asm volatile("ldmatrix.sync.aligned.m8n8.x4.trans.shared.b16 {%0,%1,%2,%3}, [%4];" \
        : "=r"((r)[0]), "=r"((r)[1]), "=r"((r)[2]), "=r"((r)[3]) : "r"(a))

#define MMA_F16(c, a, b0, b1) \
    asm volatile("mma.sync.aligned.m16n8k16.row.col.f32.f16.f16.f32 " \
        "{%0,%1,%2,%3}, {%4,%5,%6,%7}, {%8,%9}, {%0,%1,%2,%3};" \
        : "+f"((c)[0]), "+f"((c)[1]), "+f"((c)[2]), "+f"((c)[3]) \
        : "r"((a)[0]), "r"((a)[1]), "r"((a)[2]), "r"((a)[3]), "r"(b0), "r"(b1))

// ============================================================
// prep: ONE kernel, three independent jobs dispatched on blockIdx
// ============================================================
#define PREP_SUP   NN
#define PREP_XQ    (PREP_SUP + 4096)
#define PREP_TOTAL (PREP_XQ + 6144)

__global__ __launch_bounds__(256) void prep_kernel(const float* __restrict__ x,
                                                   const float* __restrict__ E,
                                                   const float* __restrict__ Wp) {
    __shared__ float sh[2048 + 256];
    const int tid = threadIdx.x;
    const int bid = blockIdx.x;

    if (bid < PREP_SUP) {
        // ---- supports row n ----
        float* vals = sh;
        float* red  = sh + 2048;
        const int n = bid;

        float en[ND];
#pragma unroll
        for (int d = 0; d < ND; d++) en[d] = E[n * ND + d];

        float lmax = -1e30f;
        for (int m = tid; m < NN; m += 256) {
            float v = 0.f;
#pragma unroll
            for (int d = 0; d < ND; d++) v = fmaf(en[d], E[m * ND + d], v);
            v = fmaxf(v, 0.f);
            vals[m] = v;
            lmax = fmaxf(lmax, v);
        }
        red[tid] = lmax; __syncthreads();
        for (int s = 128; s > 0; s >>= 1) { if (tid < s) red[tid] = fmaxf(red[tid], red[tid + s]); __syncthreads(); }
        const float gmax = red[0]; __syncthreads();

        float lsum = 0.f;
        for (int m = tid; m < NN; m += 256) {
            float e = expf(vals[m] - gmax);
            vals[m] = e; lsum += e;
        }
        red[tid] = lsum; __syncthreads();
        for (int s = 128; s > 0; s >>= 1) { if (tid < s) red[tid] += red[tid + s]; __syncthreads(); }
        const float inv = 1.f / red[0];
        for (int m = tid; m < NN; m += 256)
            g_S[n * NN + m] = __float2half_rn(vals[m] * inv);

    } else if (bid < PREP_XQ) {
        // ---- Xq tile: Xq[b*64+c][m] = fp16(x[b][m][c]), half2 stores ----
        const int id = bid - PREP_SUP;
        const int m0 = (id & 63) * 32;
        const int b  = id >> 6;
        float* sm = sh;   // 64*33 floats
#pragma unroll
        for (int p = 0; p < 8; p++) {
            int e = tid + 256 * p;
            int r = e >> 6, c = e & 63;
            sm[c * 33 + r] = x[(size_t)b * (NN * NC) + (size_t)(m0 + r) * NC + c];
        }
        __syncthreads();
#pragma unroll
        for (int p = 0; p < 4; p++) {
            int e = tid + 256 * p;
            int c = e >> 4, r2 = (e & 15) * 2;
            __half2 hp = __floats2half2_rn(sm[c * 33 + r2], sm[c * 33 + r2 + 1]);
            *(__half2*)&g_Xq[(size_t)(b * 64 + c) * NN + m0 + r2] = hp;
        }

    } else {
        // ---- weights tile: W16[n, e] = fp16(sum_d E[n,d]*Wp[d,e]) ----
        const int id = bid - PREP_XQ;
        const int e0 = (id % 48) * 256;
        const int n0 = (id / 48) * 16;
        float* Es = sh;   // [16][ND]
        if (tid < 16 * ND) Es[tid] = E[(n0 + tid / ND) * ND + (tid % ND)];
        __syncthreads();
        const int e = e0 + tid;
        float wp[ND];
#pragma unroll
        for (int d = 0; d < ND; d++) wp[d] = Wp[d * (KI * NC) + e];
#pragma unroll
        for (int nn = 0; nn < 16; nn++) {
            float acc = 0.f;
#pragma unroll
            for (int d = 0; d < ND; d++) acc = fmaf(Es[nn * ND + d], wp[d], acc);
            g_W16[(size_t)(n0 + nn) * (KI * NC) + e] = __float2half_rn(acc);
        }
    }
}

// ============================================================
// single-term fp16 GEMM (m16n8k16): C[128x128] tile, 256 threads,
// 8 warps (2x4), warp tile 64x32. 3-stage cp.async, 2 CTAs/SM.
// ============================================================
#define STG_A 0
#define STG_B 16384
#define STAGE_BYTES 32768
#define GEMM_SMEM 98304
#define NITER (NN / 64)            // 32

template <int MODE>
__global__ void __launch_bounds__(256, 2) gemm_fp16_kernel() {
    extern __shared__ float dsm[];
    const int t = threadIdx.x;
    const int l = t & 31;
    const int wid = t >> 5;
    const int wm = wid >> 2;
    const int wn = wid & 3;
    const int bm = blockIdx.y * 128;
    const int bn = blockIdx.x * 128;

    const __half* Ap = g_S + (size_t)bm * NN;
    const __half* Bp = (MODE == 1 ? g_Xq : g_Y1q) + (size_t)bn * NN;

    const uint32_t sb0 = smem_u32(dsm);

    auto load_stage = [&](int s, int k0) {
        const uint32_t sb = sb0 + (uint32_t)s * STAGE_BYTES;
#pragma unroll
        for (int p = 0; p < 4; p++) {
            const int g = t + 256 * p;
            const int row = g >> 3;
            const int c16 = g & 7;
            const int sw = c16 ^ (row & 7);
            cpa16(sb + STG_A + (uint32_t)(row * 128 + sw * 16),
                  Ap + (size_t)row * NN + k0 + c16 * 8);
        }
#pragma unroll
        for (int p = 0; p < 4; p++) {
            const int g = t + 256 * p;
            const int row = g >> 3;
            const int c16 = g & 7;
            const int sw = c16 ^ (row & 7);
            cpa16(sb + STG_B + (uint32_t)(row * 128 + sw * 16),
                  Bp + (size_t)row * NN + k0 + c16 * 8);
        }
        asm volatile("cp.async.commit_group;" ::: "memory");
    };

    float acc[4][4][4];
#pragma unroll
    for (int a = 0; a < 4; a++)
#pragma unroll
        for (int b = 0; b < 4; b++)
#pragma unroll
            for (int c = 0; c < 4; c++) acc[a][b][c] = 0.f;

    const int t4 = l >> 3;
    const int l7 = l & 7;
    const int arow_in = ((t4 & 1) << 3) + l7;
    const int brow_in = ((t4 >> 1) << 3) + l7;
    const uint32_t abase = (uint32_t)((wm * 64 + arow_in) * 128);
    const uint32_t bbase = (uint32_t)((wn * 32 + brow_in) * 128);
    const int akg = t4 >> 1;
    const int bkg = t4 & 1;

    load_stage(0, 0);
    load_stage(1, 64);

    for (int i = 0; i < NITER; i++) {
        if (i + 2 < NITER)
            asm volatile("cp.async.wait_group 1;" ::: "memory");
        else
            asm volatile("cp.async.wait_group 0;" ::: "memory");
        __syncthreads();
        if (i + 2 < NITER) load_stage((i + 2) % 3, (i + 2) * 64);
        const uint32_t sb = sb0 + (uint32_t)(i % 3) * STAGE_BYTES;
#pragma unroll
        for (int ks = 0; ks < 4; ks++) {
            const uint32_t xa = (uint32_t)(((ks * 2 + akg) ^ l7) << 4);
            const uint32_t xb = (uint32_t)(((ks * 2 + bkg) ^ l7) << 4);
            uint32_t af[4][4], bf[2][4];
#pragma unroll
            for (int mt = 0; mt < 4; mt++)
                LDSM4(af[mt], sb + STG_A + abase + (uint32_t)(mt * 16 * 128) + xa);
#pragma unroll
            for (int nh = 0; nh < 2; nh++)
                LDSM4(bf[nh], sb + STG_B + bbase + (uint32_t)(nh * 16 * 128) + xb);
#pragma unroll
            for (int mt = 0; mt < 4; mt++)
#pragma unroll
                for (int n8 = 0; n8 < 4; n8++) {
                    const int nh = n8 >> 1, q = (n8 & 1) * 2;
                    MMA_F16(acc[mt][n8], af[mt], bf[nh][q], bf[nh][q + 1]);
                }
        }
    }

    // ---------------- epilogue: Y fp16 [n][j] ----------------
    __half* Yh = (MODE == 1) ? g_Y1h : g_Y2h;
    const int lm = l >> 2;
    const int lc = (l & 3) << 1;
#pragma unroll
    for (int mt = 0; mt < 4; mt++)
#pragma unroll
        for (int n8 = 0; n8 < 4; n8++) {
            const int r = bm + wm * 64 + mt * 16 + lm;
            const int col = bn + wn * 32 + n8 * 8 + lc;
            *(__half2*)&Yh[(size_t)r * NJ + col] =
                __floats2half2_rn(acc[mt][n8][0], acc[mt][n8][1]);
            *(__half2*)&Yh[(size_t)(r + 8) * NJ + col] =
                __floats2half2_rn(acc[mt][n8][2], acc[mt][n8][3]);
        }

    if (MODE == 1) {
        __syncthreads();
#pragma unroll
        for (int mt = 0; mt < 4; mt++)
#pragma unroll
            for (int n8 = 0; n8 < 4; n8++) {
                const int jl = wn * 32 + n8 * 8 + lc;
                const int ml = wm * 64 + mt * 16 + lm;
                dsm[jl * 132 + ml]           = acc[mt][n8][0];
                dsm[(jl + 1) * 132 + ml]     = acc[mt][n8][1];
                dsm[jl * 132 + ml + 8]       = acc[mt][n8][2];
                dsm[(jl + 1) * 132 + ml + 8] = acc[mt][n8][3];
            }
        __syncthreads();
#pragma unroll
        for (int it = 0; it < 16; it++) {
            const int j = wid * 16 + it;
            const int m4 = l * 4;
            const float4 v = *(const float4*)&dsm[j * 132 + m4];
            __half2 p0 = __floats2half2_rn(v.x, v.y);
            __half2 p1 = __floats2half2_rn(v.z, v.w);
            uint2 w;
            w.x = *(uint32_t*)&p0; w.y = *(uint32_t*)&p1;
            *(uint2*)&g_Y1q[(size_t)(bn + j) * NN + bm + m4] = w;
        }
    }
}

// ============================================================
// output (tensor-core, single-term): out[b,o] = A[b,ki]@W[ki,o] + bias
//   A = fp16{x, Y1, 2*Y2-x}; 48KB smem; 3 CTAs/SM for latency hiding.
// ============================================================
#define OUT_SMEM 49152   // AHI 24576 + WHI 24576

__global__ void __launch_bounds__(256, 3) output_kernel(const float* __restrict__ x,
                                                        const float* __restrict__ E,
                                                        const float* __restrict__ bp,
                                                        float* __restrict__ out) {
    extern __shared__ char osm[];
    const uint32_t base = smem_u32(osm);
    const uint32_t AHI = base;
    const uint32_t WHI = base + 24576;

    const int n = blockIdx.x;
    const int tid = threadIdx.x;
    const int l = tid & 31;
    const int wid = tid >> 5;
    const int wm = wid >> 2;     // 0..1 (b, 32 rows)
    const int wn = wid & 3;      // 0..3 (o, 16 cols)

    const __half* Whg = g_W16 + (size_t)n * (KI * NC);
#pragma unroll
    for (int p = 0; p < 6; p++) {
        const int g = tid + 256 * p;
        const int ki = g >> 3;
        const int og = g & 7;
        cpa16(WHI + (uint32_t)(ki * 128 + ((og ^ (ki & 7)) << 4)),
              Whg + ki * 64 + og * 8);
    }
    asm volatile("cp.async.commit_group;" ::: "memory");

    // ---- build A plane [b=64][ki=192] fp16, unrolled for MLP ----
#pragma unroll
    for (int it = 0; it < 8; it++) {
        const int e = tid * 2 + it * 512;
        const int b = e >> 6;
        const int i = e & 63;            // even
        const float2 xv = *(const float2*)&x[(size_t)b * (NN * NC) + n * NC + i];
        const float2 y1 = __half22float2(*(const __half2*)&g_Y1h[(size_t)n * NJ + e]);
        const float2 y2 = __half22float2(*(const __half2*)&g_Y2h[(size_t)n * NJ + e]);
        const float2 vals[3] = { xv, y1,
            make_float2(2.f * y2.x - xv.x, 2.f * y2.y - xv.y) };
#pragma unroll
        for (int kch = 0; kch < 3; kch++) {
            const int ki = kch * 64 + i;  // even
            const uint32_t addr = (uint32_t)(b * 384 + ((ki >> 6) << 7) +
                ((((ki >> 3) & 7) ^ (b & 7)) << 4) + ((ki & 7) << 1));
            *(__half2*)(osm + addr) = __floats2half2_rn(vals[kch].x, vals[kch].y);
        }
    }
    asm volatile("cp.async.wait_group 0;" ::: "memory");
    __syncthreads();

    float acc[2][2][4];
#pragma unroll
    for (int a = 0; a < 2; a++)
#pragma unroll
        for (int b = 0; b < 2; b++)
#pragma unroll
            for (int c = 0; c < 4; c++) acc[a][b][c] = 0.f;

    const int t4 = l >> 3;
    const int l7 = l & 7;
    const int arow_in = ((t4 & 1) << 3) + l7;
    const int akg = t4 >> 1;
    const int wrow_in = ((t4 & 1) << 3) + l7;
    const int wog = wn * 2 + (t4 >> 1);

#pragma unroll
    for (int ks = 0; ks < 12; ks++) {
        uint32_t ahf[2][4], whf[4];
        const int kg = ks * 2 + akg;
#pragma unroll
        for (int mt = 0; mt < 2; mt++) {
            const int row = wm * 32 + mt * 16 + arow_in;
            const uint32_t aaddr = (uint32_t)(row * 384 + ((kg >> 3) << 7) +
                (((kg & 7) ^ (row & 7)) << 4));
            LDSM4(ahf[mt], AHI + aaddr);
        }
        {
            const int wrow = ks * 16 + wrow_in;
            LDSM4T(whf, WHI + (uint32_t)(wrow * 128 + ((wog ^ (wrow & 7)) << 4)));
        }
#pragma unroll
        for (int mt = 0; mt < 2; mt++)
#pragma unroll
            for (int n8 = 0; n8 < 2; n8++)
                MMA_F16(acc[mt][n8], ahf[mt], whf[n8 * 2], whf[n8 * 2 + 1]);
    }

    const int lm = l >> 2;
    const int lc = (l & 3) << 1;
    float bias[2][2];
#pragma unroll
    for (int n8 = 0; n8 < 2; n8++)
#pragma unroll
        for (int cc = 0; cc < 2; cc++) {
            const int o = wn * 16 + n8 * 8 + lc + cc;
            float s = 0.f;
#pragma unroll
            for (int d = 0; d < ND; d++) s = fmaf(E[n * ND + d], bp[d * NC + o], s);
            bias[n8][cc] = s;
        }

#pragma unroll
    for (int mt = 0; mt < 2; mt++)
#pragma unroll
        for (int n8 = 0; n8 < 2; n8++) {
            const int b0 = wm * 32 + mt * 16 + lm;
            const int col = wn * 16 + n8 * 8 + lc;
            *(float2*)&out[(size_t)b0 * (NN * NC) + n * NC + col] =
                make_float2(acc[mt][n8][0] + bias[n8][0], acc[mt][n8][1] + bias[n8][1]);
            *(float2*)&out[(size_t)(b0 + 8) * (NN * NC) + n * NC + col] =
                make_float2(acc[mt][n8][2] + bias[n8][0], acc[mt][n8][3] + bias[n8][1]);
        }
}

// ============================================================
extern "C" void kernel_launch(void* const* d_in, const int* in_sizes, int n_in,
                              void* d_out, int out_size) {
    (void)in_sizes; (void)n_in; (void)out_size;
    const float* x  = (const float*)d_in[0];
    const float* E  = (const float*)d_in[1];
    const float* Wp = (const float*)d_in[2];
    const float* bp = (const float*)d_in[3];
    float* out = (float*)d_out;

    cudaFuncSetAttribute(output_kernel, cudaFuncAttributeMaxDynamicSharedMemorySize, OUT_SMEM);
    cudaFuncSetAttribute(gemm_fp16_kernel<1>, cudaFuncAttributeMaxDynamicSharedMemorySize, GEMM_SMEM);
    cudaFuncSetAttribute(gemm_fp16_kernel<2>, cudaFuncAttributeMaxDynamicSharedMemorySize, GEMM_SMEM);

    prep_kernel<<<PREP_TOTAL, 256>>>(x, E, Wp);

    dim3 ggrid(NJ / 128, NN / 128);   // (32, 16) = 512 CTAs
    gemm_fp16_kernel<1><<<ggrid, 256, GEMM_SMEM>>>();
    gemm_fp16_kernel<2><<<ggrid, 256, GEMM_SMEM>>>();

    output_kernel<<<NN, 256, OUT_SMEM>>>(x, E, bp, out);
}

// round 14
// speedup vs baseline: 3.0769x; 1.0079x over previous
#include <cuda_runtime.h>
#include <cuda_fp16.h>
#include <math.h>
#include <stdint.h>

#define NB 64
#define NN 2048
#define NC 64
#define ND 10
#define NJ 4096          // NB*NC
#define KI 192           // cheb_k * C_IN

// ------------------ scratch (static device globals) ------------------
__device__ __half g_S   [NN * NN];            // fp16 supports
__device__ __half g_Xq  [(size_t)NJ * NN];    // [j][m] fp16
__device__ __half g_Y1q [(size_t)NJ * NN];    // [j][m] fp16
__device__ __half g_Y1h [(size_t)NN * NJ];    // [n][j] fp16
__device__ __half g_Y2h [(size_t)NN * NJ];    // [n][j] fp16
__device__ __half g_W16 [(size_t)NN * KI * NC];  // [n][ki][o] fp16

// ------------------ helpers ------------------
__device__ __forceinline__ uint32_t smem_u32(const void* p) {
    uint32_t a;
    asm("{ .reg .u64 t; cvta.to.shared.u64 t, %1; cvt.u32.u64 %0, t; }" : "=r"(a) : "l"(p));
    return a;
}
__device__ __forceinline__ void cpa16(uint32_t s, const void* g) {
    asm volatile("cp.async.cg.shared.global [%0], [%1], 16;" :: "r"(s), "l"(g));
}

#define LDSM4(r, a) \
    asm volatile("ldmatrix.sync.aligned.m8n8.x4.shared.b16 {%0,%1,%2,%3}, [%4];" \
        : "=r"((r)[0]), "=r"((r)[1]), "=r"((r)[2]), "=r"((r)[3]) : "r"(a))

#define LDSM4T(r, a) \
    asm volatile("ldmatrix.sync.aligned.m8n8.x4.trans.shared.b16 {%0,%1,%2,%3}, [%4];" \
        : "=r"((r)[0]), "=r"((r)[1]), "=r"((r)[2]), "=r"((r)[3]) : "r"(a))

#define MMA_F16(c, a, b0, b1) \
    asm volatile("mma.sync.aligned.m16n8k16.row.col.f32.f16.f16.f32 " \
        "{%0,%1,%2,%3}, {%4,%5,%6,%7}, {%8,%9}, {%0,%1,%2,%3};" \
        : "+f"((c)[0]), "+f"((c)[1]), "+f"((c)[2]), "+f"((c)[3]) \
        : "r"((a)[0]), "r"((a)[1]), "r"((a)[2]), "r"((a)[3]), "r"(b0), "r"(b1))

// ============================================================
// prep: ONE kernel, three independent jobs dispatched on blockIdx
// ============================================================
#define PREP_SUP   NN
#define PREP_XQ    (PREP_SUP + 4096)
#define PREP_TOTAL (PREP_XQ + 6144)

__global__ __launch_bounds__(256) void prep_kernel(const float* __restrict__ x,
                                                   const float* __restrict__ E,
                                                   const float* __restrict__ Wp) {
    __shared__ float sh[2048 + 256];
    const int tid = threadIdx.x;
    const int bid = blockIdx.x;

    if (bid < PREP_SUP) {
        // ---- supports row n ----
        float* vals = sh;
        float* red  = sh + 2048;
        const int n = bid;

        float en[ND];
#pragma unroll
        for (int d = 0; d < ND; d++) en[d] = E[n * ND + d];

        float lmax = -1e30f;
        for (int m = tid; m < NN; m += 256) {
            float v = 0.f;
#pragma unroll
            for (int d = 0; d < ND; d++) v = fmaf(en[d], E[m * ND + d], v);
            v = fmaxf(v, 0.f);
            vals[m] = v;
            lmax = fmaxf(lmax, v);
        }
        red[tid] = lmax; __syncthreads();
        for (int s = 128; s > 0; s >>= 1) { if (tid < s) red[tid] = fmaxf(red[tid], red[tid + s]); __syncthreads(); }
        const float gmax = red[0]; __syncthreads();

        float lsum = 0.f;
        for (int m = tid; m < NN; m += 256) {
            float e = expf(vals[m] - gmax);
            vals[m] = e; lsum += e;
        }
        red[tid] = lsum; __syncthreads();
        for (int s = 128; s > 0; s >>= 1) { if (tid < s) red[tid] += red[tid + s]; __syncthreads(); }
        const float inv = 1.f / red[0];
        for (int m = tid; m < NN; m += 256)
            g_S[n * NN + m] = __float2half_rn(vals[m] * inv);

    } else if (bid < PREP_XQ) {
        // ---- Xq tile: Xq[b*64+c][m] = fp16(x[b][m][c]), half2 stores ----
        const int id = bid - PREP_SUP;
        const int m0 = (id & 63) * 32;
        const int b  = id >> 6;
        float* sm = sh;   // 64*33 floats
#pragma unroll
        for (int p = 0; p < 8; p++) {
            int e = tid + 256 * p;
            int r = e >> 6, c = e & 63;
            sm[c * 33 + r] = x[(size_t)b * (NN * NC) + (size_t)(m0 + r) * NC + c];
        }
        __syncthreads();
#pragma unroll
        for (int p = 0; p < 4; p++) {
            int e = tid + 256 * p;
            int c = e >> 4, r2 = (e & 15) * 2;
            __half2 hp = __floats2half2_rn(sm[c * 33 + r2], sm[c * 33 + r2 + 1]);
            *(__half2*)&g_Xq[(size_t)(b * 64 + c) * NN + m0 + r2] = hp;
        }

    } else {
        // ---- weights tile: W16[n, e] = fp16(sum_d E[n,d]*Wp[d,e]) ----
        const int id = bid - PREP_XQ;
        const int e0 = (id % 48) * 256;
        const int n0 = (id / 48) * 16;
        float* Es = sh;   // [16][ND]
        if (tid < 16 * ND) Es[tid] = E[(n0 + tid / ND) * ND + (tid % ND)];
        __syncthreads();
        const int e = e0 + tid;
        float wp[ND];
#pragma unroll
        for (int d = 0; d < ND; d++) wp[d] = Wp[d * (KI * NC) + e];
#pragma unroll
        for (int nn = 0; nn < 16; nn++) {
            float acc = 0.f;
#pragma unroll
            for (int d = 0; d < ND; d++) acc = fmaf(Es[nn * ND + d], wp[d], acc);
            g_W16[(size_t)(n0 + nn) * (KI * NC) + e] = __float2half_rn(acc);
        }
    }
}

// ============================================================
// single-term fp16 GEMM (m16n8k16): C[128x128] tile, 256 threads,
// 8 warps (2x4), warp tile 64x32. 3-stage cp.async, 2 CTAs/SM.
// Fragment double-buffering: LDSM for ks+1 issued under ks's MMAs.
// ============================================================
#define STG_A 0
#define STG_B 16384
#define STAGE_BYTES 32768
#define GEMM_SMEM 98304
#define NITER (NN / 64)            // 32

template <int MODE>
__global__ void __launch_bounds__(256, 2) gemm_fp16_kernel() {
    extern __shared__ float dsm[];
    const int t = threadIdx.x;
    const int l = t & 31;
    const int wid = t >> 5;
    const int wm = wid >> 2;
    const int wn = wid & 3;
    const int bm = blockIdx.y * 128;
    const int bn = blockIdx.x * 128;

    const __half* Ap = g_S + (size_t)bm * NN;
    const __half* Bp = (MODE == 1 ? g_Xq : g_Y1q) + (size_t)bn * NN;

    const uint32_t sb0 = smem_u32(dsm);

    auto load_stage = [&](int s, int k0) {
        const uint32_t sb = sb0 + (uint32_t)s * STAGE_BYTES;
#pragma unroll
        for (int p = 0; p < 4; p++) {
            const int g = t + 256 * p;
            const int row = g >> 3;
            const int c16 = g & 7;
            const int sw = c16 ^ (row & 7);
            cpa16(sb + STG_A + (uint32_t)(row * 128 + sw * 16),
                  Ap + (size_t)row * NN + k0 + c16 * 8);
        }
#pragma unroll
        for (int p = 0; p < 4; p++) {
            const int g = t + 256 * p;
            const int row = g >> 3;
            const int c16 = g & 7;
            const int sw = c16 ^ (row & 7);
            cpa16(sb + STG_B + (uint32_t)(row * 128 + sw * 16),
                  Bp + (size_t)row * NN + k0 + c16 * 8);
        }
        asm volatile("cp.async.commit_group;" ::: "memory");
    };

    float acc[4][4][4];
#pragma unroll
    for (int a = 0; a < 4; a++)
#pragma unroll
        for (int b = 0; b < 4; b++)
#pragma unroll
            for (int c = 0; c < 4; c++) acc[a][b][c] = 0.f;

    const int t4 = l >> 3;
    const int l7 = l & 7;
    const int arow_in = ((t4 & 1) << 3) + l7;
    const int brow_in = ((t4 >> 1) << 3) + l7;
    const uint32_t abase = (uint32_t)((wm * 64 + arow_in) * 128);
    const uint32_t bbase = (uint32_t)((wn * 32 + brow_in) * 128);
    const int akg = t4 >> 1;
    const int bkg = t4 & 1;

    // double-buffered fragments
    uint32_t af[2][4][4], bf[2][2][4];

    load_stage(0, 0);
    load_stage(1, 64);

    for (int i = 0; i < NITER; i++) {
        if (i + 2 < NITER)
            asm volatile("cp.async.wait_group 1;" ::: "memory");
        else
            asm volatile("cp.async.wait_group 0;" ::: "memory");
        __syncthreads();
        if (i + 2 < NITER) load_stage((i + 2) % 3, (i + 2) * 64);
        const uint32_t sb = sb0 + (uint32_t)(i % 3) * STAGE_BYTES;

        // prologue: fragments for ks=0
        {
            const uint32_t xa = (uint32_t)(((0 + akg) ^ l7) << 4);
            const uint32_t xb = (uint32_t)(((0 + bkg) ^ l7) << 4);
#pragma unroll
            for (int mt = 0; mt < 4; mt++)
                LDSM4(af[0][mt], sb + STG_A + abase + (uint32_t)(mt * 16 * 128) + xa);
#pragma unroll
            for (int nh = 0; nh < 2; nh++)
                LDSM4(bf[0][nh], sb + STG_B + bbase + (uint32_t)(nh * 16 * 128) + xb);
        }

#pragma unroll
        for (int ks = 0; ks < 4; ks++) {
            const int cur = ks & 1;
            const int nxt = cur ^ 1;
            // prefetch ks+1 fragments under this ks's MMAs
            if (ks < 3) {
                const uint32_t xa = (uint32_t)((((ks + 1) * 2 + akg) ^ l7) << 4);
                const uint32_t xb = (uint32_t)((((ks + 1) * 2 + bkg) ^ l7) << 4);
#pragma unroll
                for (int mt = 0; mt < 4; mt++)
                    LDSM4(af[nxt][mt], sb + STG_A + abase + (uint32_t)(mt * 16 * 128) + xa);
#pragma unroll
                for (int nh = 0; nh < 2; nh++)
                    LDSM4(bf[nxt][nh], sb + STG_B + bbase + (uint32_t)(nh * 16 * 128) + xb);
            }
#pragma unroll
            for (int mt = 0; mt < 4; mt++)
#pragma unroll
                for (int n8 = 0; n8 < 4; n8++) {
                    const int nh = n8 >> 1, q = (n8 & 1) * 2;
                    MMA_F16(acc[mt][n8], af[cur][mt], bf[cur][nh][q], bf[cur][nh][q + 1]);
                }
        }
    }

    // ---------------- epilogue: Y fp16 [n][j] ----------------
    __half* Yh = (MODE == 1) ? g_Y1h : g_Y2h;
    const int lm = l >> 2;
    const int lc = (l & 3) << 1;
#pragma unroll
    for (int mt = 0; mt < 4; mt++)
#pragma unroll
        for (int n8 = 0; n8 < 4; n8++) {
            const int r = bm + wm * 64 + mt * 16 + lm;
            const int col = bn + wn * 32 + n8 * 8 + lc;
            *(__half2*)&Yh[(size_t)r * NJ + col] =
                __floats2half2_rn(acc[mt][n8][0], acc[mt][n8][1]);
            *(__half2*)&Yh[(size_t)(r + 8) * NJ + col] =
                __floats2half2_rn(acc[mt][n8][2], acc[mt][n8][3]);
        }

    if (MODE == 1) {
        __syncthreads();
#pragma unroll
        for (int mt = 0; mt < 4; mt++)
#pragma unroll
            for (int n8 = 0; n8 < 4; n8++) {
                const int jl = wn * 32 + n8 * 8 + lc;
                const int ml = wm * 64 + mt * 16 + lm;
                dsm[jl * 132 + ml]           = acc[mt][n8][0];
                dsm[(jl + 1) * 132 + ml]     = acc[mt][n8][1];
                dsm[jl * 132 + ml + 8]       = acc[mt][n8][2];
                dsm[(jl + 1) * 132 + ml + 8] = acc[mt][n8][3];
            }
        __syncthreads();
#pragma unroll
        for (int it = 0; it < 16; it++) {
            const int j = wid * 16 + it;
            const int m4 = l * 4;
            const float4 v = *(const float4*)&dsm[j * 132 + m4];
            __half2 p0 = __floats2half2_rn(v.x, v.y);
            __half2 p1 = __floats2half2_rn(v.z, v.w);
            uint2 w;
            w.x = *(uint32_t*)&p0; w.y = *(uint32_t*)&p1;
            *(uint2*)&g_Y1q[(size_t)(bn + j) * NN + bm + m4] = w;
        }
    }
}

// ============================================================
// output (tensor-core, single-term): out[b,o] = A[b,ki]@W[ki,o] + bias
//   A = fp16{x, Y1, 2*Y2-x}; 48KB smem; 3 CTAs/SM.
// ============================================================
#define OUT_SMEM 49152   // AHI 24576 + WHI 24576

__global__ void __launch_bounds__(256, 3) output_kernel(const float* __restrict__ x,
                                                        const float* __restrict__ E,
                                                        const float* __restrict__ bp,
                                                        float* __restrict__ out) {
    extern __shared__ char osm[];
    const uint32_t base = smem_u32(osm);
    const uint32_t AHI = base;
    const uint32_t WHI = base + 24576;

    const int n = blockIdx.x;
    const int tid = threadIdx.x;
    const int l = tid & 31;
    const int wid = tid >> 5;
    const int wm = wid >> 2;     // 0..1 (b, 32 rows)
    const int wn = wid & 3;      // 0..3 (o, 16 cols)

    const __half* Whg = g_W16 + (size_t)n * (KI * NC);
#pragma unroll
    for (int p = 0; p < 6; p++) {
        const int g = tid + 256 * p;
        const int ki = g >> 3;
        const int og = g & 7;
        cpa16(WHI + (uint32_t)(ki * 128 + ((og ^ (ki & 7)) << 4)),
              Whg + ki * 64 + og * 8);
    }
    asm volatile("cp.async.commit_group;" ::: "memory");

    // ---- build A plane [b=64][ki=192] fp16, unrolled for MLP ----
#pragma unroll
    for (int it = 0; it < 8; it++) {
        const int e = tid * 2 + it * 512;
        const int b = e >> 6;
        const int i = e & 63;            // even
        const float2 xv = *(const float2*)&x[(size_t)b * (NN * NC) + n * NC + i];
        const float2 y1 = __half22float2(*(const __half2*)&g_Y1h[(size_t)n * NJ + e]);
        const float2 y2 = __half22float2(*(const __half2*)&g_Y2h[(size_t)n * NJ + e]);
        const float2 vals[3] = { xv, y1,
            make_float2(2.f * y2.x - xv.x, 2.f * y2.y - xv.y) };
#pragma unroll
        for (int kch = 0; kch < 3; kch++) {
            const int ki = kch * 64 + i;  // even
            const uint32_t addr = (uint32_t)(b * 384 + ((ki >> 6) << 7) +
                ((((ki >> 3) & 7) ^ (b & 7)) << 4) + ((ki & 7) << 1));
            *(__half2*)(osm + addr) = __floats2half2_rn(vals[kch].x, vals[kch].y);
        }
    }
    asm volatile("cp.async.wait_group 0;" ::: "memory");
    __syncthreads();

    float acc[2][2][4];
#pragma unroll
    for (int a = 0; a < 2; a++)
#pragma unroll
        for (int b = 0; b < 2; b++)
#pragma unroll
            for (int c = 0; c < 4; c++) acc[a][b][c] = 0.f;

    const int t4 = l >> 3;
    const int l7 = l & 7;
    const int arow_in = ((t4 & 1) << 3) + l7;
    const int akg = t4 >> 1;
    const int wrow_in = ((t4 & 1) << 3) + l7;
    const int wog = wn * 2 + (t4 >> 1);

#pragma unroll
    for (int ks = 0; ks < 12; ks++) {
        uint32_t ahf[2][4], whf[4];
        const int kg = ks * 2 + akg;
#pragma unroll
        for (int mt = 0; mt < 2; mt++) {
            const int row = wm * 32 + mt * 16 + arow_in;
            const uint32_t aaddr = (uint32_t)(row * 384 + ((kg >> 3) << 7) +
                (((kg & 7) ^ (row & 7)) << 4));
            LDSM4(ahf[mt], AHI + aaddr);
        }
        {
            const int wrow = ks * 16 + wrow_in;
            LDSM4T(whf, WHI + (uint32_t)(wrow * 128 + ((wog ^ (wrow & 7)) << 4)));
        }
#pragma unroll
        for (int mt = 0; mt < 2; mt++)
#pragma unroll
            for (int n8 = 0; n8 < 2; n8++)
                MMA_F16(acc[mt][n8], ahf[mt], whf[n8 * 2], whf[n8 * 2 + 1]);
    }

    const int lm = l >> 2;
    const int lc = (l & 3) << 1;
    float bias[2][2];
#pragma unroll
    for (int n8 = 0; n8 < 2; n8++)
#pragma unroll
        for (int cc = 0; cc < 2; cc++) {
            const int o = wn * 16 + n8 * 8 + lc + cc;
            float s = 0.f;
#pragma unroll
            for (int d = 0; d < ND; d++) s = fmaf(E[n * ND + d], bp[d * NC + o], s);
            bias[n8][cc] = s;
        }

#pragma unroll
    for (int mt = 0; mt < 2; mt++)
#pragma unroll
        for (int n8 = 0; n8 < 2; n8++) {
            const int b0 = wm * 32 + mt * 16 + lm;
            const int col = wn * 16 + n8 * 8 + lc;
            *(float2*)&out[(size_t)b0 * (NN * NC) + n * NC + col] =
                make_float2(acc[mt][n8][0] + bias[n8][0], acc[mt][n8][1] + bias[n8][1]);
            *(float2*)&out[(size_t)(b0 + 8) * (NN * NC) + n * NC + col] =
                make_float2(acc[mt][n8][2] + bias[n8][0], acc[mt][n8][3] + bias[n8][1]);
        }
}

// ============================================================
extern "C" void kernel_launch(void* const* d_in, const int* in_sizes, int n_in,
                              void* d_out, int out_size) {
    (void)in_sizes; (void)n_in; (void)out_size;
    const float* x  = (const float*)d_in[0];
    const float* E  = (const float*)d_in[1];
    const float* Wp = (const float*)d_in[2];
    const float* bp = (const float*)d_in[3];
    float* out = (float*)d_out;

    cudaFuncSetAttribute(output_kernel, cudaFuncAttributeMaxDynamicSharedMemorySize, OUT_SMEM);
    cudaFuncSetAttribute(gemm_fp16_kernel<1>, cudaFuncAttributeMaxDynamicSharedMemorySize, GEMM_SMEM);
    cudaFuncSetAttribute(gemm_fp16_kernel<2>, cudaFuncAttributeMaxDynamicSharedMemorySize, GEMM_SMEM);

    prep_kernel<<<PREP_TOTAL, 256>>>(x, E, Wp);

    dim3 ggrid(NJ / 128, NN / 128);   // (32, 16) = 512 CTAs
    gemm_fp16_kernel<1><<<ggrid, 256, GEMM_SMEM>>>();
    gemm_fp16_kernel<2><<<ggrid, 256, GEMM_SMEM>>>();

    output_kernel<<<NN, 256, OUT_SMEM>>>(x, E, bp, out);
}

// round 15
// speedup vs baseline: 3.1381x; 1.0199x over previous
#include <cuda_runtime.h>
#include <cuda_fp16.h>
#include <math.h>
#include <stdint.h>

#define NB 64
#define NN 2048
#define NC 64
#define ND 10
#define NJ 4096          // NB*NC
#define KI 192           // cheb_k * C_IN

// ------------------ scratch (static device globals) ------------------
__device__ __half g_S   [NN * NN];            // fp16 supports
__device__ __half g_Xq  [(size_t)NJ * NN];    // [j][m] fp16
__device__ __half g_Y1h [(size_t)NN * NJ];    // [n][j] fp16 (GEMM1 out, GEMM2 B, output A)
__device__ __half g_Y2h [(size_t)NN * NJ];    // [n][j] fp16
__device__ __half g_W16 [(size_t)NN * KI * NC];  // [n][ki][o] fp16

// ------------------ helpers ------------------
__device__ __forceinline__ uint32_t smem_u32(const void* p) {
    uint32_t a;
    asm("{ .reg .u64 t; cvta.to.shared.u64 t, %1; cvt.u32.u64 %0, t; }" : "=r"(a) : "l"(p));
    return a;
}
__device__ __forceinline__ void cpa16(uint32_t s, const void* g) {
    asm volatile("cp.async.cg.shared.global [%0], [%1], 16;" :: "r"(s), "l"(g));
}

#define LDSM4(r, a) \
    asm volatile("ldmatrix.sync.aligned.m8n8.x4.shared.b16 {%0,%1,%2,%3}, [%4];" \
        : "=r"((r)[0]), "=r"((r)[1]), "=r"((r)[2]), "=r"((r)[3]) : "r"(a))

#define LDSM4T(r, a) \
    asm volatile("ldmatrix.sync.aligned.m8n8.x4.trans.shared.b16 {%0,%1,%2,%3}, [%4];" \
        : "=r"((r)[0]), "=r"((r)[1]), "=r"((r)[2]), "=r"((r)[3]) : "r"(a))

#define MMA_F16(c, a, b0, b1) \
    asm volatile("mma.sync.aligned.m16n8k16.row.col.f32.f16.f16.f32 " \
        "{%0,%1,%2,%3}, {%4,%5,%6,%7}, {%8,%9}, {%0,%1,%2,%3};" \
        : "+f"((c)[0]), "+f"((c)[1]), "+f"((c)[2]), "+f"((c)[3]) \
        : "r"((a)[0]), "r"((a)[1]), "r"((a)[2]), "r"((a)[3]), "r"(b0), "r"(b1))

// ============================================================
// prep: ONE kernel, 3 jobs interleaved round-robin on blockIdx
//   (1 supports : 2 xq : 3 weights per 6 blocks) so MUFU-heavy
//   supports overlaps DRAM-heavy xq/weights.
// ============================================================
#define PREP_TOTAL 12288   // 2048 sup + 4096 xq + 6144 weights

__global__ __launch_bounds__(256) void prep_kernel(const float* __restrict__ x,
                                                   const float* __restrict__ E,
                                                   const float* __restrict__ Wp) {
    __shared__ float sh[2048 + 256];
    const int tid = threadIdx.x;
    const int bid = blockIdx.x;
    const int r6 = bid % 6;
    const int q6 = bid / 6;    // 0..2047

    if (r6 == 0) {
        // ---- supports row n (no max-subtraction: |dot| <= ~35, exp safe) ----
        float* vals = sh;
        float* red  = sh + 2048;
        const int n = q6;

        float en[ND];
#pragma unroll
        for (int d = 0; d < ND; d++) en[d] = E[n * ND + d];

        float lsum = 0.f;
        for (int m = tid; m < NN; m += 256) {
            float v = 0.f;
#pragma unroll
            for (int d = 0; d < ND; d++) v = fmaf(en[d], E[m * ND + d], v);
            float e = __expf(fmaxf(v, 0.f));
            vals[m] = e;
            lsum += e;
        }
        red[tid] = lsum; __syncthreads();
        for (int s = 128; s > 0; s >>= 1) { if (tid < s) red[tid] += red[tid + s]; __syncthreads(); }
        const float inv = 1.f / red[0];
        for (int m = tid; m < NN; m += 256)
            g_S[n * NN + m] = __float2half_rn(vals[m] * inv);

    } else if (r6 <= 2) {
        // ---- Xq tile: Xq[b*64+c][m] = fp16(x[b][m][c]) ----
        const int id = q6 * 2 + (r6 - 1);    // 0..4095
        const int m0 = (id & 63) * 32;
        const int b  = id >> 6;
        float* sm = sh;   // 64*33 floats
#pragma unroll
        for (int p = 0; p < 8; p++) {
            int e = tid + 256 * p;
            int rr = e >> 6, c = e & 63;
            sm[c * 33 + rr] = x[(size_t)b * (NN * NC) + (size_t)(m0 + rr) * NC + c];
        }
        __syncthreads();
#pragma unroll
        for (int p = 0; p < 4; p++) {
            int e = tid + 256 * p;
            int c = e >> 4, r2 = (e & 15) * 2;
            __half2 hp = __floats2half2_rn(sm[c * 33 + r2], sm[c * 33 + r2 + 1]);
            *(__half2*)&g_Xq[(size_t)(b * 64 + c) * NN + m0 + r2] = hp;
        }

    } else {
        // ---- weights tile: W16[n, e] = fp16(sum_d E[n,d]*Wp[d,e]) ----
        const int id = q6 * 3 + (r6 - 3);    // 0..6143
        const int e0 = (id % 48) * 256;
        const int n0 = (id / 48) * 16;
        float* Es = sh;   // [16][ND]
        if (tid < 16 * ND) Es[tid] = E[(n0 + tid / ND) * ND + (tid % ND)];
        __syncthreads();
        const int e = e0 + tid;
        float wp[ND];
#pragma unroll
        for (int d = 0; d < ND; d++) wp[d] = Wp[d * (KI * NC) + e];
#pragma unroll
        for (int nn = 0; nn < 16; nn++) {
            float acc = 0.f;
#pragma unroll
            for (int d = 0; d < ND; d++) acc = fmaf(Es[nn * ND + d], wp[d], acc);
            g_W16[(size_t)(n0 + nn) * (KI * NC) + e] = __float2half_rn(acc);
        }
    }
}

// ============================================================
// single-term fp16 GEMM (m16n8k16): C[128x128] tile, 256 threads,
// 8 warps (2x4), warp tile 64x32. 3-stage cp.async, 2 CTAs/SM.
// MODE 1: B = Xq [j][m] k-major (ldmatrix), out = Y1h [n][j]
// MODE 2: B = Y1h [m][j] mn-major (ldmatrix.trans), out = Y2h [n][j]
// ============================================================
#define STG_A 0
#define STG_B 16384
#define STAGE_BYTES 32768
#define GEMM_SMEM 98304
#define NITER (NN / 64)            // 32

template <int MODE>
__global__ void __launch_bounds__(256, 2) gemm_fp16_kernel() {
    extern __shared__ float dsm[];
    const int t = threadIdx.x;
    const int l = t & 31;
    const int wid = t >> 5;
    const int wm = wid >> 2;       // 0..1  (m, 64 rows each)
    const int wn = wid & 3;        // 0..3  (n, 32 cols each)
    const int bm = blockIdx.y * 128;
    const int bn = blockIdx.x * 128;

    const __half* Ap = g_S + (size_t)bm * NN;

    const uint32_t sb0 = smem_u32(dsm);

    auto load_stage = [&](int s, int k0) {
        const uint32_t sb = sb0 + (uint32_t)s * STAGE_BYTES;
#pragma unroll
        for (int p = 0; p < 4; p++) {          // A: 128 rows(m) x 8 granules(k)
            const int g = t + 256 * p;
            const int row = g >> 3;
            const int c16 = g & 7;
            const int sw = c16 ^ (row & 7);
            cpa16(sb + STG_A + (uint32_t)(row * 128 + sw * 16),
                  Ap + (size_t)row * NN + k0 + c16 * 8);
        }
        if (MODE == 1) {
            // B = Xq [j][m]: 128 rows(j) x 8 granules(k), 128B rows
            const __half* Bp = g_Xq + (size_t)bn * NN;
#pragma unroll
            for (int p = 0; p < 4; p++) {
                const int g = t + 256 * p;
                const int row = g >> 3;
                const int c16 = g & 7;
                const int sw = c16 ^ (row & 7);
                cpa16(sb + STG_B + (uint32_t)(row * 128 + sw * 16),
                      Bp + (size_t)row * NN + k0 + c16 * 8);
            }
        } else {
            // B = Y1h [m][j]: 64 rows(k) x 16 granules(j), 256B rows (2x128B subrows)
#pragma unroll
            for (int p = 0; p < 4; p++) {
                const int g = t + 256 * p;          // 1024 granules
                const int k = g >> 4;
                const int jg = g & 15;
                const uint32_t dst = (uint32_t)(k * 256 + ((jg >> 3) << 7) +
                                                (((jg & 7) ^ (k & 7)) << 4));
                cpa16(sb + STG_B + dst,
                      g_Y1h + (size_t)(k0 + k) * NJ + bn + jg * 8);
            }
        }
        asm volatile("cp.async.commit_group;" ::: "memory");
    };

    float acc[4][4][4];
#pragma unroll
    for (int a = 0; a < 4; a++)
#pragma unroll
        for (int b = 0; b < 4; b++)
#pragma unroll
            for (int c = 0; c < 4; c++) acc[a][b][c] = 0.f;

    const int t4 = l >> 3;
    const int l7 = l & 7;
    const int arow_in = ((t4 & 1) << 3) + l7;
    const int brow_in = ((t4 >> 1) << 3) + l7;   // MODE 1 (k-major B)
    const uint32_t abase = (uint32_t)((wm * 64 + arow_in) * 128);
    const uint32_t bbase = (uint32_t)((wn * 32 + brow_in) * 128);
    const int akg = t4 >> 1;
    const int bkg = t4 & 1;
    // MODE 2 (mn-major B) lane geometry (mirrors output kernel W path)
    const int b2row_in = ((t4 & 1) << 3) + l7;   // k subrow
    const int b2gsel   = t4 >> 1;                // j-granule select (0/1)

    load_stage(0, 0);
    load_stage(1, 64);

    for (int i = 0; i < NITER; i++) {
        if (i + 2 < NITER)
            asm volatile("cp.async.wait_group 1;" ::: "memory");
        else
            asm volatile("cp.async.wait_group 0;" ::: "memory");
        __syncthreads();
        if (i + 2 < NITER) load_stage((i + 2) % 3, (i + 2) * 64);
        const uint32_t sb = sb0 + (uint32_t)(i % 3) * STAGE_BYTES;
#pragma unroll
        for (int ks = 0; ks < 4; ks++) {
            const uint32_t xa = (uint32_t)(((ks * 2 + akg) ^ l7) << 4);
            uint32_t af[4][4], bf[2][4];
#pragma unroll
            for (int mt = 0; mt < 4; mt++)
                LDSM4(af[mt], sb + STG_A + abase + (uint32_t)(mt * 16 * 128) + xa);
            if (MODE == 1) {
                const uint32_t xb = (uint32_t)(((ks * 2 + bkg) ^ l7) << 4);
#pragma unroll
                for (int nh = 0; nh < 2; nh++)
                    LDSM4(bf[nh], sb + STG_B + bbase + (uint32_t)(nh * 16 * 128) + xb);
            } else {
#pragma unroll
                for (int nh = 0; nh < 2; nh++) {
                    const int kr = ks * 16 + b2row_in;
                    const int jg = wn * 4 + nh * 2 + b2gsel;
                    const uint32_t addr = (uint32_t)(kr * 256 + ((jg >> 3) << 7) +
                                                     (((jg & 7) ^ (kr & 7)) << 4));
                    LDSM4T(bf[nh], sb + STG_B + addr);
                }
            }
#pragma unroll
            for (int mt = 0; mt < 4; mt++)
#pragma unroll
                for (int n8 = 0; n8 < 4; n8++) {
                    const int nh = n8 >> 1, q = (n8 & 1) * 2;
                    MMA_F16(acc[mt][n8], af[mt], bf[nh][q], bf[nh][q + 1]);
                }
        }
    }

    // ---------------- epilogue: Y fp16 [n][j] ----------------
    __half* Yh = (MODE == 1) ? g_Y1h : g_Y2h;
    const int lm = l >> 2;
    const int lc = (l & 3) << 1;
#pragma unroll
    for (int mt = 0; mt < 4; mt++)
#pragma unroll
        for (int n8 = 0; n8 < 4; n8++) {
            const int r = bm + wm * 64 + mt * 16 + lm;
            const int col = bn + wn * 32 + n8 * 8 + lc;
            *(__half2*)&Yh[(size_t)r * NJ + col] =
                __floats2half2_rn(acc[mt][n8][0], acc[mt][n8][1]);
            *(__half2*)&Yh[(size_t)(r + 8) * NJ + col] =
                __floats2half2_rn(acc[mt][n8][2], acc[mt][n8][3]);
        }
}

// ============================================================
// output (tensor-core, single-term): out[b,o] = A[b,ki]@W[ki,o] + bias
//   A = fp16{x, Y1, 2*Y2-x}; 48KB smem; 3 CTAs/SM.
// ============================================================
#define OUT_SMEM 49152   // AHI 24576 + WHI 24576

__global__ void __launch_bounds__(256, 3) output_kernel(const float* __restrict__ x,
                                                        const float* __restrict__ E,
                                                        const float* __restrict__ bp,
                                                        float* __restrict__ out) {
    extern __shared__ char osm[];
    const uint32_t base = smem_u32(osm);
    const uint32_t AHI = base;
    const uint32_t WHI = base + 24576;

    const int n = blockIdx.x;
    const int tid = threadIdx.x;
    const int l = tid & 31;
    const int wid = tid >> 5;
    const int wm = wid >> 2;     // 0..1 (b, 32 rows)
    const int wn = wid & 3;      // 0..3 (o, 16 cols)

    const __half* Whg = g_W16 + (size_t)n * (KI * NC);
#pragma unroll
    for (int p = 0; p < 6; p++) {
        const int g = tid + 256 * p;
        const int ki = g >> 3;
        const int og = g & 7;
        cpa16(WHI + (uint32_t)(ki * 128 + ((og ^ (ki & 7)) << 4)),
              Whg + ki * 64 + og * 8);
    }
    asm volatile("cp.async.commit_group;" ::: "memory");

    // ---- build A plane [b=64][ki=192] fp16, unrolled for MLP ----
#pragma unroll
    for (int it = 0; it < 8; it++) {
        const int e = tid * 2 + it * 512;
        const int b = e >> 6;
        const int i = e & 63;            // even
        const float2 xv = *(const float2*)&x[(size_t)b * (NN * NC) + n * NC + i];
        const float2 y1 = __half22float2(*(const __half2*)&g_Y1h[(size_t)n * NJ + e]);
        const float2 y2 = __half22float2(*(const __half2*)&g_Y2h[(size_t)n * NJ + e]);
        const float2 vals[3] = { xv, y1,
            make_float2(2.f * y2.x - xv.x, 2.f * y2.y - xv.y) };
#pragma unroll
        for (int kch = 0; kch < 3; kch++) {
            const int ki = kch * 64 + i;  // even
            const uint32_t addr = (uint32_t)(b * 384 + ((ki >> 6) << 7) +
                ((((ki >> 3) & 7) ^ (b & 7)) << 4) + ((ki & 7) << 1));
            *(__half2*)(osm + addr) = __floats2half2_rn(vals[kch].x, vals[kch].y);
        }
    }
    asm volatile("cp.async.wait_group 0;" ::: "memory");
    __syncthreads();

    float acc[2][2][4];
#pragma unroll
    for (int a = 0; a < 2; a++)
#pragma unroll
        for (int b = 0; b < 2; b++)
#pragma unroll
            for (int c = 0; c < 4; c++) acc[a][b][c] = 0.f;

    const int t4 = l >> 3;
    const int l7 = l & 7;
    const int arow_in = ((t4 & 1) << 3) + l7;
    const int akg = t4 >> 1;
    const int wrow_in = ((t4 & 1) << 3) + l7;
    const int wog = wn * 2 + (t4 >> 1);

#pragma unroll
    for (int ks = 0; ks < 12; ks++) {
        uint32_t ahf[2][4], whf[4];
        const int kg = ks * 2 + akg;
#pragma unroll
        for (int mt = 0; mt < 2; mt++) {
            const int row = wm * 32 + mt * 16 + arow_in;
            const uint32_t aaddr = (uint32_t)(row * 384 + ((kg >> 3) << 7) +
                (((kg & 7) ^ (row & 7)) << 4));
            LDSM4(ahf[mt], AHI + aaddr);
        }
        {
            const int wrow = ks * 16 + wrow_in;
            LDSM4T(whf, WHI + (uint32_t)(wrow * 128 + ((wog ^ (wrow & 7)) << 4)));
        }
#pragma unroll
        for (int mt = 0; mt < 2; mt++)
#pragma unroll
            for (int n8 = 0; n8 < 2; n8++)
                MMA_F16(acc[mt][n8], ahf[mt], whf[n8 * 2], whf[n8 * 2 + 1]);
    }

    const int lm = l >> 2;
    const int lc = (l & 3) << 1;
    float bias[2][2];
#pragma unroll
    for (int n8 = 0; n8 < 2; n8++)
#pragma unroll
        for (int cc = 0; cc < 2; cc++) {
            const int o = wn * 16 + n8 * 8 + lc + cc;
            float s = 0.f;
#pragma unroll
            for (int d = 0; d < ND; d++) s = fmaf(E[n * ND + d], bp[d * NC + o], s);
            bias[n8][cc] = s;
        }

#pragma unroll
    for (int mt = 0; mt < 2; mt++)
#pragma unroll
        for (int n8 = 0; n8 < 2; n8++) {
            const int b0 = wm * 32 + mt * 16 + lm;
            const int col = wn * 16 + n8 * 8 + lc;
            *(float2*)&out[(size_t)b0 * (NN * NC) + n * NC + col] =
                make_float2(acc[mt][n8][0] + bias[n8][0], acc[mt][n8][1] + bias[n8][1]);
            *(float2*)&out[(size_t)(b0 + 8) * (NN * NC) + n * NC + col] =
                make_float2(acc[mt][n8][2] + bias[n8][0], acc[mt][n8][3] + bias[n8][1]);
        }
}

// ============================================================
extern "C" void kernel_launch(void* const* d_in, const int* in_sizes, int n_in,
                              void* d_out, int out_size) {
    (void)in_sizes; (void)n_in; (void)out_size;
    const float* x  = (const float*)d_in[0];
    const float* E  = (const float*)d_in[1];
    const float* Wp = (const float*)d_in[2];
    const float* bp = (const float*)d_in[3];
    float* out = (float*)d_out;

    cudaFuncSetAttribute(output_kernel, cudaFuncAttributeMaxDynamicSharedMemorySize, OUT_SMEM);
    cudaFuncSetAttribute(gemm_fp16_kernel<1>, cudaFuncAttributeMaxDynamicSharedMemorySize, GEMM_SMEM);
    cudaFuncSetAttribute(gemm_fp16_kernel<2>, cudaFuncAttributeMaxDynamicSharedMemorySize, GEMM_SMEM);

    prep_kernel<<<PREP_TOTAL, 256>>>(x, E, Wp);

    dim3 ggrid(NJ / 128, NN / 128);   // (32, 16) = 512 CTAs
    gemm_fp16_kernel<1><<<ggrid, 256, GEMM_SMEM>>>();
    gemm_fp16_kernel<2><<<ggrid, 256, GEMM_SMEM>>>();

    output_kernel<<<NN, 256, OUT_SMEM>>>(x, E, bp, out);
}